// round 2
// baseline (speedup 1.0000x reference)
#include <cuda_runtime.h>
#include <cstdint>

#define BB 8
#define NPTS 2048
#define KNN 32
typedef long long ll;

// ---------------- scratch (device globals; allocation-free) ----------------
static __device__ float g_xT3[BB * NPTS * 3];
static __device__ float g_sqn[BB * NPTS];
static __device__ float g_dist[(ll)BB * NPTS * NPTS];   // also reused as attention matrix
static __device__ int   g_idx[BB * NPTS * KNN];
static __device__ float g_xcT[BB * NPTS * 192];         // concat(f1,f2,f3), point-major
static __device__ float g_h [(ll)BB * 1024 * NPTS];
static __device__ float g_q [(ll)BB * 1024 * NPTS];     // later: h2
static __device__ float g_k [(ll)BB * 1024 * NPTS];     // later: ff out
static __device__ float g_v [(ll)BB * 1024 * NPTS];     // later: h3
static __device__ float g_xr[(ll)BB * 1024 * NPTS];
static __device__ float g_ffb[(ll)BB * 512 * NPTS];

// ---------------- small kernels ----------------
__global__ void transpose_x_kernel(const float* __restrict__ x, float* __restrict__ xt) {
    int i = blockIdx.x * blockDim.x + threadIdx.x;
    if (i >= BB * NPTS) return;
    int b = i / NPTS, n = i % NPTS;
#pragma unroll
    for (int c = 0; c < 3; c++)
        xt[i * 3 + c] = x[(b * 3 + c) * NPTS + n];
}

__global__ void sqnorm_kernel(const float* __restrict__ xt, int rs, int off, int C,
                              float* __restrict__ sq) {
    int i = blockIdx.x * blockDim.x + threadIdx.x;
    if (i >= BB * NPTS) return;
    const float* p = xt + (ll)i * rs + off;
    float s = 0.f;
    for (int c = 0; c < C; c++) { float v = p[c]; s += v * v; }
    sq[i] = s;
}

// ---------------- generic tiled SGEMM ----------------
// C[bz][i,j] = sum_k Aelem(i,k) * Belem(k,j)
// Aelem = TA ? A[k*lda+i] : A[i*lda+k];  Belem = TB ? B[j*ldb+k] : B[k*ldb+j]
// EPI: 0 none, 1 lrelu, 2 bn(p1,bnc)+lrelu, 3 dist: p1[i]+p2[j]-2*acc
template <int TA, int TB, int EPI>
__global__ __launch_bounds__(256, 2)
void gemm_kernel(const float* __restrict__ A, const float* __restrict__ B,
                 float* __restrict__ C, int M, int Nn, int K,
                 int lda, int ldb, int ldc,
                 ll sA, ll sB, ll sC,
                 const float* __restrict__ p1, const float* __restrict__ p2,
                 ll p1s, ll p2s, int bnc) {
    __shared__ float As[16][132];
    __shared__ float Bs[16][132];
    const int tid = threadIdx.x;
    const int tx = tid & 15, ty = tid >> 4;
    const int i0 = blockIdx.y * 128, j0 = blockIdx.x * 128;
    const int bz = blockIdx.z;
    const float* Ab = A + (ll)bz * sA;
    const float* Bb = B + (ll)bz * sB;
    float acc[8][8];
#pragma unroll
    for (int i = 0; i < 8; i++)
#pragma unroll
        for (int j = 0; j < 8; j++) acc[i][j] = 0.f;

    for (int k0 = 0; k0 < K; k0 += 16) {
#pragma unroll
        for (int t = tid; t < 2048; t += 256) {
            int i, kq;
            if (TA) { i = t & 127; kq = t >> 7; } else { kq = t & 15; i = t >> 4; }
            int gi = i0 + i, gk = k0 + kq;
            float v = 0.f;
            if (gi < M && gk < K)
                v = TA ? Ab[(ll)gk * lda + gi] : Ab[(ll)gi * lda + gk];
            As[kq][i] = v;
        }
#pragma unroll
        for (int t = tid; t < 2048; t += 256) {
            int j, kq;
            if (TB) { kq = t & 15; j = t >> 4; } else { j = t & 127; kq = t >> 7; }
            int gj = j0 + j, gk = k0 + kq;
            float v = 0.f;
            if (gj < Nn && gk < K)
                v = TB ? Bb[(ll)gj * ldb + gk] : Bb[(ll)gk * ldb + gj];
            Bs[kq][j] = v;
        }
        __syncthreads();
#pragma unroll
        for (int kq = 0; kq < 16; kq++) {
            float4 a0 = *(const float4*)&As[kq][ty * 8];
            float4 a1 = *(const float4*)&As[kq][ty * 8 + 4];
            float4 b0 = *(const float4*)&Bs[kq][tx * 8];
            float4 b1 = *(const float4*)&Bs[kq][tx * 8 + 4];
            float a[8] = {a0.x, a0.y, a0.z, a0.w, a1.x, a1.y, a1.z, a1.w};
            float b[8] = {b0.x, b0.y, b0.z, b0.w, b1.x, b1.y, b1.z, b1.w};
#pragma unroll
            for (int i = 0; i < 8; i++)
#pragma unroll
                for (int j = 0; j < 8; j++) acc[i][j] += a[i] * b[j];
        }
        __syncthreads();
    }
    float* Cb = C + (ll)bz * sC;
    const float* p1b = p1 ? p1 + (ll)bz * p1s : nullptr;
    const float* p2b = p2 ? p2 + (ll)bz * p2s : nullptr;
#pragma unroll
    for (int ii = 0; ii < 8; ii++) {
        int gi = i0 + ty * 8 + ii;
        if (gi >= M) continue;
        float s = 1.f, t = 0.f, sqi = 0.f;
        if (EPI == 2) {
            float g = p1b[gi], be = p1b[bnc + gi], mm = p1b[2 * bnc + gi], va = p1b[3 * bnc + gi];
            s = g * rsqrtf(va + 1e-5f);
            t = be - mm * s;
        }
        if (EPI == 3) sqi = p1b[gi];
#pragma unroll
        for (int jj = 0; jj < 8; jj++) {
            int gj = j0 + tx * 8 + jj;
            if (gj >= Nn) continue;
            float v = acc[ii][jj];
            if (EPI == 1) v = v >= 0.f ? v : 0.2f * v;
            else if (EPI == 2) { v = v * s + t; v = v >= 0.f ? v : 0.2f * v; }
            else if (EPI == 3) v = sqi + p2b[gj] - 2.f * v;
            Cb[(ll)gi * ldc + gj] = v;
        }
    }
}

// ---------------- top-k (k=32 smallest, ties -> lowest index) ----------------
__global__ __launch_bounds__(256)
void topk_kernel(const float* __restrict__ dist, int* __restrict__ out) {
    __shared__ float sd[NPTS];
    __shared__ float rv[256];
    __shared__ int ri[256];
    const int tid = threadIdx.x;
    const float* row = dist + (ll)blockIdx.x * NPTS;
    for (int t = tid; t < NPTS; t += 256) sd[t] = row[t];
    __syncthreads();
    int* op = out + blockIdx.x * KNN;
    for (int s = 0; s < KNN; s++) {
        float best = 3.4e38f; int bi = NPTS;
        for (int t = tid; t < NPTS; t += 256) {
            float v = sd[t];
            if (v < best) { best = v; bi = t; }
        }
        rv[tid] = best; ri[tid] = bi;
        __syncthreads();
        for (int h = 128; h > 0; h >>= 1) {
            if (tid < h) {
                float ov = rv[tid + h]; int oi = ri[tid + h];
                if (ov < rv[tid] || (ov == rv[tid] && oi < ri[tid])) { rv[tid] = ov; ri[tid] = oi; }
            }
            __syncthreads();
        }
        if (tid == 0) { op[s] = ri[0]; sd[ri[0]] = 3.4e38f; }
        __syncthreads();
    }
}

// ---------------- fused EdgeConv (gather + conv1+bn+lrelu + conv2+bn+lrelu + max_k) ----------------
template <int CIN>
__global__ __launch_bounds__(256)
void edgeconv_kernel(const float* __restrict__ xin, int rsin, int offin,
                     const int* __restrict__ idx,
                     const float* __restrict__ w1, const float* __restrict__ bn1,
                     const float* __restrict__ w2, const float* __restrict__ bn2,
                     float* __restrict__ xout, int rsout, int offout) {
    constexpr int C2 = 2 * CIN;
    extern __shared__ float sm[];
    float* w1s = sm;                       // C2*64 transposed
    float* w2s = w1s + C2 * 64;            // 64*64 transposed
    float* es  = w2s + 4096;               // 32 * C2
    float* h1s = es + 32 * C2;             // 64 * 33 (padded)
    float* red = h1s + 64 * 33;            // 256
    float* ctr = red + 256;                // CIN
    int*   iks = (int*)(ctr + ((CIN + 3) & ~3));  // 32

    const int tid = threadIdx.x;
    const int o = tid & 63, kg = tid >> 6;

    for (int t = tid; t < 64 * C2; t += 256) { int oo = t & 63, c = t >> 6; w1s[t] = w1[oo * C2 + c]; }
    for (int t = tid; t < 4096; t += 256)    { int oo = t & 63, c = t >> 6; w2s[t] = w2[oo * 64 + c]; }
    const float s1 = bn1[o] * rsqrtf(bn1[192 + o] + 1e-5f);
    const float t1 = bn1[64 + o] - bn1[128 + o] * s1;
    const float s2 = bn2[o] * rsqrtf(bn2[192 + o] + 1e-5f);
    const float t2 = bn2[64 + o] - bn2[128 + o] * s2;
    __syncthreads();

    for (int p = blockIdx.x; p < BB * NPTS; p += gridDim.x) {
        const int b = p >> 11;
        if (tid < CIN) ctr[tid] = xin[(ll)p * rsin + offin + tid];
        if (tid < KNN) iks[tid] = idx[p * KNN + tid];
        __syncthreads();
        for (int t = tid; t < KNN * CIN; t += 256) {
            int kq = t / CIN, c = t - kq * CIN;
            int m = iks[kq];
            float v = xin[(ll)(b * NPTS + m) * rsin + offin + c];
            es[kq * C2 + c] = v - ctr[c];
            es[kq * C2 + CIN + c] = ctr[c];
        }
        __syncthreads();
        float acc[8];
#pragma unroll
        for (int j = 0; j < 8; j++) acc[j] = 0.f;
        for (int c = 0; c < C2; c++) {
            float w = w1s[c * 64 + o];
#pragma unroll
            for (int j = 0; j < 8; j++) acc[j] += w * es[(kg * 8 + j) * C2 + c];
        }
#pragma unroll
        for (int j = 0; j < 8; j++) {
            float v = acc[j] * s1 + t1;
            v = v >= 0.f ? v : 0.2f * v;
            h1s[o * 33 + kg * 8 + j] = v;
            acc[j] = 0.f;
        }
        __syncthreads();
        for (int c = 0; c < 64; c++) {
            float w = w2s[c * 64 + o];
#pragma unroll
            for (int j = 0; j < 8; j++) acc[j] += w * h1s[c * 33 + kg * 8 + j];
        }
        float mx = -3.4e38f;
#pragma unroll
        for (int j = 0; j < 8; j++) {
            float v = acc[j] * s2 + t2;
            v = v >= 0.f ? v : 0.2f * v;
            mx = fmaxf(mx, v);
        }
        red[kg * 64 + o] = mx;
        __syncthreads();
        if (kg == 0) {
            float m = fmaxf(fmaxf(red[o], red[64 + o]), fmaxf(red[128 + o], red[192 + o]));
            xout[(ll)p * rsout + offout + o] = m;
        }
        __syncthreads();
    }
}

// ---------------- softmax over last dim (with 1/32 scale folded in) ----------------
__global__ __launch_bounds__(256)
void softmax_kernel(float* __restrict__ att) {
    __shared__ float sd[NPTS];
    __shared__ float red[256];
    const int tid = threadIdx.x;
    float* p = att + (ll)blockIdx.x * NPTS;
    float mx = -3.4e38f;
    for (int t = tid; t < NPTS; t += 256) {
        float v = p[t] * 0.03125f;
        sd[t] = v;
        mx = fmaxf(mx, v);
    }
    red[tid] = mx;
    __syncthreads();
    for (int h = 128; h > 0; h >>= 1) {
        if (tid < h) red[tid] = fmaxf(red[tid], red[tid + h]);
        __syncthreads();
    }
    mx = red[0];
    __syncthreads();
    float sum = 0.f;
    for (int t = tid; t < NPTS; t += 256) {
        float e = expf(sd[t] - mx);
        sd[t] = e;
        sum += e;
    }
    red[tid] = sum;
    __syncthreads();
    for (int h = 128; h > 0; h >>= 1) {
        if (tid < h) red[tid] += red[tid + h];
        __syncthreads();
    }
    float inv = 1.f / red[0];
    __syncthreads();
    for (int t = tid; t < NPTS; t += 256) p[t] = sd[t] * inv;
}

// ---------------- residual add + BN ----------------
__global__ void addbn_kernel(const float* __restrict__ a, const float* __restrict__ r,
                             const float* __restrict__ bn, float* __restrict__ out,
                             int C, ll total) {
    ll i = (ll)blockIdx.x * blockDim.x + threadIdx.x;
    if (i >= total) return;
    int c = (int)((i / NPTS) % C);
    float g = bn[c], be = bn[C + c], m = bn[2 * C + c], va = bn[3 * C + c];
    float s = g * rsqrtf(va + 1e-5f);
    out[i] = (a[i] + r[i]) * s + (be - m * s);
}

// ---------------- launcher ----------------
extern "C" void kernel_launch(void* const* d_in, const int* in_sizes, int n_in,
                              void* d_out, int out_size) {
    const float* x       = (const float*)d_in[0];
    const float* ec1_w1  = (const float*)d_in[1];
    const float* ec1_bn1 = (const float*)d_in[2];
    const float* ec1_w2  = (const float*)d_in[3];
    const float* ec1_bn2 = (const float*)d_in[4];
    const float* ec2_w1  = (const float*)d_in[5];
    const float* ec2_bn1 = (const float*)d_in[6];
    const float* ec2_w2  = (const float*)d_in[7];
    const float* ec2_bn2 = (const float*)d_in[8];
    const float* ec3_w1  = (const float*)d_in[9];
    const float* ec3_bn1 = (const float*)d_in[10];
    const float* ec3_w2  = (const float*)d_in[11];
    const float* ec3_bn2 = (const float*)d_in[12];
    const float* emb_w   = (const float*)d_in[13];
    const float* q_w     = (const float*)d_in[14];
    const float* k_w     = (const float*)d_in[15];
    const float* v_w     = (const float*)d_in[16];
    const float* att_bn1 = (const float*)d_in[17];
    const float* ff_w1   = (const float*)d_in[18];
    const float* ff_w2   = (const float*)d_in[19];
    const float* att_bn2 = (const float*)d_in[20];
    const float* cb_w    = (const float*)d_in[21];
    const float* cb_bn   = (const float*)d_in[22];
    float* out = (float*)d_out;

    float *xT3, *sqn, *dist, *xcT, *h, *q, *kk, *v, *xr, *ffb;
    int* idxp;
    cudaGetSymbolAddress((void**)&xT3, g_xT3);
    cudaGetSymbolAddress((void**)&sqn, g_sqn);
    cudaGetSymbolAddress((void**)&dist, g_dist);
    cudaGetSymbolAddress((void**)&idxp, g_idx);
    cudaGetSymbolAddress((void**)&xcT, g_xcT);
    cudaGetSymbolAddress((void**)&h, g_h);
    cudaGetSymbolAddress((void**)&q, g_q);
    cudaGetSymbolAddress((void**)&kk, g_k);
    cudaGetSymbolAddress((void**)&v, g_v);
    cudaGetSymbolAddress((void**)&xr, g_xr);
    cudaGetSymbolAddress((void**)&ffb, g_ffb);

    const size_t sm3  = (size_t)(6 * 64 + 4096 + 32 * 6 + 64 * 33 + 256 + 4 + 32) * 4;
    const size_t sm64 = (size_t)(128 * 64 + 4096 + 32 * 128 + 64 * 33 + 256 + 64 + 32) * 4;
    cudaFuncSetAttribute((const void*)edgeconv_kernel<64>,
                         cudaFuncAttributeMaxDynamicSharedMemorySize, (int)sm64);

    const int npts = BB * NPTS;
    const ll CH = (ll)1024 * NPTS;
    const ll AT = (ll)NPTS * NPTS;
    const ll total = (ll)BB * 1024 * NPTS;

    transpose_x_kernel<<<(npts + 255) / 256, 256>>>(x, xT3);

    // ---- EdgeConv 1 (C=3) ----
    sqnorm_kernel<<<(npts + 255) / 256, 256>>>(xT3, 3, 0, 3, sqn);
    dim3 gd(NPTS / 128, NPTS / 128, BB);
    gemm_kernel<0, 1, 3><<<gd, 256>>>(xT3, xT3, dist, NPTS, NPTS, 3, 3, 3, NPTS,
                                      (ll)NPTS * 3, (ll)NPTS * 3, AT,
                                      sqn, sqn, NPTS, NPTS, 0);
    topk_kernel<<<npts, 256>>>(dist, idxp);
    edgeconv_kernel<3><<<1024, 256, sm3>>>(xT3, 3, 0, idxp, ec1_w1, ec1_bn1, ec1_w2, ec1_bn2,
                                           xcT, 192, 0);

    // ---- EdgeConv 2 (C=64, input f1 = xcT cols [0,64)) ----
    sqnorm_kernel<<<(npts + 255) / 256, 256>>>(xcT, 192, 0, 64, sqn);
    gemm_kernel<0, 1, 3><<<gd, 256>>>(xcT, xcT, dist, NPTS, NPTS, 64, 192, 192, NPTS,
                                      (ll)NPTS * 192, (ll)NPTS * 192, AT,
                                      sqn, sqn, NPTS, NPTS, 0);
    topk_kernel<<<npts, 256>>>(dist, idxp);
    edgeconv_kernel<64><<<1024, 256, sm64>>>(xcT, 192, 0, idxp, ec2_w1, ec2_bn1, ec2_w2, ec2_bn2,
                                             xcT, 192, 64);

    // ---- EdgeConv 3 (C=64, input f2 = xcT cols [64,128)) ----
    sqnorm_kernel<<<(npts + 255) / 256, 256>>>(xcT, 192, 64, 64, sqn);
    gemm_kernel<0, 1, 3><<<gd, 256>>>(xcT + 64, xcT + 64, dist, NPTS, NPTS, 64, 192, 192, NPTS,
                                      (ll)NPTS * 192, (ll)NPTS * 192, AT,
                                      sqn, sqn, NPTS, NPTS, 0);
    topk_kernel<<<npts, 256>>>(dist, idxp);
    edgeconv_kernel<64><<<1024, 256, sm64>>>(xcT, 192, 64, idxp, ec3_w1, ec3_bn1, ec3_w2, ec3_bn2,
                                             xcT, 192, 128);

    // ---- embedding + attention + FF + classifier ----
    dim3 ge(NPTS / 128, 1024 / 128, BB);
    gemm_kernel<0, 1, 0><<<ge, 256>>>(emb_w, xcT, h, 1024, NPTS, 192, 192, 192, NPTS,
                                      0, (ll)NPTS * 192, CH, nullptr, nullptr, 0, 0, 0);
    gemm_kernel<0, 0, 0><<<ge, 256>>>(q_w, h, q, 1024, NPTS, 1024, 1024, NPTS, NPTS,
                                      0, CH, CH, nullptr, nullptr, 0, 0, 0);
    gemm_kernel<0, 0, 0><<<ge, 256>>>(k_w, h, kk, 1024, NPTS, 1024, 1024, NPTS, NPTS,
                                      0, CH, CH, nullptr, nullptr, 0, 0, 0);
    gemm_kernel<0, 0, 0><<<ge, 256>>>(v_w, h, v, 1024, NPTS, 1024, 1024, NPTS, NPTS,
                                      0, CH, CH, nullptr, nullptr, 0, 0, 0);
    dim3 ga(NPTS / 128, NPTS / 128, BB);
    gemm_kernel<1, 0, 0><<<ga, 256>>>(q, kk, dist, NPTS, NPTS, 1024, NPTS, NPTS, NPTS,
                                      CH, CH, AT, nullptr, nullptr, 0, 0, 0);
    softmax_kernel<<<npts, 256>>>(dist);
    gemm_kernel<0, 1, 0><<<ge, 256>>>(v, dist, xr, 1024, NPTS, NPTS, NPTS, NPTS, NPTS,
                                      CH, AT, CH, nullptr, nullptr, 0, 0, 0);
    addbn_kernel<<<(int)((total + 255) / 256), 256>>>(h, xr, att_bn1, q /*h2*/, 1024, total);
    dim3 gf(NPTS / 128, 512 / 128, BB);
    gemm_kernel<0, 0, 1><<<gf, 256>>>(ff_w1, q, ffb, 512, NPTS, 1024, 1024, NPTS, NPTS,
                                      0, CH, (ll)512 * NPTS, nullptr, nullptr, 0, 0, 0);
    gemm_kernel<0, 0, 0><<<ge, 256>>>(ff_w2, ffb, kk /*ff out*/, 1024, NPTS, 512, 512, NPTS, NPTS,
                                      0, (ll)512 * NPTS, CH, nullptr, nullptr, 0, 0, 0);
    addbn_kernel<<<(int)((total + 255) / 256), 256>>>(q, kk, att_bn2, v /*h3*/, 1024, total);
    gemm_kernel<0, 0, 2><<<ge, 256>>>(cb_w, v, out, 1024, NPTS, 1024, 1024, NPTS, NPTS,
                                      0, CH, CH, cb_bn, nullptr, 0, 0, 1024);
}

// round 5
// speedup vs baseline: 2.1623x; 2.1623x over previous
#include <cuda_runtime.h>
#include <cuda_bf16.h>
#include <cstdint>

#define BB 8
#define NPTS 2048
#define KNN 32
typedef long long ll;
typedef uint32_t u32;
typedef unsigned short u16;

// ==================== scratch (device globals) ====================
static __device__ float g_xT3[BB * NPTS * 3];
static __device__ float g_sqn[BB * NPTS];
static __device__ float g_dist[(ll)BB * NPTS * NPTS];   // fp32 dist; reused (as u32) for logits/att
static __device__ int   g_idx[BB * NPTS * KNN];
static __device__ float g_xcT[BB * NPTS * 192];
static __device__ u32   g_xchl[BB * NPTS * 192];
static __device__ u32   g_h [(ll)BB * NPTS * 1024];
static __device__ u32   g_q [(ll)BB * NPTS * 1024];     // later h2
static __device__ u32   g_k [(ll)BB * NPTS * 1024];     // later ff out
static __device__ u32   g_v [(ll)BB * NPTS * 1024];     // later h3
static __device__ u32   g_xr[(ll)BB * NPTS * 1024];
static __device__ u32   g_ffo[(ll)BB * NPTS * 512];
static __device__ u32   g_embw[1024 * 192];
static __device__ u32   g_qw[1024 * 1024];
static __device__ u32   g_kw[1024 * 1024];
static __device__ u32   g_vw[1024 * 1024];
static __device__ u32   g_f1w[512 * 1024];
static __device__ u32   g_f2w[1024 * 512];
static __device__ u32   g_cw[1024 * 1024];

// ==================== helpers ====================
__device__ __forceinline__ u32 pack_hl(float v) {
    __nv_bfloat16 h = __float2bfloat16(v);
    float r = v - __bfloat162float(h);
    __nv_bfloat16 l = __float2bfloat16(r);
    return (u32)__bfloat16_as_ushort(h) | ((u32)__bfloat16_as_ushort(l) << 16);
}
__device__ __forceinline__ float unpack_hl(u32 u) {
    return __bfloat162float(__ushort_as_bfloat16((u16)(u & 0xffffu)))
         + __bfloat162float(__ushort_as_bfloat16((u16)(u >> 16)));
}
__device__ __forceinline__ void mma16816(float* c, u32 a0, u32 a1, u32 a2, u32 a3, u32 b0, u32 b1) {
    asm volatile("mma.sync.aligned.m16n8k16.row.col.f32.bf16.bf16.f32 "
                 "{%0,%1,%2,%3}, {%4,%5,%6,%7}, {%8,%9}, {%0,%1,%2,%3};"
                 : "+f"(c[0]), "+f"(c[1]), "+f"(c[2]), "+f"(c[3])
                 : "r"(a0), "r"(a1), "r"(a2), "r"(a3), "r"(b0), "r"(b1));
}

// ==================== small kernels ====================
__global__ void transpose_x_kernel(const float* __restrict__ x, float* __restrict__ xt) {
    int i = blockIdx.x * blockDim.x + threadIdx.x;
    if (i >= BB * NPTS) return;
    int b = i / NPTS, n = i % NPTS;
#pragma unroll
    for (int c = 0; c < 3; c++)
        xt[i * 3 + c] = x[(b * 3 + c) * NPTS + n];
}

__global__ void sqnorm_kernel(const float* __restrict__ xt, int rs, int off, int C,
                              float* __restrict__ sq) {
    int i = blockIdx.x * blockDim.x + threadIdx.x;
    if (i >= BB * NPTS) return;
    const float* p = xt + (ll)i * rs + off;
    float s = 0.f;
    for (int c = 0; c < C; c++) { float v = p[c]; s += v * v; }
    sq[i] = s;
}

__global__ void split_kernel(const float* __restrict__ in, u32* __restrict__ out, ll n) {
    ll i = (ll)blockIdx.x * blockDim.x + threadIdx.x;
    if (i < n) out[i] = pack_hl(in[i]);
}

// ==================== SIMT SGEMM for kNN distances ====================
__global__ __launch_bounds__(256, 2)
void distgemm_kernel(const float* __restrict__ A, float* __restrict__ C, int K, int lda,
                     ll sA, const float* __restrict__ sq) {
    __shared__ float As[16][132];
    __shared__ float Bs[16][132];
    const int tid = threadIdx.x;
    const int tx = tid & 15, ty = tid >> 4;
    const int i0 = blockIdx.y * 128, j0 = blockIdx.x * 128;
    const int bz = blockIdx.z;
    const float* Ab = A + (ll)bz * sA;
    float acc[8][8];
#pragma unroll
    for (int i = 0; i < 8; i++)
#pragma unroll
        for (int j = 0; j < 8; j++) acc[i][j] = 0.f;
    for (int k0 = 0; k0 < K; k0 += 16) {
        for (int t = tid; t < 2048; t += 256) {
            int kq = t & 15, i = t >> 4;
            int gk = k0 + kq;
            As[kq][i] = (gk < K) ? Ab[(ll)(i0 + i) * lda + gk] : 0.f;
        }
        for (int t = tid; t < 2048; t += 256) {
            int kq = t & 15, j = t >> 4;
            int gk = k0 + kq;
            Bs[kq][j] = (gk < K) ? Ab[(ll)(j0 + j) * lda + gk] : 0.f;
        }
        __syncthreads();
#pragma unroll
        for (int kq = 0; kq < 16; kq++) {
            float4 a0 = *(const float4*)&As[kq][ty * 8];
            float4 a1 = *(const float4*)&As[kq][ty * 8 + 4];
            float4 b0 = *(const float4*)&Bs[kq][tx * 8];
            float4 b1 = *(const float4*)&Bs[kq][tx * 8 + 4];
            float a[8] = {a0.x, a0.y, a0.z, a0.w, a1.x, a1.y, a1.z, a1.w};
            float b[8] = {b0.x, b0.y, b0.z, b0.w, b1.x, b1.y, b1.z, b1.w};
#pragma unroll
            for (int i = 0; i < 8; i++)
#pragma unroll
                for (int j = 0; j < 8; j++) acc[i][j] += a[i] * b[j];
        }
        __syncthreads();
    }
    float* Cb = C + (ll)bz * NPTS * NPTS;
    const float* sqb = sq + (ll)bz * NPTS;
#pragma unroll
    for (int ii = 0; ii < 8; ii++) {
        int gi = i0 + ty * 8 + ii;
        float sqi = sqb[gi];
#pragma unroll
        for (int jj = 0; jj < 8; jj++) {
            int gj = j0 + tx * 8 + jj;
            Cb[(ll)gi * NPTS + gj] = sqi + sqb[gj] - 2.f * acc[ii][jj];
        }
    }
}

// ==================== top-k: warp argmin, 2 stages ====================
__global__ __launch_bounds__(256)
void topk_kernel(const float* __restrict__ dist, int* __restrict__ out) {
    __shared__ float cv[256];
    __shared__ int   ci[256];
    const int tid = threadIdx.x;
    const int w = tid >> 5, lane = tid & 31;
    const float* rp = dist + (ll)blockIdx.x * NPTS;
    const int base = w * 256;
    float v[8];
#pragma unroll
    for (int j = 0; j < 8; j++) v[j] = rp[base + j * 32 + lane];
    for (int s = 0; s < KNN; s++) {
        float bv = 3.4e38f; int bj = 0;
#pragma unroll
        for (int j = 0; j < 8; j++)
            if (v[j] < bv) { bv = v[j]; bj = j; }
        int bidx = base + bj * 32 + lane;
#pragma unroll
        for (int o = 16; o > 0; o >>= 1) {
            float ov = __shfl_xor_sync(0xffffffffu, bv, o);
            int   oi = __shfl_xor_sync(0xffffffffu, bidx, o);
            if (ov < bv || (ov == bv && oi < bidx)) { bv = ov; bidx = oi; }
        }
        if ((bidx & 31) == lane) {
            int wj = (bidx >> 5) & 7;
#pragma unroll
            for (int j = 0; j < 8; j++)
                if (j == wj) v[j] = 3.4e38f;
        }
        if (lane == 0) { cv[w * 32 + s] = bv; ci[w * 32 + s] = bidx; }
    }
    __syncthreads();
    if (w == 0) {
        float mv[8]; int mi[8];
#pragma unroll
        for (int j = 0; j < 8; j++) { mv[j] = cv[lane * 8 + j]; mi[j] = ci[lane * 8 + j]; }
        int* op = out + (ll)blockIdx.x * KNN;
        for (int s = 0; s < KNN; s++) {
            float bv = 3.4e38f; int bidx = 0x7fffffff; int bj = 0;
#pragma unroll
            for (int j = 0; j < 8; j++)
                if (mv[j] < bv || (mv[j] == bv && mi[j] < bidx)) { bv = mv[j]; bidx = mi[j]; bj = j; }
            int lb = bidx;
#pragma unroll
            for (int o = 16; o > 0; o >>= 1) {
                float ov = __shfl_xor_sync(0xffffffffu, bv, o);
                int   oi = __shfl_xor_sync(0xffffffffu, bidx, o);
                if (ov < bv || (ov == bv && oi < bidx)) { bv = ov; bidx = oi; }
            }
            if (lb == bidx) {
#pragma unroll
                for (int j = 0; j < 8; j++)
                    if (j == bj) mv[j] = 3.4e38f;
            }
            if (lane == 0) op[s] = bidx;
        }
    }
}

// ==================== fused EdgeConv ====================
template <int CIN>
__global__ __launch_bounds__(256)
void edgeconv_kernel(const float* __restrict__ xin, int rsin, int offin,
                     const int* __restrict__ idx,
                     const float* __restrict__ w1, const float* __restrict__ bn1,
                     const float* __restrict__ w2, const float* __restrict__ bn2,
                     float* __restrict__ xout, int rsout, int offout) {
    constexpr int C2 = 2 * CIN;
    extern __shared__ float sm[];
    float* w1s = sm;
    float* w2s = w1s + C2 * 64;
    float* es  = w2s + 4096;
    float* h1s = es + 32 * C2;
    float* red = h1s + 64 * 33;
    float* ctr = red + 256;
    int*   iks = (int*)(ctr + ((CIN + 3) & ~3));

    const int tid = threadIdx.x;
    const int o = tid & 63, kg = tid >> 6;
    for (int t = tid; t < 64 * C2; t += 256) { int oo = t & 63, c = t >> 6; w1s[t] = w1[oo * C2 + c]; }
    for (int t = tid; t < 4096; t += 256)    { int oo = t & 63, c = t >> 6; w2s[t] = w2[oo * 64 + c]; }
    const float s1 = bn1[o] * rsqrtf(bn1[192 + o] + 1e-5f);
    const float t1 = bn1[64 + o] - bn1[128 + o] * s1;
    const float s2 = bn2[o] * rsqrtf(bn2[192 + o] + 1e-5f);
    const float t2 = bn2[64 + o] - bn2[128 + o] * s2;
    __syncthreads();
    for (int p = blockIdx.x; p < BB * NPTS; p += gridDim.x) {
        const int b = p >> 11;
        if (tid < CIN) ctr[tid] = xin[(ll)p * rsin + offin + tid];
        if (tid < KNN) iks[tid] = idx[p * KNN + tid];
        __syncthreads();
        for (int t = tid; t < KNN * CIN; t += 256) {
            int kq = t / CIN, c = t - kq * CIN;
            int m = iks[kq];
            float v = xin[(ll)(b * NPTS + m) * rsin + offin + c];
            es[kq * C2 + c] = v - ctr[c];
            es[kq * C2 + CIN + c] = ctr[c];
        }
        __syncthreads();
        float acc[8];
#pragma unroll
        for (int j = 0; j < 8; j++) acc[j] = 0.f;
        for (int c = 0; c < C2; c++) {
            float w = w1s[c * 64 + o];
#pragma unroll
            for (int j = 0; j < 8; j++) acc[j] += w * es[(kg * 8 + j) * C2 + c];
        }
#pragma unroll
        for (int j = 0; j < 8; j++) {
            float v = acc[j] * s1 + t1;
            v = v >= 0.f ? v : 0.2f * v;
            h1s[o * 33 + kg * 8 + j] = v;
            acc[j] = 0.f;
        }
        __syncthreads();
        for (int c = 0; c < 64; c++) {
            float w = w2s[c * 64 + o];
#pragma unroll
            for (int j = 0; j < 8; j++) acc[j] += w * h1s[c * 33 + kg * 8 + j];
        }
        float mx = -3.4e38f;
#pragma unroll
        for (int j = 0; j < 8; j++) {
            float v = acc[j] * s2 + t2;
            v = v >= 0.f ? v : 0.2f * v;
            mx = fmaxf(mx, v);
        }
        red[kg * 64 + o] = mx;
        __syncthreads();
        if (kg == 0) {
            float m = fmaxf(fmaxf(red[o], red[64 + o]), fmaxf(red[128 + o], red[192 + o]));
            xout[(ll)p * rsout + offout + o] = m;
        }
        __syncthreads();
    }
}

// ==================== mma.sync split-bf16 GEMM ====================
// C[i,j] = sum_k Af(i,k)*Bf(j,k); A,B packed hi/lo u32; fp32 accum.
// A smem tile used verbatim (u32 = (Ah,Al) bf16 pair => K' doubled);
// B expanded to (Bh,Bh) + (Bl,Bl) dup tiles; both passes accumulate.
// EPI: 0 pack store, 1 lrelu+pack, 2 BN+lrelu fp32 store
template <int EPI>
__global__ __launch_bounds__(256)
void mmamm_kernel(const u32* __restrict__ A, const u32* __restrict__ B,
                  u32* __restrict__ Co, float* __restrict__ Cf,
                  int K, int sAm, int sAk, int sBn, int sBk, int ldc,
                  ll strideA, ll strideB, ll strideC, const float* __restrict__ bn) {
    extern __shared__ u32 smu[];
    u32 (*As)[36] = (u32(*)[36])smu;            // 128 x 36
    u32 (*Bh)[36] = (u32(*)[36])(smu + 128 * 36);
    u32 (*Bl)[36] = (u32(*)[36])(smu + 2 * 128 * 36);
    const int tid = threadIdx.x, lane = tid & 31, w = tid >> 5;
    const int mw = (w & 1) * 64, nw = (w >> 1) * 32;
    const int i0 = blockIdx.y * 128, j0 = blockIdx.x * 128, bz = blockIdx.z;
    const u32* Ab = A + (ll)bz * strideA;
    const u32* Bb = B + (ll)bz * strideB;
    const int lq = lane >> 2, lr = lane & 3;

    float acc[4][4][4];
#pragma unroll
    for (int a = 0; a < 4; a++)
#pragma unroll
        for (int b = 0; b < 4; b++)
#pragma unroll
            for (int c = 0; c < 4; c++) acc[a][b][c] = 0.f;

    for (int k0 = 0; k0 < K; k0 += 32) {
        if (sAk == 1) {
            for (int t = tid; t < 4096; t += 256) {
                int kk = t & 31, m = t >> 5;
                As[m][kk] = Ab[(ll)(i0 + m) * sAm + (k0 + kk)];
            }
        } else {
            for (int t = tid; t < 4096; t += 256) {
                int m = t & 127, kk = t >> 7;
                As[m][kk] = Ab[(ll)(i0 + m) + (ll)(k0 + kk) * sAk];
            }
        }
        if (sBk == 1) {
            for (int t = tid; t < 4096; t += 256) {
                int kk = t & 31, n = t >> 5;
                u32 wv = Bb[(ll)(j0 + n) * sBn + (k0 + kk)];
                Bh[n][kk] = (wv & 0xffffu) * 0x10001u;
                Bl[n][kk] = (wv >> 16) * 0x10001u;
            }
        } else {
            for (int t = tid; t < 4096; t += 256) {
                int n = t & 127, kk = t >> 7;
                u32 wv = Bb[(ll)(j0 + n) + (ll)(k0 + kk) * sBk];
                Bh[n][kk] = (wv & 0xffffu) * 0x10001u;
                Bl[n][kk] = (wv >> 16) * 0x10001u;
            }
        }
        __syncthreads();
#pragma unroll
        for (int ks = 0; ks < 4; ks++) {
            const int kw = ks * 8;
            u32 bh[4][2], bl[4][2];
#pragma unroll
            for (int nt = 0; nt < 4; nt++) {
                int n = nw + nt * 8 + lq;
                bh[nt][0] = Bh[n][kw + lr];     bh[nt][1] = Bh[n][kw + 4 + lr];
                bl[nt][0] = Bl[n][kw + lr];     bl[nt][1] = Bl[n][kw + 4 + lr];
            }
#pragma unroll
            for (int mt = 0; mt < 4; mt++) {
                int m = mw + mt * 16 + lq;
                u32 a0 = As[m][kw + lr], a1 = As[m + 8][kw + lr];
                u32 a2 = As[m][kw + 4 + lr], a3 = As[m + 8][kw + 4 + lr];
#pragma unroll
                for (int nt = 0; nt < 4; nt++) {
                    mma16816(acc[mt][nt], a0, a1, a2, a3, bh[nt][0], bh[nt][1]);
                    mma16816(acc[mt][nt], a0, a1, a2, a3, bl[nt][0], bl[nt][1]);
                }
            }
        }
        __syncthreads();
    }

    // ---- epilogue: direct fragment stores ----
#pragma unroll
    for (int mt = 0; mt < 4; mt++) {
#pragma unroll
        for (int nt = 0; nt < 4; nt++) {
        int gm0 = i0 + mw + mt * 16 + lq;
        int gn  = j0 + nw + nt * 8 + lr * 2;
#pragma unroll
        for (int half = 0; half < 2; half++) {
            int gm = gm0 + half * 8;
            float v0 = acc[mt][nt][half * 2], v1 = acc[mt][nt][half * 2 + 1];
            if (EPI == 0) {
                uint2 pv = make_uint2(pack_hl(v0), pack_hl(v1));
                *(uint2*)&Co[(ll)bz * strideC + (ll)gm * ldc + gn] = pv;
            } else if (EPI == 1) {
                v0 = v0 >= 0.f ? v0 : 0.2f * v0;
                v1 = v1 >= 0.f ? v1 : 0.2f * v1;
                uint2 pv = make_uint2(pack_hl(v0), pack_hl(v1));
                *(uint2*)&Co[(ll)bz * strideC + (ll)gm * ldc + gn] = pv;
            } else {
                float g = bn[gm], be = bn[1024 + gm], mm = bn[2048 + gm], va = bn[3072 + gm];
                float s = g * rsqrtf(va + 1e-5f);
                float t = be - mm * s;
                v0 = v0 * s + t; v0 = v0 >= 0.f ? v0 : 0.2f * v0;
                v1 = v1 * s + t; v1 = v1 >= 0.f ? v1 : 0.2f * v1;
                *(float2*)&Cf[(ll)bz * strideC + (ll)gm * ldc + gn] = make_float2(v0, v1);
            }
        }
        }
    }
}

// ==================== softmax over packed rows (scale 1/32) ====================
__global__ __launch_bounds__(256)
void softmax_hl_kernel(u32* __restrict__ att) {
    __shared__ float sd[NPTS];
    __shared__ float red[256];
    const int tid = threadIdx.x;
    u32* p = att + (ll)blockIdx.x * NPTS;
    float mx = -3.4e38f;
    for (int t = tid; t < NPTS; t += 256) {
        float v = unpack_hl(p[t]) * 0.03125f;
        sd[t] = v;
        mx = fmaxf(mx, v);
    }
    red[tid] = mx;
    __syncthreads();
    for (int h = 128; h > 0; h >>= 1) {
        if (tid < h) red[tid] = fmaxf(red[tid], red[tid + h]);
        __syncthreads();
    }
    mx = red[0];
    __syncthreads();
    float sum = 0.f;
    for (int t = tid; t < NPTS; t += 256) {
        float e = __expf(sd[t] - mx);
        sd[t] = e;
        sum += e;
    }
    red[tid] = sum;
    __syncthreads();
    for (int h = 128; h > 0; h >>= 1) {
        if (tid < h) red[tid] += red[tid + h];
        __syncthreads();
    }
    float inv = 1.f / red[0];
    __syncthreads();
    for (int t = tid; t < NPTS; t += 256) p[t] = pack_hl(sd[t] * inv);
}

// ==================== residual add + BN (packed) ====================
__global__ void addbn_hl_kernel(const u32* __restrict__ a, const u32* __restrict__ r,
                                const float* __restrict__ bn, u32* __restrict__ out, ll total) {
    ll i = (ll)blockIdx.x * blockDim.x + threadIdx.x;
    if (i >= total) return;
    int c = (int)((i >> 11) & 1023);
    float g = bn[c], be = bn[1024 + c], m = bn[2048 + c], va = bn[3072 + c];
    float s = g * rsqrtf(va + 1e-5f);
    float v = (unpack_hl(a[i]) + unpack_hl(r[i])) * s + (be - m * s);
    out[i] = pack_hl(v);
}

// ==================== launcher ====================
extern "C" void kernel_launch(void* const* d_in, const int* in_sizes, int n_in,
                              void* d_out, int out_size) {
    const float* x       = (const float*)d_in[0];
    const float* ec1_w1  = (const float*)d_in[1];
    const float* ec1_bn1 = (const float*)d_in[2];
    const float* ec1_w2  = (const float*)d_in[3];
    const float* ec1_bn2 = (const float*)d_in[4];
    const float* ec2_w1  = (const float*)d_in[5];
    const float* ec2_bn1 = (const float*)d_in[6];
    const float* ec2_w2  = (const float*)d_in[7];
    const float* ec2_bn2 = (const float*)d_in[8];
    const float* ec3_w1  = (const float*)d_in[9];
    const float* ec3_bn1 = (const float*)d_in[10];
    const float* ec3_w2  = (const float*)d_in[11];
    const float* ec3_bn2 = (const float*)d_in[12];
    const float* emb_w   = (const float*)d_in[13];
    const float* q_w     = (const float*)d_in[14];
    const float* k_w     = (const float*)d_in[15];
    const float* v_w     = (const float*)d_in[16];
    const float* att_bn1 = (const float*)d_in[17];
    const float* ff_w1   = (const float*)d_in[18];
    const float* ff_w2   = (const float*)d_in[19];
    const float* att_bn2 = (const float*)d_in[20];
    const float* cb_w    = (const float*)d_in[21];
    const float* cb_bn   = (const float*)d_in[22];
    float* out = (float*)d_out;

    float *xT3, *sqn, *dist, *xcT;
    u32 *xchl, *h, *q, *kk, *v, *xr, *ffo, *embw, *qw, *kw, *vw, *f1w, *f2w, *cw;
    int* idxp;
    cudaGetSymbolAddress((void**)&xT3, g_xT3);
    cudaGetSymbolAddress((void**)&sqn, g_sqn);
    cudaGetSymbolAddress((void**)&dist, g_dist);
    cudaGetSymbolAddress((void**)&idxp, g_idx);
    cudaGetSymbolAddress((void**)&xcT, g_xcT);
    cudaGetSymbolAddress((void**)&xchl, g_xchl);
    cudaGetSymbolAddress((void**)&h, g_h);
    cudaGetSymbolAddress((void**)&q, g_q);
    cudaGetSymbolAddress((void**)&kk, g_k);
    cudaGetSymbolAddress((void**)&v, g_v);
    cudaGetSymbolAddress((void**)&xr, g_xr);
    cudaGetSymbolAddress((void**)&ffo, g_ffo);
    cudaGetSymbolAddress((void**)&embw, g_embw);
    cudaGetSymbolAddress((void**)&qw, g_qw);
    cudaGetSymbolAddress((void**)&kw, g_kw);
    cudaGetSymbolAddress((void**)&vw, g_vw);
    cudaGetSymbolAddress((void**)&f1w, g_f1w);
    cudaGetSymbolAddress((void**)&f2w, g_f2w);
    cudaGetSymbolAddress((void**)&cw, g_cw);

    const size_t sm3  = (size_t)(6 * 64 + 4096 + 32 * 6 + 64 * 33 + 256 + 4 + 32) * 4;
    const size_t sm64 = (size_t)(128 * 64 + 4096 + 32 * 128 + 64 * 33 + 256 + 64 + 32) * 4;
    cudaFuncSetAttribute((const void*)edgeconv_kernel<64>,
                         cudaFuncAttributeMaxDynamicSharedMemorySize, (int)sm64);
    const int SMTC = 3 * 128 * 36 * 4;  // 55296 B
    cudaFuncSetAttribute((const void*)mmamm_kernel<0>, cudaFuncAttributeMaxDynamicSharedMemorySize, SMTC);
    cudaFuncSetAttribute((const void*)mmamm_kernel<1>, cudaFuncAttributeMaxDynamicSharedMemorySize, SMTC);
    cudaFuncSetAttribute((const void*)mmamm_kernel<2>, cudaFuncAttributeMaxDynamicSharedMemorySize, SMTC);

    const int npts = BB * NPTS;
    const ll CH = (ll)1024 * NPTS;
    const ll AT = (ll)NPTS * NPTS;
    const ll total = (ll)BB * 1024 * NPTS;

    transpose_x_kernel<<<(npts + 255) / 256, 256>>>(x, xT3);

    dim3 gd(NPTS / 128, NPTS / 128, BB);
    // EdgeConv 1 (C=3)
    sqnorm_kernel<<<(npts + 255) / 256, 256>>>(xT3, 3, 0, 3, sqn);
    distgemm_kernel<<<gd, 256>>>(xT3, dist, 3, 3, (ll)NPTS * 3, sqn);
    topk_kernel<<<npts, 256>>>(dist, idxp);
    edgeconv_kernel<3><<<1024, 256, sm3>>>(xT3, 3, 0, idxp, ec1_w1, ec1_bn1, ec1_w2, ec1_bn2, xcT, 192, 0);
    // EdgeConv 2
    sqnorm_kernel<<<(npts + 255) / 256, 256>>>(xcT, 192, 0, 64, sqn);
    distgemm_kernel<<<gd, 256>>>(xcT, dist, 64, 192, (ll)NPTS * 192, sqn);
    topk_kernel<<<npts, 256>>>(dist, idxp);
    edgeconv_kernel<64><<<1024, 256, sm64>>>(xcT, 192, 0, idxp, ec2_w1, ec2_bn1, ec2_w2, ec2_bn2, xcT, 192, 64);
    // EdgeConv 3
    sqnorm_kernel<<<(npts + 255) / 256, 256>>>(xcT, 192, 64, 64, sqn);
    distgemm_kernel<<<gd, 256>>>(xcT + 64, dist, 64, 192, (ll)NPTS * 192, sqn);
    topk_kernel<<<npts, 256>>>(dist, idxp);
    edgeconv_kernel<64><<<1024, 256, sm64>>>(xcT, 192, 64, idxp, ec3_w1, ec3_bn1, ec3_w2, ec3_bn2, xcT, 192, 128);

    // pack activations + weights to hi/lo
    split_kernel<<<(int)(((ll)npts * 192 + 255) / 256), 256>>>(xcT, xchl, (ll)npts * 192);
    split_kernel<<<(1024 * 192 + 255) / 256, 256>>>(emb_w, embw, 1024 * 192);
    split_kernel<<<(1024 * 1024 + 255) / 256, 256>>>(q_w, qw, 1024 * 1024);
    split_kernel<<<(1024 * 1024 + 255) / 256, 256>>>(k_w, kw, 1024 * 1024);
    split_kernel<<<(1024 * 1024 + 255) / 256, 256>>>(v_w, vw, 1024 * 1024);
    split_kernel<<<(512 * 1024 + 255) / 256, 256>>>(ff_w1, f1w, 512 * 1024);
    split_kernel<<<(512 * 1024 + 255) / 256, 256>>>(ff_w2, f2w, 512 * 1024);
    split_kernel<<<(1024 * 1024 + 255) / 256, 256>>>(cb_w, cw, 1024 * 1024);

    u32* distu = (u32*)dist;
    dim3 ge(NPTS / 128, 1024 / 128, BB);
    dim3 ga(NPTS / 128, NPTS / 128, BB);
    dim3 gf(NPTS / 128, 512 / 128, BB);
    // h = emb_w @ xc
    mmamm_kernel<0><<<ge, 256, SMTC>>>(embw, xchl, h, nullptr, 192, 192, 1, 192, 1, NPTS,
                                       0, (ll)NPTS * 192, CH, nullptr);
    // q, k, v
    mmamm_kernel<0><<<ge, 256, SMTC>>>(qw, h, q, nullptr, 1024, 1024, 1, 1, NPTS, NPTS, 0, CH, CH, nullptr);
    mmamm_kernel<0><<<ge, 256, SMTC>>>(kw, h, kk, nullptr, 1024, 1024, 1, 1, NPTS, NPTS, 0, CH, CH, nullptr);
    mmamm_kernel<0><<<ge, 256, SMTC>>>(vw, h, v, nullptr, 1024, 1024, 1, 1, NPTS, NPTS, 0, CH, CH, nullptr);
    // logits[n,m] = sum_c q[c,n] k[c,m]
    mmamm_kernel<0><<<ga, 256, SMTC>>>(q, kk, distu, nullptr, 1024, 1, NPTS, 1, NPTS, NPTS, CH, CH, AT, nullptr);
    softmax_hl_kernel<<<npts, 256>>>(distu);
    // xr[c,n] = sum_m v[c,m] att[n,m]
    mmamm_kernel<0><<<ge, 256, SMTC>>>(v, distu, xr, nullptr, NPTS, NPTS, 1, NPTS, 1, NPTS, CH, AT, CH, nullptr);
    addbn_hl_kernel<<<(int)((total + 255) / 256), 256>>>(h, xr, att_bn1, q /*h2*/, total);
    // ff
    mmamm_kernel<1><<<gf, 256, SMTC>>>(f1w, q, ffo, nullptr, 1024, 1024, 1, 1, NPTS, NPTS, 0, CH, (ll)512 * NPTS, nullptr);
    mmamm_kernel<0><<<ge, 256, SMTC>>>(f2w, ffo, kk /*ff*/, nullptr, 512, 512, 1, 1, NPTS, NPTS, 0, (ll)512 * NPTS, CH, nullptr);
    addbn_hl_kernel<<<(int)((total + 255) / 256), 256>>>(q, kk, att_bn2, v /*h3*/, total);
    // classifier: BN + lrelu, fp32 out
    mmamm_kernel<2><<<ge, 256, SMTC>>>(cw, v, nullptr, out, 1024, 1024, 1, 1, NPTS, NPTS, 0, CH, CH, cb_bn);
}

// round 8
// speedup vs baseline: 2.4539x; 1.1349x over previous
#include <cuda_runtime.h>
#include <cuda_bf16.h>
#include <cstdint>

#define BB 8
#define NPTS 2048
#define KNN 32
typedef long long ll;
typedef uint32_t u32;
typedef unsigned short u16;

// ==================== scratch (device globals) ====================
static __device__ float g_xT3[BB * NPTS * 3];
static __device__ float g_sqn[BB * NPTS];
static __device__ float g_dist[(ll)BB * NPTS * NPTS];   // fp32 dist; reused (as u32) for logits/att
static __device__ int   g_idx[BB * NPTS * KNN];
static __device__ float g_xcT[BB * NPTS * 192];
static __device__ u32   g_xchl[BB * NPTS * 192];
static __device__ u32   g_h [(ll)BB * NPTS * 1024];
static __device__ u32   g_q [(ll)BB * NPTS * 1024];     // later h2
static __device__ u32   g_k [(ll)BB * NPTS * 1024];     // later ff out
static __device__ u32   g_v [(ll)BB * NPTS * 1024];     // later h3
static __device__ u32   g_xr[(ll)BB * NPTS * 1024];
static __device__ u32   g_ffo[(ll)BB * NPTS * 512];
static __device__ u32   g_embw[1024 * 192];
static __device__ u32   g_qw[1024 * 1024];
static __device__ u32   g_kw[1024 * 1024];
static __device__ u32   g_vw[1024 * 1024];
static __device__ u32   g_f1w[512 * 1024];
static __device__ u32   g_f2w[1024 * 512];
static __device__ u32   g_cw[1024 * 1024];

// ==================== helpers ====================
__device__ __forceinline__ u32 pack_hl(float v) {
    __nv_bfloat16 h = __float2bfloat16(v);
    float r = v - __bfloat162float(h);
    __nv_bfloat16 l = __float2bfloat16(r);
    return (u32)__bfloat16_as_ushort(h) | ((u32)__bfloat16_as_ushort(l) << 16);
}
__device__ __forceinline__ float unpack_hl(u32 u) {
    return __bfloat162float(__ushort_as_bfloat16((u16)(u & 0xffffu)))
         + __bfloat162float(__ushort_as_bfloat16((u16)(u >> 16)));
}
__device__ __forceinline__ void mma16816(float* c, u32 a0, u32 a1, u32 a2, u32 a3, u32 b0, u32 b1) {
    asm volatile("mma.sync.aligned.m16n8k16.row.col.f32.bf16.bf16.f32 "
                 "{%0,%1,%2,%3}, {%4,%5,%6,%7}, {%8,%9}, {%0,%1,%2,%3};"
                 : "+f"(c[0]), "+f"(c[1]), "+f"(c[2]), "+f"(c[3])
                 : "r"(a0), "r"(a1), "r"(a2), "r"(a3), "r"(b0), "r"(b1));
}
__device__ __forceinline__ u32 smem_u32p(const void* p) {
    u32 a;
    asm("{ .reg .u64 t; cvta.to.shared.u64 t, %1; cvt.u32.u64 %0, t; }" : "=r"(a) : "l"(p));
    return a;
}
__device__ __forceinline__ void cpasync16(u32 smaddr, const void* gptr) {
    asm volatile("cp.async.cg.shared.global [%0], [%1], 16;" :: "r"(smaddr), "l"(gptr));
}
__device__ __forceinline__ void cpasync4(u32 smaddr, const void* gptr) {
    asm volatile("cp.async.ca.shared.global [%0], [%1], 4;" :: "r"(smaddr), "l"(gptr));
}
#define CP_COMMIT() asm volatile("cp.async.commit_group;" ::: "memory")
#define CP_WAIT1()  asm volatile("cp.async.wait_group 1;" ::: "memory")
#define CP_WAIT0()  asm volatile("cp.async.wait_group 0;" ::: "memory")

// ==================== small kernels ====================
__global__ void transpose_x_kernel(const float* __restrict__ x, float* __restrict__ xt) {
    int i = blockIdx.x * blockDim.x + threadIdx.x;
    if (i >= BB * NPTS) return;
    int b = i / NPTS, n = i % NPTS;
#pragma unroll
    for (int c = 0; c < 3; c++)
        xt[i * 3 + c] = x[(b * 3 + c) * NPTS + n];
}

__global__ void sqnorm_kernel(const float* __restrict__ xt, int rs, int off, int C,
                              float* __restrict__ sq) {
    int i = blockIdx.x * blockDim.x + threadIdx.x;
    if (i >= BB * NPTS) return;
    const float* p = xt + (ll)i * rs + off;
    float s = 0.f;
    for (int c = 0; c < C; c++) { float v = p[c]; s += v * v; }
    sq[i] = s;
}

__global__ void split_kernel(const float* __restrict__ in, u32* __restrict__ out, ll n) {
    ll i = (ll)blockIdx.x * blockDim.x + threadIdx.x;
    if (i < n) out[i] = pack_hl(in[i]);
}

// ==================== SIMT SGEMM for kNN distances ====================
__global__ __launch_bounds__(256, 2)
void distgemm_kernel(const float* __restrict__ A, float* __restrict__ C, int K, int lda,
                     ll sA, const float* __restrict__ sq) {
    __shared__ float As[16][132];
    __shared__ float Bs[16][132];
    const int tid = threadIdx.x;
    const int tx = tid & 15, ty = tid >> 4;
    const int i0 = blockIdx.y * 128, j0 = blockIdx.x * 128;
    const int bz = blockIdx.z;
    const float* Ab = A + (ll)bz * sA;
    float acc[8][8];
#pragma unroll
    for (int i = 0; i < 8; i++)
#pragma unroll
        for (int j = 0; j < 8; j++) acc[i][j] = 0.f;
    for (int k0 = 0; k0 < K; k0 += 16) {
        for (int t = tid; t < 2048; t += 256) {
            int kq = t & 15, i = t >> 4;
            int gk = k0 + kq;
            As[kq][i] = (gk < K) ? Ab[(ll)(i0 + i) * lda + gk] : 0.f;
        }
        for (int t = tid; t < 2048; t += 256) {
            int kq = t & 15, j = t >> 4;
            int gk = k0 + kq;
            Bs[kq][j] = (gk < K) ? Ab[(ll)(j0 + j) * lda + gk] : 0.f;
        }
        __syncthreads();
#pragma unroll
        for (int kq = 0; kq < 16; kq++) {
            float4 a0 = *(const float4*)&As[kq][ty * 8];
            float4 a1 = *(const float4*)&As[kq][ty * 8 + 4];
            float4 b0 = *(const float4*)&Bs[kq][tx * 8];
            float4 b1 = *(const float4*)&Bs[kq][tx * 8 + 4];
            float a[8] = {a0.x, a0.y, a0.z, a0.w, a1.x, a1.y, a1.z, a1.w};
            float b[8] = {b0.x, b0.y, b0.z, b0.w, b1.x, b1.y, b1.z, b1.w};
#pragma unroll
            for (int i = 0; i < 8; i++)
#pragma unroll
                for (int j = 0; j < 8; j++) acc[i][j] += a[i] * b[j];
        }
        __syncthreads();
    }
    float* Cb = C + (ll)bz * NPTS * NPTS;
    const float* sqb = sq + (ll)bz * NPTS;
#pragma unroll
    for (int ii = 0; ii < 8; ii++) {
        int gi = i0 + ty * 8 + ii;
        float sqi = sqb[gi];
#pragma unroll
        for (int jj = 0; jj < 8; jj++) {
            int gj = j0 + tx * 8 + jj;
            Cb[(ll)gi * NPTS + gj] = sqi + sqb[gj] - 2.f * acc[ii][jj];
        }
    }
}

// ==================== top-k via radix select (set semantics; (value,idx) tie rule) ====================
__global__ __launch_bounds__(256)
void topk_kernel(const float* __restrict__ dist, int* __restrict__ out) {
    __shared__ u32 hist[256];
    __shared__ u32 cum[256];
    __shared__ u32 candk[2048];
    __shared__ u32 candi[2048];
    __shared__ u32 ctr[2];
    __shared__ u32 selbin, selbefore;
    const int tid = threadIdx.x;
    const float* rp = dist + (ll)blockIdx.x * NPTS;
    hist[tid] = 0;
    if (tid < 2) ctr[tid] = 0;
    __syncthreads();
    u32 key[8];
#pragma unroll
    for (int j = 0; j < 8; j++) {
        u32 u = __float_as_uint(rp[tid + j * 256]);
        key[j] = (u & 0x80000000u) ? ~u : (u | 0x80000000u);
        atomicAdd(&hist[key[j] >> 24], 1u);
    }
    __syncthreads();
    cum[tid] = hist[tid];
    __syncthreads();
#pragma unroll
    for (int off = 1; off < 256; off <<= 1) {
        u32 v = (tid >= off) ? cum[tid - off] : 0u;
        __syncthreads();
        cum[tid] += v;
        __syncthreads();
    }
    {
        u32 inc = cum[tid], exc = inc - hist[tid];
        if (exc < KNN && inc >= KNN) { selbin = (u32)tid; selbefore = exc; }
    }
    __syncthreads();
    const u32 sb = selbin, before = selbefore;
    int* op = out + (ll)blockIdx.x * KNN;
#pragma unroll
    for (int j = 0; j < 8; j++) {
        u32 b = key[j] >> 24;
        int idx = tid + j * 256;
        if (b < sb) {
            u32 p = atomicAdd(&ctr[0], 1u);
            op[p] = idx;
        } else if (b == sb) {
            u32 p = atomicAdd(&ctr[1], 1u);
            candk[p] = key[j];
            candi[p] = (u32)idx;
        }
    }
    __syncthreads();
    const int need = KNN - (int)before;
    const int cnt = (int)ctr[1];
    if (tid < 32) {
        for (int s = 0; s < need; s++) {
            u32 bk = 0xffffffffu, bi = 0xffffffffu;
            for (int t = tid; t < cnt; t += 32) {
                u32 k2 = candk[t], i2 = candi[t];
                if (k2 < bk || (k2 == bk && i2 < bi)) { bk = k2; bi = i2; }
            }
#pragma unroll
            for (int off = 16; off > 0; off >>= 1) {
                u32 ok = __shfl_xor_sync(0xffffffffu, bk, off);
                u32 oi = __shfl_xor_sync(0xffffffffu, bi, off);
                if (ok < bk || (ok == bk && oi < bi)) { bk = ok; bi = oi; }
            }
            for (int t = tid; t < cnt; t += 32) {
                if (candk[t] == bk && candi[t] == bi) { candk[t] = 0xffffffffu; candi[t] = 0xffffffffu; }
            }
            if (tid == 0) op[before + s] = (int)bi;
            __syncwarp();
        }
    }
}

// ==================== fused EdgeConv (float4 conv loops) ====================
template <int CIN>
__global__ __launch_bounds__(256)
void edgeconv_kernel(const float* __restrict__ xin, int rsin, int offin,
                     const int* __restrict__ idx,
                     const float* __restrict__ w1, const float* __restrict__ bn1,
                     const float* __restrict__ w2, const float* __restrict__ bn2,
                     float* __restrict__ xout, int rsout, int offout) {
    constexpr int C2 = 2 * CIN;
    extern __shared__ float sm[];
    float* w1s = sm;                         // [64][C2] verbatim
    float* w2s = w1s + C2 * 64;              // [64][64] verbatim
    float* es  = w2s + 4096;                 // [32][C2]
    float* h1s = es + 32 * C2;               // [32][68]  (k-major)
    float* red = h1s + 32 * 68;              // 256
    float* ctr = red + 256;                  // CIN (padded)
    int*   iks = (int*)(ctr + ((CIN + 3) & ~3));

    const int tid = threadIdx.x;
    const int o = tid & 63, kg = tid >> 6;
    for (int t = tid; t < 64 * C2; t += 256) w1s[t] = w1[t];
    for (int t = tid; t < 4096; t += 256)    w2s[t] = w2[t];
    const float s1 = bn1[o] * rsqrtf(bn1[192 + o] + 1e-5f);
    const float t1 = bn1[64 + o] - bn1[128 + o] * s1;
    const float s2 = bn2[o] * rsqrtf(bn2[192 + o] + 1e-5f);
    const float t2 = bn2[64 + o] - bn2[128 + o] * s2;
    __syncthreads();
    for (int p = blockIdx.x; p < BB * NPTS; p += gridDim.x) {
        const int b = p >> 11;
        if (tid < CIN) ctr[tid] = xin[(ll)p * rsin + offin + tid];
        if (tid < KNN) iks[tid] = idx[p * KNN + tid];
        __syncthreads();
        for (int t = tid; t < KNN * CIN; t += 256) {
            int kq = t / CIN, c = t - kq * CIN;
            int m = iks[kq];
            float v = xin[(ll)(b * NPTS + m) * rsin + offin + c];
            es[kq * C2 + c] = v - ctr[c];
            es[kq * C2 + CIN + c] = ctr[c];
        }
        __syncthreads();
        float acc[8];
#pragma unroll
        for (int j = 0; j < 8; j++) acc[j] = 0.f;
        if (C2 % 4 == 0) {
            const float4* w4 = (const float4*)&w1s[o * C2];
            for (int c4 = 0; c4 < C2 / 4; c4++) {
                float4 wv = w4[c4];
#pragma unroll
                for (int j = 0; j < 8; j++) {
                    float4 ev = *(const float4*)&es[(kg * 8 + j) * C2 + c4 * 4];
                    acc[j] += wv.x * ev.x + wv.y * ev.y + wv.z * ev.z + wv.w * ev.w;
                }
            }
        } else {
            for (int c = 0; c < C2; c++) {
                float w = w1s[o * C2 + c];
#pragma unroll
                for (int j = 0; j < 8; j++) acc[j] += w * es[(kg * 8 + j) * C2 + c];
            }
        }
#pragma unroll
        for (int j = 0; j < 8; j++) {
            float v = acc[j] * s1 + t1;
            v = v >= 0.f ? v : 0.2f * v;
            h1s[(kg * 8 + j) * 68 + o] = v;
            acc[j] = 0.f;
        }
        __syncthreads();
        {
            const float4* w4 = (const float4*)&w2s[o * 64];
#pragma unroll
            for (int c4 = 0; c4 < 16; c4++) {
                float4 wv = w4[c4];
#pragma unroll
                for (int j = 0; j < 8; j++) {
                    float4 hv = *(const float4*)&h1s[(kg * 8 + j) * 68 + c4 * 4];
                    acc[j] += wv.x * hv.x + wv.y * hv.y + wv.z * hv.z + wv.w * hv.w;
                }
            }
        }
        float mx = -3.4e38f;
#pragma unroll
        for (int j = 0; j < 8; j++) {
            float v = acc[j] * s2 + t2;
            v = v >= 0.f ? v : 0.2f * v;
            mx = fmaxf(mx, v);
        }
        red[kg * 64 + o] = mx;
        __syncthreads();
        if (kg == 0) {
            float m = fmaxf(fmaxf(red[o], red[64 + o]), fmaxf(red[128 + o], red[192 + o]));
            xout[(ll)p * rsout + offout + o] = m;
        }
        __syncthreads();
    }
}

// ==================== mma.sync split-bf16 GEMM (cp.async 2-stage pipeline) ====================
// C[i,j] = sum_k Af(i,k)*Bf(j,k); A,B packed hi/lo u32; fp32 accum.
// A used verbatim (u32 = (Ah,Al) bf16); B stored packed, expanded at frag load.
// EPI: 0 pack store, 1 lrelu+pack, 2 BN+lrelu fp32 store
#define STG_W (128 * 36)           // words per tile
#define STG_B (2 * STG_W * 4)      // bytes per stage (A+B)

__device__ __forceinline__ void stage_load(const u32* __restrict__ Ab, const u32* __restrict__ Bb,
                                           int i0, int j0, int k0,
                                           int sAm, int sAk, int sBn, int sBk,
                                           u32 aAddr, u32 bAddr, int tid) {
    if (sAk == 1) {
        for (int t = tid; t < 1024; t += 256) {
            int m = t >> 3, q = (t & 7) << 2;
            cpasync16(aAddr + (u32)(m * 36 + q) * 4, Ab + (ll)(i0 + m) * sAm + k0 + q);
        }
    } else {
        for (int t = tid; t < 4096; t += 256) {
            int m = t & 127, kk = t >> 7;
            cpasync4(aAddr + (u32)(m * 36 + kk) * 4, Ab + (ll)(i0 + m) + (ll)(k0 + kk) * sAk);
        }
    }
    if (sBk == 1) {
        for (int t = tid; t < 1024; t += 256) {
            int n = t >> 3, q = (t & 7) << 2;
            cpasync16(bAddr + (u32)(n * 36 + q) * 4, Bb + (ll)(j0 + n) * sBn + k0 + q);
        }
    } else {
        for (int t = tid; t < 4096; t += 256) {
            int n = t & 127, kk = t >> 7;
            cpasync4(bAddr + (u32)(n * 36 + kk) * 4, Bb + (ll)(j0 + n) + (ll)(k0 + kk) * sBk);
        }
    }
}

template <int EPI>
__global__ __launch_bounds__(256)
void mmamm_kernel(const u32* __restrict__ A, const u32* __restrict__ B,
                  u32* __restrict__ Co, float* __restrict__ Cf,
                  int K, int sAm, int sAk, int sBn, int sBk, int ldc,
                  ll strideA, ll strideB, ll strideC, const float* __restrict__ bn) {
    extern __shared__ u32 smu[];
    const int tid = threadIdx.x, lane = tid & 31, w = tid >> 5;
    const int mw = (w & 1) * 64, nw = (w >> 1) * 32;
    const int i0 = blockIdx.y * 128, j0 = blockIdx.x * 128, bz = blockIdx.z;
    const u32* Ab = A + (ll)bz * strideA;
    const u32* Bb = B + (ll)bz * strideB;
    const int lq = lane >> 2, lr = lane & 3;
    const u32 sbase = smem_u32p(smu);

    float acc[4][4][4];
#pragma unroll
    for (int a = 0; a < 4; a++)
#pragma unroll
        for (int b = 0; b < 4; b++)
#pragma unroll
            for (int c = 0; c < 4; c++) acc[a][b][c] = 0.f;

    const int nch = K >> 5;
    stage_load(Ab, Bb, i0, j0, 0, sAm, sAk, sBn, sBk, sbase, sbase + STG_W * 4, tid);
    CP_COMMIT();
    for (int ch = 0; ch < nch; ch++) {
        const int st = ch & 1;
        if (ch + 1 < nch) {
            const int st2 = (ch + 1) & 1;
            stage_load(Ab, Bb, i0, j0, (ch + 1) << 5, sAm, sAk, sBn, sBk,
                       sbase + st2 * STG_B, sbase + st2 * STG_B + STG_W * 4, tid);
            CP_COMMIT();
            CP_WAIT1();
        } else {
            CP_WAIT0();
        }
        __syncthreads();
        u32 (*As)[36] = (u32(*)[36])(smu + st * 2 * STG_W);
        u32 (*Bs)[36] = (u32(*)[36])(smu + st * 2 * STG_W + STG_W);
#pragma unroll
        for (int ks = 0; ks < 4; ks++) {
            const int kw = ks * 8;
            u32 bh[4][2], bl[4][2];
#pragma unroll
            for (int nt = 0; nt < 4; nt++) {
                int n = nw + nt * 8 + lq;
                u32 b0 = Bs[n][kw + lr], b1 = Bs[n][kw + 4 + lr];
                bh[nt][0] = (b0 & 0xffffu) * 0x10001u;
                bl[nt][0] = (b0 >> 16) * 0x10001u;
                bh[nt][1] = (b1 & 0xffffu) * 0x10001u;
                bl[nt][1] = (b1 >> 16) * 0x10001u;
            }
#pragma unroll
            for (int mt = 0; mt < 4; mt++) {
                int m = mw + mt * 16 + lq;
                u32 a0 = As[m][kw + lr], a1 = As[m + 8][kw + lr];
                u32 a2 = As[m][kw + 4 + lr], a3 = As[m + 8][kw + 4 + lr];
#pragma unroll
                for (int nt = 0; nt < 4; nt++) {
                    mma16816(acc[mt][nt], a0, a1, a2, a3, bh[nt][0], bh[nt][1]);
                    mma16816(acc[mt][nt], a0, a1, a2, a3, bl[nt][0], bl[nt][1]);
                }
            }
        }
        __syncthreads();
    }

    // ---- epilogue: direct fragment stores ----
#pragma unroll
    for (int mt = 0; mt < 4; mt++) {
#pragma unroll
        for (int nt = 0; nt < 4; nt++) {
            int gm0 = i0 + mw + mt * 16 + lq;
            int gn  = j0 + nw + nt * 8 + lr * 2;
#pragma unroll
            for (int half = 0; half < 2; half++) {
                int gm = gm0 + half * 8;
                float v0 = acc[mt][nt][half * 2], v1 = acc[mt][nt][half * 2 + 1];
                if (EPI == 0) {
                    uint2 pv = make_uint2(pack_hl(v0), pack_hl(v1));
                    *(uint2*)&Co[(ll)bz * strideC + (ll)gm * ldc + gn] = pv;
                } else if (EPI == 1) {
                    v0 = v0 >= 0.f ? v0 : 0.2f * v0;
                    v1 = v1 >= 0.f ? v1 : 0.2f * v1;
                    uint2 pv = make_uint2(pack_hl(v0), pack_hl(v1));
                    *(uint2*)&Co[(ll)bz * strideC + (ll)gm * ldc + gn] = pv;
                } else {
                    float g = bn[gm], be = bn[1024 + gm], mm = bn[2048 + gm], va = bn[3072 + gm];
                    float s = g * rsqrtf(va + 1e-5f);
                    float t = be - mm * s;
                    v0 = v0 * s + t; v0 = v0 >= 0.f ? v0 : 0.2f * v0;
                    v1 = v1 * s + t; v1 = v1 >= 0.f ? v1 : 0.2f * v1;
                    *(float2*)&Cf[(ll)bz * strideC + (ll)gm * ldc + gn] = make_float2(v0, v1);
                }
            }
        }
    }
}

// ==================== softmax over packed rows (scale 1/32) ====================
__global__ __launch_bounds__(256)
void softmax_hl_kernel(u32* __restrict__ att) {
    __shared__ float sd[NPTS];
    __shared__ float red[256];
    const int tid = threadIdx.x;
    u32* p = att + (ll)blockIdx.x * NPTS;
    float mx = -3.4e38f;
    for (int t = tid; t < NPTS; t += 256) {
        float v = unpack_hl(p[t]) * 0.03125f;
        sd[t] = v;
        mx = fmaxf(mx, v);
    }
    red[tid] = mx;
    __syncthreads();
    for (int h = 128; h > 0; h >>= 1) {
        if (tid < h) red[tid] = fmaxf(red[tid], red[tid + h]);
        __syncthreads();
    }
    mx = red[0];
    __syncthreads();
    float sum = 0.f;
    for (int t = tid; t < NPTS; t += 256) {
        float e = __expf(sd[t] - mx);
        sd[t] = e;
        sum += e;
    }
    red[tid] = sum;
    __syncthreads();
    for (int h = 128; h > 0; h >>= 1) {
        if (tid < h) red[tid] += red[tid + h];
        __syncthreads();
    }
    float inv = 1.f / red[0];
    __syncthreads();
    for (int t = tid; t < NPTS; t += 256) p[t] = pack_hl(sd[t] * inv);
}

// ==================== residual add + BN (packed) ====================
__global__ void addbn_hl_kernel(const u32* __restrict__ a, const u32* __restrict__ r,
                                const float* __restrict__ bn, u32* __restrict__ out, ll total) {
    ll i = (ll)blockIdx.x * blockDim.x + threadIdx.x;
    if (i >= total) return;
    int c = (int)((i >> 11) & 1023);
    float g = bn[c], be = bn[1024 + c], m = bn[2048 + c], va = bn[3072 + c];
    float s = g * rsqrtf(va + 1e-5f);
    float v = (unpack_hl(a[i]) + unpack_hl(r[i])) * s + (be - m * s);
    out[i] = pack_hl(v);
}

// ==================== launcher ====================
extern "C" void kernel_launch(void* const* d_in, const int* in_sizes, int n_in,
                              void* d_out, int out_size) {
    const float* x       = (const float*)d_in[0];
    const float* ec1_w1  = (const float*)d_in[1];
    const float* ec1_bn1 = (const float*)d_in[2];
    const float* ec1_w2  = (const float*)d_in[3];
    const float* ec1_bn2 = (const float*)d_in[4];
    const float* ec2_w1  = (const float*)d_in[5];
    const float* ec2_bn1 = (const float*)d_in[6];
    const float* ec2_w2  = (const float*)d_in[7];
    const float* ec2_bn2 = (const float*)d_in[8];
    const float* ec3_w1  = (const float*)d_in[9];
    const float* ec3_bn1 = (const float*)d_in[10];
    const float* ec3_w2  = (const float*)d_in[11];
    const float* ec3_bn2 = (const float*)d_in[12];
    const float* emb_w   = (const float*)d_in[13];
    const float* q_w     = (const float*)d_in[14];
    const float* k_w     = (const float*)d_in[15];
    const float* v_w     = (const float*)d_in[16];
    const float* att_bn1 = (const float*)d_in[17];
    const float* ff_w1   = (const float*)d_in[18];
    const float* ff_w2   = (const float*)d_in[19];
    const float* att_bn2 = (const float*)d_in[20];
    const float* cb_w    = (const float*)d_in[21];
    const float* cb_bn   = (const float*)d_in[22];
    float* out = (float*)d_out;

    float *xT3, *sqn, *dist, *xcT;
    u32 *xchl, *h, *q, *kk, *v, *xr, *ffo, *embw, *qw, *kw, *vw, *f1w, *f2w, *cw;
    int* idxp;
    cudaGetSymbolAddress((void**)&xT3, g_xT3);
    cudaGetSymbolAddress((void**)&sqn, g_sqn);
    cudaGetSymbolAddress((void**)&dist, g_dist);
    cudaGetSymbolAddress((void**)&idxp, g_idx);
    cudaGetSymbolAddress((void**)&xcT, g_xcT);
    cudaGetSymbolAddress((void**)&xchl, g_xchl);
    cudaGetSymbolAddress((void**)&h, g_h);
    cudaGetSymbolAddress((void**)&q, g_q);
    cudaGetSymbolAddress((void**)&kk, g_k);
    cudaGetSymbolAddress((void**)&v, g_v);
    cudaGetSymbolAddress((void**)&xr, g_xr);
    cudaGetSymbolAddress((void**)&ffo, g_ffo);
    cudaGetSymbolAddress((void**)&embw, g_embw);
    cudaGetSymbolAddress((void**)&qw, g_qw);
    cudaGetSymbolAddress((void**)&kw, g_kw);
    cudaGetSymbolAddress((void**)&vw, g_vw);
    cudaGetSymbolAddress((void**)&f1w, g_f1w);
    cudaGetSymbolAddress((void**)&f2w, g_f2w);
    cudaGetSymbolAddress((void**)&cw, g_cw);

    const size_t sm3  = (size_t)(6 * 64 + 4096 + 32 * 6 + 32 * 68 + 256 + 4 + 32) * 4;
    const size_t sm64 = (size_t)(128 * 64 + 4096 + 32 * 128 + 32 * 68 + 256 + 64 + 32) * 4;
    cudaFuncSetAttribute((const void*)edgeconv_kernel<64>,
                         cudaFuncAttributeMaxDynamicSharedMemorySize, (int)sm64);
    const int SMTC = 2 * STG_B;  // 73728 B
    cudaFuncSetAttribute((const void*)mmamm_kernel<0>, cudaFuncAttributeMaxDynamicSharedMemorySize, SMTC);
    cudaFuncSetAttribute((const void*)mmamm_kernel<1>, cudaFuncAttributeMaxDynamicSharedMemorySize, SMTC);
    cudaFuncSetAttribute((const void*)mmamm_kernel<2>, cudaFuncAttributeMaxDynamicSharedMemorySize, SMTC);

    const int npts = BB * NPTS;
    const ll CH = (ll)1024 * NPTS;
    const ll AT = (ll)NPTS * NPTS;
    const ll total = (ll)BB * 1024 * NPTS;

    transpose_x_kernel<<<(npts + 255) / 256, 256>>>(x, xT3);

    dim3 gd(NPTS / 128, NPTS / 128, BB);
    // EdgeConv 1 (C=3)
    sqnorm_kernel<<<(npts + 255) / 256, 256>>>(xT3, 3, 0, 3, sqn);
    distgemm_kernel<<<gd, 256>>>(xT3, dist, 3, 3, (ll)NPTS * 3, sqn);
    topk_kernel<<<npts, 256>>>(dist, idxp);
    edgeconv_kernel<3><<<1024, 256, sm3>>>(xT3, 3, 0, idxp, ec1_w1, ec1_bn1, ec1_w2, ec1_bn2, xcT, 192, 0);
    // EdgeConv 2
    sqnorm_kernel<<<(npts + 255) / 256, 256>>>(xcT, 192, 0, 64, sqn);
    distgemm_kernel<<<gd, 256>>>(xcT, dist, 64, 192, (ll)NPTS * 192, sqn);
    topk_kernel<<<npts, 256>>>(dist, idxp);
    edgeconv_kernel<64><<<1024, 256, sm64>>>(xcT, 192, 0, idxp, ec2_w1, ec2_bn1, ec2_w2, ec2_bn2, xcT, 192, 64);
    // EdgeConv 3
    sqnorm_kernel<<<(npts + 255) / 256, 256>>>(xcT, 192, 64, 64, sqn);
    distgemm_kernel<<<gd, 256>>>(xcT + 64, dist, 64, 192, (ll)NPTS * 192, sqn);
    topk_kernel<<<npts, 256>>>(dist, idxp);
    edgeconv_kernel<64><<<1024, 256, sm64>>>(xcT, 192, 64, idxp, ec3_w1, ec3_bn1, ec3_w2, ec3_bn2, xcT, 192, 128);

    // pack activations + weights to hi/lo
    split_kernel<<<(int)(((ll)npts * 192 + 255) / 256), 256>>>(xcT, xchl, (ll)npts * 192);
    split_kernel<<<(1024 * 192 + 255) / 256, 256>>>(emb_w, embw, 1024 * 192);
    split_kernel<<<(1024 * 1024 + 255) / 256, 256>>>(q_w, qw, 1024 * 1024);
    split_kernel<<<(1024 * 1024 + 255) / 256, 256>>>(k_w, kw, 1024 * 1024);
    split_kernel<<<(1024 * 1024 + 255) / 256, 256>>>(v_w, vw, 1024 * 1024);
    split_kernel<<<(512 * 1024 + 255) / 256, 256>>>(ff_w1, f1w, 512 * 1024);
    split_kernel<<<(512 * 1024 + 255) / 256, 256>>>(ff_w2, f2w, 512 * 1024);
    split_kernel<<<(1024 * 1024 + 255) / 256, 256>>>(cb_w, cw, 1024 * 1024);

    u32* distu = (u32*)dist;
    dim3 ge(NPTS / 128, 1024 / 128, BB);
    dim3 ga(NPTS / 128, NPTS / 128, BB);
    dim3 gf(NPTS / 128, 512 / 128, BB);
    // h = emb_w @ xc
    mmamm_kernel<0><<<ge, 256, SMTC>>>(embw, xchl, h, nullptr, 192, 192, 1, 192, 1, NPTS,
                                       0, (ll)NPTS * 192, CH, nullptr);
    // q, k, v
    mmamm_kernel<0><<<ge, 256, SMTC>>>(qw, h, q, nullptr, 1024, 1024, 1, 1, NPTS, NPTS, 0, CH, CH, nullptr);
    mmamm_kernel<0><<<ge, 256, SMTC>>>(kw, h, kk, nullptr, 1024, 1024, 1, 1, NPTS, NPTS, 0, CH, CH, nullptr);
    mmamm_kernel<0><<<ge, 256, SMTC>>>(vw, h, v, nullptr, 1024, 1024, 1, 1, NPTS, NPTS, 0, CH, CH, nullptr);
    // logits[n,m] = sum_c q[c,n] k[c,m]
    mmamm_kernel<0><<<ga, 256, SMTC>>>(q, kk, distu, nullptr, 1024, 1, NPTS, 1, NPTS, NPTS, CH, CH, AT, nullptr);
    softmax_hl_kernel<<<npts, 256>>>(distu);
    // xr[c,n] = sum_m v[c,m] att[n,m]
    mmamm_kernel<0><<<ge, 256, SMTC>>>(v, distu, xr, nullptr, NPTS, NPTS, 1, NPTS, 1, NPTS, CH, AT, CH, nullptr);
    addbn_hl_kernel<<<(int)((total + 255) / 256), 256>>>(h, xr, att_bn1, q /*h2*/, total);
    // ff
    mmamm_kernel<1><<<gf, 256, SMTC>>>(f1w, q, ffo, nullptr, 1024, 1024, 1, 1, NPTS, NPTS, 0, CH, (ll)512 * NPTS, nullptr);
    mmamm_kernel<0><<<ge, 256, SMTC>>>(f2w, ffo, kk /*ff*/, nullptr, 512, 512, 1, 1, NPTS, NPTS, 0, (ll)512 * NPTS, CH, nullptr);
    addbn_hl_kernel<<<(int)((total + 255) / 256), 256>>>(q, kk, att_bn2, v /*h3*/, total);
    // classifier: BN + lrelu, fp32 out
    mmamm_kernel<2><<<ge, 256, SMTC>>>(cw, v, nullptr, out, 1024, 1024, 1, 1, NPTS, NPTS, 0, CH, CH, cb_bn);
}

// round 9
// speedup vs baseline: 3.2490x; 1.3240x over previous
#include <cuda_runtime.h>
#include <cuda_bf16.h>
#include <cstdint>

#define BB 8
#define NPTS 2048
#define KNN 32
typedef long long ll;
typedef uint32_t u32;
typedef unsigned short u16;

// ==================== scratch (device globals) ====================
static __device__ float g_xT3[BB * NPTS * 3];
static __device__ float g_sqn[BB * NPTS];
static __device__ float g_dist[(ll)BB * NPTS * NPTS];   // fp32 dist; reused (as u32) for logits/att
static __device__ int   g_idx[BB * NPTS * KNN];
static __device__ float g_xcT[BB * NPTS * 192];
static __device__ u32   g_xchl[BB * NPTS * 192];
static __device__ u32   g_h [(ll)BB * NPTS * 1024];
static __device__ u32   g_q [(ll)BB * NPTS * 1024];     // later h2
static __device__ u32   g_k [(ll)BB * NPTS * 1024];     // later ff out
static __device__ u32   g_v [(ll)BB * NPTS * 1024];     // later h3
static __device__ u32   g_xr[(ll)BB * NPTS * 1024];
static __device__ u32   g_ffo[(ll)BB * NPTS * 512];
static __device__ u32   g_embw[1024 * 192];
static __device__ u32   g_qw[1024 * 1024];
static __device__ u32   g_kw[1024 * 1024];
static __device__ u32   g_vw[1024 * 1024];
static __device__ u32   g_f1w[512 * 1024];
static __device__ u32   g_f2w[1024 * 512];
static __device__ u32   g_cw[1024 * 1024];

// ==================== helpers ====================
__device__ __forceinline__ u32 pack_hl(float v) {
    __nv_bfloat16 h = __float2bfloat16(v);
    float r = v - __bfloat162float(h);
    __nv_bfloat16 l = __float2bfloat16(r);
    return (u32)__bfloat16_as_ushort(h) | ((u32)__bfloat16_as_ushort(l) << 16);
}
__device__ __forceinline__ float unpack_hl(u32 u) {
    return __bfloat162float(__ushort_as_bfloat16((u16)(u & 0xffffu)))
         + __bfloat162float(__ushort_as_bfloat16((u16)(u >> 16)));
}
__device__ __forceinline__ void mma16816(float* c, u32 a0, u32 a1, u32 a2, u32 a3, u32 b0, u32 b1) {
    asm volatile("mma.sync.aligned.m16n8k16.row.col.f32.bf16.bf16.f32 "
                 "{%0,%1,%2,%3}, {%4,%5,%6,%7}, {%8,%9}, {%0,%1,%2,%3};"
                 : "+f"(c[0]), "+f"(c[1]), "+f"(c[2]), "+f"(c[3])
                 : "r"(a0), "r"(a1), "r"(a2), "r"(a3), "r"(b0), "r"(b1));
}
__device__ __forceinline__ u32 smem_u32p(const void* p) {
    u32 a;
    asm("{ .reg .u64 t; cvta.to.shared.u64 t, %1; cvt.u32.u64 %0, t; }" : "=r"(a) : "l"(p));
    return a;
}
__device__ __forceinline__ void cpasync16(u32 smaddr, const void* gptr) {
    asm volatile("cp.async.cg.shared.global [%0], [%1], 16;" :: "r"(smaddr), "l"(gptr));
}
__device__ __forceinline__ void cpasync4(u32 smaddr, const void* gptr) {
    asm volatile("cp.async.ca.shared.global [%0], [%1], 4;" :: "r"(smaddr), "l"(gptr));
}
#define CP_COMMIT() asm volatile("cp.async.commit_group;" ::: "memory")
#define CP_WAIT1()  asm volatile("cp.async.wait_group 1;" ::: "memory")
#define CP_WAIT0()  asm volatile("cp.async.wait_group 0;" ::: "memory")

// ==================== small kernels ====================
__global__ void transpose_x_kernel(const float* __restrict__ x, float* __restrict__ xt) {
    int i = blockIdx.x * blockDim.x + threadIdx.x;
    if (i >= BB * NPTS) return;
    int b = i / NPTS, n = i % NPTS;
#pragma unroll
    for (int c = 0; c < 3; c++)
        xt[i * 3 + c] = x[(b * 3 + c) * NPTS + n];
}

__global__ void sqnorm_kernel(const float* __restrict__ xt, int rs, int off, int C,
                              float* __restrict__ sq) {
    int i = blockIdx.x * blockDim.x + threadIdx.x;
    if (i >= BB * NPTS) return;
    const float* p = xt + (ll)i * rs + off;
    float s = 0.f;
    for (int c = 0; c < C; c++) { float v = p[c]; s += v * v; }
    sq[i] = s;
}

__global__ void split_kernel(const float* __restrict__ in, u32* __restrict__ out, ll n) {
    ll i = (ll)blockIdx.x * blockDim.x + threadIdx.x;
    if (i < n) out[i] = pack_hl(in[i]);
}

// ==================== SIMT SGEMM for kNN distances ====================
__global__ __launch_bounds__(256, 2)
void distgemm_kernel(const float* __restrict__ A, float* __restrict__ C, int K, int lda,
                     ll sA, const float* __restrict__ sq) {
    __shared__ float As[16][132];
    __shared__ float Bs[16][132];
    const int tid = threadIdx.x;
    const int tx = tid & 15, ty = tid >> 4;
    const int i0 = blockIdx.y * 128, j0 = blockIdx.x * 128;
    const int bz = blockIdx.z;
    const float* Ab = A + (ll)bz * sA;
    float acc[8][8];
#pragma unroll
    for (int i = 0; i < 8; i++)
#pragma unroll
        for (int j = 0; j < 8; j++) acc[i][j] = 0.f;
    for (int k0 = 0; k0 < K; k0 += 16) {
        for (int t = tid; t < 2048; t += 256) {
            int kq = t & 15, i = t >> 4;
            int gk = k0 + kq;
            As[kq][i] = (gk < K) ? Ab[(ll)(i0 + i) * lda + gk] : 0.f;
        }
        for (int t = tid; t < 2048; t += 256) {
            int kq = t & 15, j = t >> 4;
            int gk = k0 + kq;
            Bs[kq][j] = (gk < K) ? Ab[(ll)(j0 + j) * lda + gk] : 0.f;
        }
        __syncthreads();
#pragma unroll
        for (int kq = 0; kq < 16; kq++) {
            float4 a0 = *(const float4*)&As[kq][ty * 8];
            float4 a1 = *(const float4*)&As[kq][ty * 8 + 4];
            float4 b0 = *(const float4*)&Bs[kq][tx * 8];
            float4 b1 = *(const float4*)&Bs[kq][tx * 8 + 4];
            float a[8] = {a0.x, a0.y, a0.z, a0.w, a1.x, a1.y, a1.z, a1.w};
            float b[8] = {b0.x, b0.y, b0.z, b0.w, b1.x, b1.y, b1.z, b1.w};
#pragma unroll
            for (int i = 0; i < 8; i++)
#pragma unroll
                for (int j = 0; j < 8; j++) acc[i][j] += a[i] * b[j];
        }
        __syncthreads();
    }
    float* Cb = C + (ll)bz * NPTS * NPTS;
    const float* sqb = sq + (ll)bz * NPTS;
#pragma unroll
    for (int ii = 0; ii < 8; ii++) {
        int gi = i0 + ty * 8 + ii;
        float sqi = sqb[gi];
#pragma unroll
        for (int jj = 0; jj < 8; jj++) {
            int gj = j0 + tx * 8 + jj;
            Cb[(ll)gi * NPTS + gj] = sqi + sqb[gj] - 2.f * acc[ii][jj];
        }
    }
}

// ==================== top-k via 2-level radix select ====================
__global__ __launch_bounds__(256)
void topk_kernel(const float* __restrict__ dist, int* __restrict__ out) {
    __shared__ u32 hist[256];
    __shared__ u32 cum[256];
    __shared__ u32 candk[2048];
    __shared__ u32 candi[2048];
    __shared__ u32 candk2[2048];
    __shared__ u32 candi2[2048];
    __shared__ u32 ctr[2];
    __shared__ u32 selbin, selbefore;
    const int tid = threadIdx.x;
    const float* rp = dist + (ll)blockIdx.x * NPTS;
    hist[tid] = 0;
    if (tid < 2) ctr[tid] = 0;
    __syncthreads();
    u32 key[8];
#pragma unroll
    for (int j = 0; j < 8; j++) {
        u32 u = __float_as_uint(rp[tid + j * 256]);
        key[j] = (u & 0x80000000u) ? ~u : (u | 0x80000000u);
        atomicAdd(&hist[key[j] >> 24], 1u);
    }
    __syncthreads();
    cum[tid] = hist[tid];
    __syncthreads();
#pragma unroll
    for (int off = 1; off < 256; off <<= 1) {
        u32 v = (tid >= off) ? cum[tid - off] : 0u;
        __syncthreads();
        cum[tid] += v;
        __syncthreads();
    }
    {
        u32 inc = cum[tid], exc = inc - hist[tid];
        if (exc < KNN && inc >= KNN) { selbin = (u32)tid; selbefore = exc; }
    }
    __syncthreads();
    const u32 sb = selbin, before = selbefore;
    int* op = out + (ll)blockIdx.x * KNN;
#pragma unroll
    for (int j = 0; j < 8; j++) {
        u32 b = key[j] >> 24;
        int idx = tid + j * 256;
        if (b < sb) {
            u32 p = atomicAdd(&ctr[0], 1u);
            op[p] = idx;
        } else if (b == sb) {
            u32 p = atomicAdd(&ctr[1], 1u);
            candk[p] = key[j];
            candi[p] = (u32)idx;
        }
    }
    __syncthreads();
    // ---- level 2: radix on bits [16,24) of boundary-bin candidates ----
    const int cnt = (int)ctr[1];
    const u32 need1 = KNN - before;
    hist[tid] = 0;
    __syncthreads();
    for (int t = tid; t < cnt; t += 256)
        atomicAdd(&hist[(candk[t] >> 16) & 0xffu], 1u);
    __syncthreads();
    cum[tid] = hist[tid];
    __syncthreads();
#pragma unroll
    for (int off = 1; off < 256; off <<= 1) {
        u32 v = (tid >= off) ? cum[tid - off] : 0u;
        __syncthreads();
        cum[tid] += v;
        __syncthreads();
    }
    {
        u32 inc = cum[tid], exc = inc - hist[tid];
        if (exc < need1 && inc >= need1) { selbin = (u32)tid; selbefore = exc; }
    }
    if (tid == 0) { ctr[0] = 0; ctr[1] = 0; }
    __syncthreads();
    const u32 sb2 = selbin, before2 = selbefore;
    for (int t = tid; t < cnt; t += 256) {
        u32 k2 = candk[t];
        u32 b2 = (k2 >> 16) & 0xffu;
        if (b2 < sb2) {
            u32 p = atomicAdd(&ctr[0], 1u);
            op[before + p] = (int)candi[t];
        } else if (b2 == sb2) {
            u32 p = atomicAdd(&ctr[1], 1u);
            candk2[p] = k2;
            candi2[p] = candi[t];
        }
    }
    __syncthreads();
    const int need2 = (int)(KNN - before - before2);
    const int cnt2 = (int)ctr[1];
    if (tid < 32) {
        for (int s = 0; s < need2; s++) {
            u32 bk = 0xffffffffu, bi = 0xffffffffu;
            for (int t = tid; t < cnt2; t += 32) {
                u32 k2 = candk2[t], i2 = candi2[t];
                if (k2 < bk || (k2 == bk && i2 < bi)) { bk = k2; bi = i2; }
            }
#pragma unroll
            for (int off = 16; off > 0; off >>= 1) {
                u32 ok = __shfl_xor_sync(0xffffffffu, bk, off);
                u32 oi = __shfl_xor_sync(0xffffffffu, bi, off);
                if (ok < bk || (ok == bk && oi < bi)) { bk = ok; bi = oi; }
            }
            for (int t = tid; t < cnt2; t += 32) {
                if (candk2[t] == bk && candi2[t] == bi) { candk2[t] = 0xffffffffu; candi2[t] = 0xffffffffu; }
            }
            if (tid == 0) op[before + before2 + s] = (int)bi;
            __syncwarp();
        }
    }
}

// ==================== fused EdgeConv (conflict-free layouts + center-bias factorization) ====================
// smem layout (floats):
//   w1s [C2][64]   transposed weights, conflict-free scalar reads by o-lane
//   w2s [64][64]   transposed (c-major)
//   es  [CIN][36]  (nbr - ctr), c-major, k padded to 36
//   h1  [32][68]   k-major, c padded to 68
//   red [256]
//   ctr [CIN pad4]
//   iks [32]
template <int CIN>
__global__ __launch_bounds__(256)
void edgeconv_kernel(const float* __restrict__ xin, int rsin, int offin,
                     const int* __restrict__ idx,
                     const float* __restrict__ w1, const float* __restrict__ bn1,
                     const float* __restrict__ w2, const float* __restrict__ bn2,
                     float* __restrict__ xout, int rsout, int offout) {
    constexpr int C2 = 2 * CIN;
    constexpr int CPAD = (CIN + 3) & ~3;
    extern __shared__ float sm[];
    float* w1s = sm;                          // C2*64
    float* w2s = w1s + C2 * 64;               // 4096
    float* es  = w2s + 4096;                  // CIN*36
    float* h1  = es + CIN * 36;               // 32*68
    float* red = h1 + 32 * 68;                // 256
    float* ctr = red + 256;                   // CPAD
    int*   iks = (int*)(ctr + CPAD);          // 32

    const int tid = threadIdx.x;
    const int o = tid & 63, kg = tid >> 6;
    // transposed weight loads (gmem coalesced, one-time)
    for (int t = tid; t < 64 * C2; t += 256) {
        int oo = t / C2, c = t - oo * C2;
        w1s[c * 64 + oo] = w1[t];
    }
    for (int t = tid; t < 4096; t += 256) {
        int oo = t >> 6, c = t & 63;
        w2s[c * 64 + oo] = w2[t];
    }
    const float s1 = bn1[o] * rsqrtf(bn1[192 + o] + 1e-5f);
    const float t1 = bn1[64 + o] - bn1[128 + o] * s1;
    const float s2 = bn2[o] * rsqrtf(bn2[192 + o] + 1e-5f);
    const float t2 = bn2[64 + o] - bn2[128 + o] * s2;
    __syncthreads();

    for (int p = blockIdx.x; p < BB * NPTS; p += gridDim.x) {
        const int b = p >> 11;
        if (tid < CIN) ctr[tid] = xin[(ll)p * rsin + offin + tid];
        if (tid < KNN) iks[tid] = idx[p * KNN + tid];
        __syncthreads();
        // gather neighbors -> es[c][k] = nbr - ctr
        if (CIN % 4 == 0) {
            for (int t = tid; t < 32 * (CIN / 4); t += 256) {
                int kq = t & 31, cg = t >> 5;
                int m = iks[kq];
                float4 v = *(const float4*)&xin[(ll)(b * NPTS + m) * rsin + offin + cg * 4];
                float4 c4 = *(const float4*)&ctr[cg * 4];
                es[(cg * 4 + 0) * 36 + kq] = v.x - c4.x;
                es[(cg * 4 + 1) * 36 + kq] = v.y - c4.y;
                es[(cg * 4 + 2) * 36 + kq] = v.z - c4.z;
                es[(cg * 4 + 3) * 36 + kq] = v.w - c4.w;
            }
        } else {
            for (int t = tid; t < 32 * CIN; t += 256) {
                int kq = t & 31, c = t >> 5;
                int m = iks[kq];
                es[c * 36 + kq] = xin[(ll)(b * NPTS + m) * rsin + offin + c] - ctr[c];
            }
        }
        __syncthreads();
        // per-o bias: sum_c w1[o][CIN+c] * ctr[c]  (k-independent half of conv1)
        float bias = 0.f;
        for (int c = 0; c < CIN; c++)
            bias += w1s[(CIN + c) * 64 + o] * ctr[c];
        float acc[8];
#pragma unroll
        for (int j = 0; j < 8; j++) acc[j] = bias;
        // conv1 over difference half
        for (int c = 0; c < CIN; c++) {
            float w = w1s[c * 64 + o];
            float4 e0 = *(const float4*)&es[c * 36 + kg * 8];
            float4 e1 = *(const float4*)&es[c * 36 + kg * 8 + 4];
            acc[0] += w * e0.x; acc[1] += w * e0.y; acc[2] += w * e0.z; acc[3] += w * e0.w;
            acc[4] += w * e1.x; acc[5] += w * e1.y; acc[6] += w * e1.z; acc[7] += w * e1.w;
        }
#pragma unroll
        for (int j = 0; j < 8; j++) {
            float v = acc[j] * s1 + t1;
            v = v >= 0.f ? v : 0.2f * v;
            h1[(kg * 8 + j) * 68 + o] = v;   // conflict-free store (lanes consecutive o)
            acc[j] = 0.f;
        }
        __syncthreads();
        // conv2: float4 broadcast over c, scalar conflict-free weights
#pragma unroll 4
        for (int c4 = 0; c4 < 16; c4++) {
            float w0 = w2s[(c4 * 4 + 0) * 64 + o];
            float w1v = w2s[(c4 * 4 + 1) * 64 + o];
            float w2v = w2s[(c4 * 4 + 2) * 64 + o];
            float w3 = w2s[(c4 * 4 + 3) * 64 + o];
#pragma unroll
            for (int j = 0; j < 8; j++) {
                float4 hv = *(const float4*)&h1[(kg * 8 + j) * 68 + c4 * 4];
                acc[j] += w0 * hv.x + w1v * hv.y + w2v * hv.z + w3 * hv.w;
            }
        }
        float mx = -3.4e38f;
#pragma unroll
        for (int j = 0; j < 8; j++) {
            float v = acc[j] * s2 + t2;
            v = v >= 0.f ? v : 0.2f * v;
            mx = fmaxf(mx, v);
        }
        red[kg * 64 + o] = mx;
        __syncthreads();
        if (kg == 0) {
            float m = fmaxf(fmaxf(red[o], red[64 + o]), fmaxf(red[128 + o], red[192 + o]));
            xout[(ll)p * rsout + offout + o] = m;
        }
        __syncthreads();
    }
}

// ==================== mma.sync split-bf16 GEMM (cp.async 2-stage pipeline) ====================
#define STG_W (128 * 36)
#define STG_B (2 * STG_W * 4)

__device__ __forceinline__ void stage_load(const u32* __restrict__ Ab, const u32* __restrict__ Bb,
                                           int i0, int j0, int k0,
                                           int sAm, int sAk, int sBn, int sBk,
                                           u32 aAddr, u32 bAddr, int tid) {
    if (sAk == 1) {
        for (int t = tid; t < 1024; t += 256) {
            int m = t >> 3, q = (t & 7) << 2;
            cpasync16(aAddr + (u32)(m * 36 + q) * 4, Ab + (ll)(i0 + m) * sAm + k0 + q);
        }
    } else {
        for (int t = tid; t < 4096; t += 256) {
            int m = t & 127, kk = t >> 7;
            cpasync4(aAddr + (u32)(m * 36 + kk) * 4, Ab + (ll)(i0 + m) + (ll)(k0 + kk) * sAk);
        }
    }
    if (sBk == 1) {
        for (int t = tid; t < 1024; t += 256) {
            int n = t >> 3, q = (t & 7) << 2;
            cpasync16(bAddr + (u32)(n * 36 + q) * 4, Bb + (ll)(j0 + n) * sBn + k0 + q);
        }
    } else {
        for (int t = tid; t < 4096; t += 256) {
            int n = t & 127, kk = t >> 7;
            cpasync4(bAddr + (u32)(n * 36 + kk) * 4, Bb + (ll)(j0 + n) + (ll)(k0 + kk) * sBk);
        }
    }
}

template <int EPI>
__global__ __launch_bounds__(256)
void mmamm_kernel(const u32* __restrict__ A, const u32* __restrict__ B,
                  u32* __restrict__ Co, float* __restrict__ Cf,
                  int K, int sAm, int sAk, int sBn, int sBk, int ldc,
                  ll strideA, ll strideB, ll strideC, const float* __restrict__ bn) {
    extern __shared__ u32 smu[];
    const int tid = threadIdx.x, lane = tid & 31, w = tid >> 5;
    const int mw = (w & 1) * 64, nw = (w >> 1) * 32;
    const int i0 = blockIdx.y * 128, j0 = blockIdx.x * 128, bz = blockIdx.z;
    const u32* Ab = A + (ll)bz * strideA;
    const u32* Bb = B + (ll)bz * strideB;
    const int lq = lane >> 2, lr = lane & 3;
    const u32 sbase = smem_u32p(smu);

    float acc[4][4][4];
#pragma unroll
    for (int a = 0; a < 4; a++)
#pragma unroll
        for (int b = 0; b < 4; b++)
#pragma unroll
            for (int c = 0; c < 4; c++) acc[a][b][c] = 0.f;

    const int nch = K >> 5;
    stage_load(Ab, Bb, i0, j0, 0, sAm, sAk, sBn, sBk, sbase, sbase + STG_W * 4, tid);
    CP_COMMIT();
    for (int ch = 0; ch < nch; ch++) {
        const int st = ch & 1;
        if (ch + 1 < nch) {
            const int st2 = (ch + 1) & 1;
            stage_load(Ab, Bb, i0, j0, (ch + 1) << 5, sAm, sAk, sBn, sBk,
                       sbase + st2 * STG_B, sbase + st2 * STG_B + STG_W * 4, tid);
            CP_COMMIT();
            CP_WAIT1();
        } else {
            CP_WAIT0();
        }
        __syncthreads();
        u32 (*As)[36] = (u32(*)[36])(smu + st * 2 * STG_W);
        u32 (*Bs)[36] = (u32(*)[36])(smu + st * 2 * STG_W + STG_W);
#pragma unroll
        for (int ks = 0; ks < 4; ks++) {
            const int kw = ks * 8;
            u32 bh[4][2], bl[4][2];
#pragma unroll
            for (int nt = 0; nt < 4; nt++) {
                int n = nw + nt * 8 + lq;
                u32 b0 = Bs[n][kw + lr], b1 = Bs[n][kw + 4 + lr];
                bh[nt][0] = (b0 & 0xffffu) * 0x10001u;
                bl[nt][0] = (b0 >> 16) * 0x10001u;
                bh[nt][1] = (b1 & 0xffffu) * 0x10001u;
                bl[nt][1] = (b1 >> 16) * 0x10001u;
            }
#pragma unroll
            for (int mt = 0; mt < 4; mt++) {
                int m = mw + mt * 16 + lq;
                u32 a0 = As[m][kw + lr], a1 = As[m + 8][kw + lr];
                u32 a2 = As[m][kw + 4 + lr], a3 = As[m + 8][kw + 4 + lr];
#pragma unroll
                for (int nt = 0; nt < 4; nt++) {
                    mma16816(acc[mt][nt], a0, a1, a2, a3, bh[nt][0], bh[nt][1]);
                    mma16816(acc[mt][nt], a0, a1, a2, a3, bl[nt][0], bl[nt][1]);
                }
            }
        }
        __syncthreads();
    }

#pragma unroll
    for (int mt = 0; mt < 4; mt++) {
#pragma unroll
        for (int nt = 0; nt < 4; nt++) {
            int gm0 = i0 + mw + mt * 16 + lq;
            int gn  = j0 + nw + nt * 8 + lr * 2;
#pragma unroll
            for (int half = 0; half < 2; half++) {
                int gm = gm0 + half * 8;
                float v0 = acc[mt][nt][half * 2], v1 = acc[mt][nt][half * 2 + 1];
                if (EPI == 0) {
                    uint2 pv = make_uint2(pack_hl(v0), pack_hl(v1));
                    *(uint2*)&Co[(ll)bz * strideC + (ll)gm * ldc + gn] = pv;
                } else if (EPI == 1) {
                    v0 = v0 >= 0.f ? v0 : 0.2f * v0;
                    v1 = v1 >= 0.f ? v1 : 0.2f * v1;
                    uint2 pv = make_uint2(pack_hl(v0), pack_hl(v1));
                    *(uint2*)&Co[(ll)bz * strideC + (ll)gm * ldc + gn] = pv;
                } else {
                    float g = bn[gm], be = bn[1024 + gm], mm = bn[2048 + gm], va = bn[3072 + gm];
                    float s = g * rsqrtf(va + 1e-5f);
                    float t = be - mm * s;
                    v0 = v0 * s + t; v0 = v0 >= 0.f ? v0 : 0.2f * v0;
                    v1 = v1 * s + t; v1 = v1 >= 0.f ? v1 : 0.2f * v1;
                    *(float2*)&Cf[(ll)bz * strideC + (ll)gm * ldc + gn] = make_float2(v0, v1);
                }
            }
        }
    }
}

// ==================== softmax over packed rows (scale 1/32) ====================
__global__ __launch_bounds__(256)
void softmax_hl_kernel(u32* __restrict__ att) {
    __shared__ float sd[NPTS];
    __shared__ float red[256];
    const int tid = threadIdx.x;
    u32* p = att + (ll)blockIdx.x * NPTS;
    float mx = -3.4e38f;
    for (int t = tid; t < NPTS; t += 256) {
        float v = unpack_hl(p[t]) * 0.03125f;
        sd[t] = v;
        mx = fmaxf(mx, v);
    }
    red[tid] = mx;
    __syncthreads();
    for (int h = 128; h > 0; h >>= 1) {
        if (tid < h) red[tid] = fmaxf(red[tid], red[tid + h]);
        __syncthreads();
    }
    mx = red[0];
    __syncthreads();
    float sum = 0.f;
    for (int t = tid; t < NPTS; t += 256) {
        float e = __expf(sd[t] - mx);
        sd[t] = e;
        sum += e;
    }
    red[tid] = sum;
    __syncthreads();
    for (int h = 128; h > 0; h >>= 1) {
        if (tid < h) red[tid] += red[tid + h];
        __syncthreads();
    }
    float inv = 1.f / red[0];
    __syncthreads();
    for (int t = tid; t < NPTS; t += 256) p[t] = pack_hl(sd[t] * inv);
}

// ==================== residual add + BN (packed) ====================
__global__ void addbn_hl_kernel(const u32* __restrict__ a, const u32* __restrict__ r,
                                const float* __restrict__ bn, u32* __restrict__ out, ll total) {
    ll i = (ll)blockIdx.x * blockDim.x + threadIdx.x;
    if (i >= total) return;
    int c = (int)((i >> 11) & 1023);
    float g = bn[c], be = bn[1024 + c], m = bn[2048 + c], va = bn[3072 + c];
    float s = g * rsqrtf(va + 1e-5f);
    float v = (unpack_hl(a[i]) + unpack_hl(r[i])) * s + (be - m * s);
    out[i] = pack_hl(v);
}

// ==================== launcher ====================
extern "C" void kernel_launch(void* const* d_in, const int* in_sizes, int n_in,
                              void* d_out, int out_size) {
    const float* x       = (const float*)d_in[0];
    const float* ec1_w1  = (const float*)d_in[1];
    const float* ec1_bn1 = (const float*)d_in[2];
    const float* ec1_w2  = (const float*)d_in[3];
    const float* ec1_bn2 = (const float*)d_in[4];
    const float* ec2_w1  = (const float*)d_in[5];
    const float* ec2_bn1 = (const float*)d_in[6];
    const float* ec2_w2  = (const float*)d_in[7];
    const float* ec2_bn2 = (const float*)d_in[8];
    const float* ec3_w1  = (const float*)d_in[9];
    const float* ec3_bn1 = (const float*)d_in[10];
    const float* ec3_w2  = (const float*)d_in[11];
    const float* ec3_bn2 = (const float*)d_in[12];
    const float* emb_w   = (const float*)d_in[13];
    const float* q_w     = (const float*)d_in[14];
    const float* k_w     = (const float*)d_in[15];
    const float* v_w     = (const float*)d_in[16];
    const float* att_bn1 = (const float*)d_in[17];
    const float* ff_w1   = (const float*)d_in[18];
    const float* ff_w2   = (const float*)d_in[19];
    const float* att_bn2 = (const float*)d_in[20];
    const float* cb_w    = (const float*)d_in[21];
    const float* cb_bn   = (const float*)d_in[22];
    float* out = (float*)d_out;

    float *xT3, *sqn, *dist, *xcT;
    u32 *xchl, *h, *q, *kk, *v, *xr, *ffo, *embw, *qw, *kw, *vw, *f1w, *f2w, *cw;
    int* idxp;
    cudaGetSymbolAddress((void**)&xT3, g_xT3);
    cudaGetSymbolAddress((void**)&sqn, g_sqn);
    cudaGetSymbolAddress((void**)&dist, g_dist);
    cudaGetSymbolAddress((void**)&idxp, g_idx);
    cudaGetSymbolAddress((void**)&xcT, g_xcT);
    cudaGetSymbolAddress((void**)&xchl, g_xchl);
    cudaGetSymbolAddress((void**)&h, g_h);
    cudaGetSymbolAddress((void**)&q, g_q);
    cudaGetSymbolAddress((void**)&kk, g_k);
    cudaGetSymbolAddress((void**)&v, g_v);
    cudaGetSymbolAddress((void**)&xr, g_xr);
    cudaGetSymbolAddress((void**)&ffo, g_ffo);
    cudaGetSymbolAddress((void**)&embw, g_embw);
    cudaGetSymbolAddress((void**)&qw, g_qw);
    cudaGetSymbolAddress((void**)&kw, g_kw);
    cudaGetSymbolAddress((void**)&vw, g_vw);
    cudaGetSymbolAddress((void**)&f1w, g_f1w);
    cudaGetSymbolAddress((void**)&f2w, g_f2w);
    cudaGetSymbolAddress((void**)&cw, g_cw);

    const size_t sm3  = (size_t)(6 * 64 + 4096 + 3 * 36 + 32 * 68 + 256 + 4 + 32) * 4;
    const size_t sm64 = (size_t)(128 * 64 + 4096 + 64 * 36 + 32 * 68 + 256 + 64 + 32) * 4;
    cudaFuncSetAttribute((const void*)edgeconv_kernel<64>,
                         cudaFuncAttributeMaxDynamicSharedMemorySize, (int)sm64);
    const int SMTC = 2 * STG_B;  // 73728 B
    cudaFuncSetAttribute((const void*)mmamm_kernel<0>, cudaFuncAttributeMaxDynamicSharedMemorySize, SMTC);
    cudaFuncSetAttribute((const void*)mmamm_kernel<1>, cudaFuncAttributeMaxDynamicSharedMemorySize, SMTC);
    cudaFuncSetAttribute((const void*)mmamm_kernel<2>, cudaFuncAttributeMaxDynamicSharedMemorySize, SMTC);

    const int npts = BB * NPTS;
    const ll CH = (ll)1024 * NPTS;
    const ll AT = (ll)NPTS * NPTS;
    const ll total = (ll)BB * 1024 * NPTS;

    transpose_x_kernel<<<(npts + 255) / 256, 256>>>(x, xT3);

    dim3 gd(NPTS / 128, NPTS / 128, BB);
    // EdgeConv 1 (C=3)
    sqnorm_kernel<<<(npts + 255) / 256, 256>>>(xT3, 3, 0, 3, sqn);
    distgemm_kernel<<<gd, 256>>>(xT3, dist, 3, 3, (ll)NPTS * 3, sqn);
    topk_kernel<<<npts, 256>>>(dist, idxp);
    edgeconv_kernel<3><<<1024, 256, sm3>>>(xT3, 3, 0, idxp, ec1_w1, ec1_bn1, ec1_w2, ec1_bn2, xcT, 192, 0);
    // EdgeConv 2
    sqnorm_kernel<<<(npts + 255) / 256, 256>>>(xcT, 192, 0, 64, sqn);
    distgemm_kernel<<<gd, 256>>>(xcT, dist, 64, 192, (ll)NPTS * 192, sqn);
    topk_kernel<<<npts, 256>>>(dist, idxp);
    edgeconv_kernel<64><<<1024, 256, sm64>>>(xcT, 192, 0, idxp, ec2_w1, ec2_bn1, ec2_w2, ec2_bn2, xcT, 192, 64);
    // EdgeConv 3
    sqnorm_kernel<<<(npts + 255) / 256, 256>>>(xcT, 192, 64, 64, sqn);
    distgemm_kernel<<<gd, 256>>>(xcT + 64, dist, 64, 192, (ll)NPTS * 192, sqn);
    topk_kernel<<<npts, 256>>>(dist, idxp);
    edgeconv_kernel<64><<<1024, 256, sm64>>>(xcT, 192, 64, idxp, ec3_w1, ec3_bn1, ec3_w2, ec3_bn2, xcT, 192, 128);

    // pack activations + weights to hi/lo
    split_kernel<<<(int)(((ll)npts * 192 + 255) / 256), 256>>>(xcT, xchl, (ll)npts * 192);
    split_kernel<<<(1024 * 192 + 255) / 256, 256>>>(emb_w, embw, 1024 * 192);
    split_kernel<<<(1024 * 1024 + 255) / 256, 256>>>(q_w, qw, 1024 * 1024);
    split_kernel<<<(1024 * 1024 + 255) / 256, 256>>>(k_w, kw, 1024 * 1024);
    split_kernel<<<(1024 * 1024 + 255) / 256, 256>>>(v_w, vw, 1024 * 1024);
    split_kernel<<<(512 * 1024 + 255) / 256, 256>>>(ff_w1, f1w, 512 * 1024);
    split_kernel<<<(512 * 1024 + 255) / 256, 256>>>(ff_w2, f2w, 512 * 1024);
    split_kernel<<<(1024 * 1024 + 255) / 256, 256>>>(cb_w, cw, 1024 * 1024);

    u32* distu = (u32*)dist;
    dim3 ge(NPTS / 128, 1024 / 128, BB);
    dim3 ga(NPTS / 128, NPTS / 128, BB);
    dim3 gf(NPTS / 128, 512 / 128, BB);
    // h = emb_w @ xc
    mmamm_kernel<0><<<ge, 256, SMTC>>>(embw, xchl, h, nullptr, 192, 192, 1, 192, 1, NPTS,
                                       0, (ll)NPTS * 192, CH, nullptr);
    // q, k, v
    mmamm_kernel<0><<<ge, 256, SMTC>>>(qw, h, q, nullptr, 1024, 1024, 1, 1, NPTS, NPTS, 0, CH, CH, nullptr);
    mmamm_kernel<0><<<ge, 256, SMTC>>>(kw, h, kk, nullptr, 1024, 1024, 1, 1, NPTS, NPTS, 0, CH, CH, nullptr);
    mmamm_kernel<0><<<ge, 256, SMTC>>>(vw, h, v, nullptr, 1024, 1024, 1, 1, NPTS, NPTS, 0, CH, CH, nullptr);
    // logits[n,m] = sum_c q[c,n] k[c,m]
    mmamm_kernel<0><<<ga, 256, SMTC>>>(q, kk, distu, nullptr, 1024, 1, NPTS, 1, NPTS, NPTS, CH, CH, AT, nullptr);
    softmax_hl_kernel<<<npts, 256>>>(distu);
    // xr[c,n] = sum_m v[c,m] att[n,m]
    mmamm_kernel<0><<<ge, 256, SMTC>>>(v, distu, xr, nullptr, NPTS, NPTS, 1, NPTS, 1, NPTS, CH, AT, CH, nullptr);
    addbn_hl_kernel<<<(int)((total + 255) / 256), 256>>>(h, xr, att_bn1, q /*h2*/, total);
    // ff
    mmamm_kernel<1><<<gf, 256, SMTC>>>(f1w, q, ffo, nullptr, 1024, 1024, 1, 1, NPTS, NPTS, 0, CH, (ll)512 * NPTS, nullptr);
    mmamm_kernel<0><<<ge, 256, SMTC>>>(f2w, ffo, kk /*ff*/, nullptr, 512, 512, 1, 1, NPTS, NPTS, 0, (ll)512 * NPTS, CH, nullptr);
    addbn_hl_kernel<<<(int)((total + 255) / 256), 256>>>(q, kk, att_bn2, v /*h3*/, total);
    // classifier: BN + lrelu, fp32 out
    mmamm_kernel<2><<<ge, 256, SMTC>>>(cw, v, nullptr, out, 1024, 1024, 1, 1, NPTS, NPTS, 0, CH, CH, cb_bn);
}

// round 11
// speedup vs baseline: 4.2717x; 1.3148x over previous
#include <cuda_runtime.h>
#include <cuda_bf16.h>
#include <cuda_fp16.h>
#include <cstdint>

#define BB 8
#define NPTS 2048
#define KNN 32
typedef long long ll;
typedef uint32_t u32;
typedef unsigned short u16;

// ==================== scratch (device globals) ====================
static __device__ float g_xT3[BB * NPTS * 3];
static __device__ float g_sqn[BB * NPTS];
static __device__ float g_dist[(ll)BB * NPTS * NPTS];   // fp32 dist; reused (as u32) for logits/att
static __device__ int   g_idx[BB * NPTS * KNN];
static __device__ float g_xcT[BB * NPTS * 192];
static __device__ u32   g_xchl[BB * NPTS * 192];
static __device__ u32   g_h [(ll)BB * NPTS * 1024];
static __device__ u32   g_q [(ll)BB * NPTS * 1024];     // q_t fp16, later h2
static __device__ u32   g_k [(ll)BB * NPTS * 1024];     // k_t fp16
static __device__ u32   g_v [(ll)BB * NPTS * 1024];     // v fp16, later h3
static __device__ u32   g_ffo[(ll)BB * NPTS * 512];
static __device__ u32   g_embw[1024 * 192];
static __device__ u32   g_qw[1024 * 1024];
static __device__ u32   g_kw[1024 * 1024];
static __device__ u32   g_vw[1024 * 1024];
static __device__ u32   g_f1w[512 * 1024];
static __device__ u32   g_f2w[1024 * 512];
static __device__ u32   g_cw[1024 * 1024];

// ==================== helpers ====================
__device__ __forceinline__ u32 pack_hl(float v) {
    __nv_bfloat16 h = __float2bfloat16(v);
    float r = v - __bfloat162float(h);
    __nv_bfloat16 l = __float2bfloat16(r);
    return (u32)__bfloat16_as_ushort(h) | ((u32)__bfloat16_as_ushort(l) << 16);
}
__device__ __forceinline__ float unpack_hl(u32 u) {
    return __bfloat162float(__ushort_as_bfloat16((u16)(u & 0xffffu)))
         + __bfloat162float(__ushort_as_bfloat16((u16)(u >> 16)));
}
__device__ __forceinline__ u32 pack_f16x2(float lo, float hi) {
    __half2 hv = __floats2half2_rn(lo, hi);
    return *reinterpret_cast<u32*>(&hv);
}
__device__ __forceinline__ void mma16816(float* c, u32 a0, u32 a1, u32 a2, u32 a3, u32 b0, u32 b1) {
    asm volatile("mma.sync.aligned.m16n8k16.row.col.f32.bf16.bf16.f32 "
                 "{%0,%1,%2,%3}, {%4,%5,%6,%7}, {%8,%9}, {%0,%1,%2,%3};"
                 : "+f"(c[0]), "+f"(c[1]), "+f"(c[2]), "+f"(c[3])
                 : "r"(a0), "r"(a1), "r"(a2), "r"(a3), "r"(b0), "r"(b1));
}
__device__ __forceinline__ void mma16816h(float* c, u32 a0, u32 a1, u32 a2, u32 a3, u32 b0, u32 b1) {
    asm volatile("mma.sync.aligned.m16n8k16.row.col.f32.f16.f16.f32 "
                 "{%0,%1,%2,%3}, {%4,%5,%6,%7}, {%8,%9}, {%0,%1,%2,%3};"
                 : "+f"(c[0]), "+f"(c[1]), "+f"(c[2]), "+f"(c[3])
                 : "r"(a0), "r"(a1), "r"(a2), "r"(a3), "r"(b0), "r"(b1));
}
__device__ __forceinline__ u32 smem_u32p(const void* p) {
    u32 a;
    asm("{ .reg .u64 t; cvta.to.shared.u64 t, %1; cvt.u32.u64 %0, t; }" : "=r"(a) : "l"(p));
    return a;
}
__device__ __forceinline__ void cpasync16(u32 smaddr, const void* gptr) {
    asm volatile("cp.async.cg.shared.global [%0], [%1], 16;" :: "r"(smaddr), "l"(gptr));
}
__device__ __forceinline__ void cpasync4(u32 smaddr, const void* gptr) {
    asm volatile("cp.async.ca.shared.global [%0], [%1], 4;" :: "r"(smaddr), "l"(gptr));
}
#define CP_COMMIT() asm volatile("cp.async.commit_group;" ::: "memory")
#define CP_WAIT1()  asm volatile("cp.async.wait_group 1;" ::: "memory")
#define CP_WAIT0()  asm volatile("cp.async.wait_group 0;" ::: "memory")

// ==================== small kernels ====================
__global__ void transpose_x_kernel(const float* __restrict__ x, float* __restrict__ xt) {
    int i = blockIdx.x * blockDim.x + threadIdx.x;
    if (i >= BB * NPTS) return;
    int b = i / NPTS, n = i % NPTS;
#pragma unroll
    for (int c = 0; c < 3; c++)
        xt[i * 3 + c] = x[(b * 3 + c) * NPTS + n];
}

__global__ void sqnorm_kernel(const float* __restrict__ xt, int rs, int off, int C,
                              float* __restrict__ sq) {
    int i = blockIdx.x * blockDim.x + threadIdx.x;
    if (i >= BB * NPTS) return;
    const float* p = xt + (ll)i * rs + off;
    float s = 0.f;
    for (int c = 0; c < C; c++) { float v = p[c]; s += v * v; }
    sq[i] = s;
}

__global__ void split_kernel(const float* __restrict__ in, u32* __restrict__ out, ll n) {
    ll i = (ll)blockIdx.x * blockDim.x + threadIdx.x;
    if (i < n) out[i] = pack_hl(in[i]);
}

// ==================== SIMT SGEMM for kNN distances ====================
__global__ __launch_bounds__(256, 2)
void distgemm_kernel(const float* __restrict__ A, float* __restrict__ C, int K, int lda,
                     ll sA, const float* __restrict__ sq) {
    __shared__ float As[16][132];
    __shared__ float Bs[16][132];
    const int tid = threadIdx.x;
    const int tx = tid & 15, ty = tid >> 4;
    const int i0 = blockIdx.y * 128, j0 = blockIdx.x * 128;
    const int bz = blockIdx.z;
    const float* Ab = A + (ll)bz * sA;
    float acc[8][8];
#pragma unroll
    for (int i = 0; i < 8; i++)
#pragma unroll
        for (int j = 0; j < 8; j++) acc[i][j] = 0.f;
    for (int k0 = 0; k0 < K; k0 += 16) {
        for (int t = tid; t < 2048; t += 256) {
            int kq = t & 15, i = t >> 4;
            int gk = k0 + kq;
            As[kq][i] = (gk < K) ? Ab[(ll)(i0 + i) * lda + gk] : 0.f;
        }
        for (int t = tid; t < 2048; t += 256) {
            int kq = t & 15, j = t >> 4;
            int gk = k0 + kq;
            Bs[kq][j] = (gk < K) ? Ab[(ll)(j0 + j) * lda + gk] : 0.f;
        }
        __syncthreads();
#pragma unroll
        for (int kq = 0; kq < 16; kq++) {
            float4 a0 = *(const float4*)&As[kq][ty * 8];
            float4 a1 = *(const float4*)&As[kq][ty * 8 + 4];
            float4 b0 = *(const float4*)&Bs[kq][tx * 8];
            float4 b1 = *(const float4*)&Bs[kq][tx * 8 + 4];
            float a[8] = {a0.x, a0.y, a0.z, a0.w, a1.x, a1.y, a1.z, a1.w};
            float b[8] = {b0.x, b0.y, b0.z, b0.w, b1.x, b1.y, b1.z, b1.w};
#pragma unroll
            for (int i = 0; i < 8; i++)
#pragma unroll
                for (int j = 0; j < 8; j++) acc[i][j] += a[i] * b[j];
        }
        __syncthreads();
    }
    float* Cb = C + (ll)bz * NPTS * NPTS;
    const float* sqb = sq + (ll)bz * NPTS;
#pragma unroll
    for (int ii = 0; ii < 8; ii++) {
        int gi = i0 + ty * 8 + ii;
        float sqi = sqb[gi];
#pragma unroll
        for (int jj = 0; jj < 8; jj++) {
            int gj = j0 + tx * 8 + jj;
            Cb[(ll)gi * NPTS + gj] = sqi + sqb[gj] - 2.f * acc[ii][jj];
        }
    }
}

// ==================== top-k via 2-level radix select ====================
__global__ __launch_bounds__(256)
void topk_kernel(const float* __restrict__ dist, int* __restrict__ out) {
    __shared__ u32 hist[256];
    __shared__ u32 cum[256];
    __shared__ u32 candk[2048];
    __shared__ u32 candi[2048];
    __shared__ u32 candk2[2048];
    __shared__ u32 candi2[2048];
    __shared__ u32 ctr[2];
    __shared__ u32 selbin, selbefore;
    const int tid = threadIdx.x;
    const float* rp = dist + (ll)blockIdx.x * NPTS;
    hist[tid] = 0;
    if (tid < 2) ctr[tid] = 0;
    __syncthreads();
    u32 key[8];
#pragma unroll
    for (int j = 0; j < 8; j++) {
        u32 u = __float_as_uint(rp[tid + j * 256]);
        key[j] = (u & 0x80000000u) ? ~u : (u | 0x80000000u);
        atomicAdd(&hist[key[j] >> 24], 1u);
    }
    __syncthreads();
    cum[tid] = hist[tid];
    __syncthreads();
#pragma unroll
    for (int off = 1; off < 256; off <<= 1) {
        u32 v = (tid >= off) ? cum[tid - off] : 0u;
        __syncthreads();
        cum[tid] += v;
        __syncthreads();
    }
    {
        u32 inc = cum[tid], exc = inc - hist[tid];
        if (exc < KNN && inc >= KNN) { selbin = (u32)tid; selbefore = exc; }
    }
    __syncthreads();
    const u32 sb = selbin, before = selbefore;
    int* op = out + (ll)blockIdx.x * KNN;
#pragma unroll
    for (int j = 0; j < 8; j++) {
        u32 b = key[j] >> 24;
        int idx = tid + j * 256;
        if (b < sb) {
            u32 p = atomicAdd(&ctr[0], 1u);
            op[p] = idx;
        } else if (b == sb) {
            u32 p = atomicAdd(&ctr[1], 1u);
            candk[p] = key[j];
            candi[p] = (u32)idx;
        }
    }
    __syncthreads();
    const int cnt = (int)ctr[1];
    const u32 need1 = KNN - before;
    hist[tid] = 0;
    __syncthreads();
    for (int t = tid; t < cnt; t += 256)
        atomicAdd(&hist[(candk[t] >> 16) & 0xffu], 1u);
    __syncthreads();
    cum[tid] = hist[tid];
    __syncthreads();
#pragma unroll
    for (int off = 1; off < 256; off <<= 1) {
        u32 v = (tid >= off) ? cum[tid - off] : 0u;
        __syncthreads();
        cum[tid] += v;
        __syncthreads();
    }
    {
        u32 inc = cum[tid], exc = inc - hist[tid];
        if (exc < need1 && inc >= need1) { selbin = (u32)tid; selbefore = exc; }
    }
    if (tid == 0) { ctr[0] = 0; ctr[1] = 0; }
    __syncthreads();
    const u32 sb2 = selbin, before2 = selbefore;
    for (int t = tid; t < cnt; t += 256) {
        u32 k2 = candk[t];
        u32 b2 = (k2 >> 16) & 0xffu;
        if (b2 < sb2) {
            u32 p = atomicAdd(&ctr[0], 1u);
            op[before + p] = (int)candi[t];
        } else if (b2 == sb2) {
            u32 p = atomicAdd(&ctr[1], 1u);
            candk2[p] = k2;
            candi2[p] = candi[t];
        }
    }
    __syncthreads();
    const int need2 = (int)(KNN - before - before2);
    const int cnt2 = (int)ctr[1];
    if (tid < 32) {
        for (int s = 0; s < need2; s++) {
            u32 bk = 0xffffffffu, bi = 0xffffffffu;
            for (int t = tid; t < cnt2; t += 32) {
                u32 k2 = candk2[t], i2 = candi2[t];
                if (k2 < bk || (k2 == bk && i2 < bi)) { bk = k2; bi = i2; }
            }
#pragma unroll
            for (int off = 16; off > 0; off >>= 1) {
                u32 ok = __shfl_xor_sync(0xffffffffu, bk, off);
                u32 oi = __shfl_xor_sync(0xffffffffu, bi, off);
                if (ok < bk || (ok == bk && oi < bi)) { bk = ok; bi = oi; }
            }
            for (int t = tid; t < cnt2; t += 32) {
                if (candk2[t] == bk && candi2[t] == bi) { candk2[t] = 0xffffffffu; candi2[t] = 0xffffffffu; }
            }
            if (tid == 0) op[before + before2 + s] = (int)bi;
            __syncwarp();
        }
    }
}

// ==================== fused EdgeConv (conflict-free layouts + center-bias factorization) ====================
template <int CIN>
__global__ __launch_bounds__(256)
void edgeconv_kernel(const float* __restrict__ xin, int rsin, int offin,
                     const int* __restrict__ idx,
                     const float* __restrict__ w1, const float* __restrict__ bn1,
                     const float* __restrict__ w2, const float* __restrict__ bn2,
                     float* __restrict__ xout, int rsout, int offout) {
    constexpr int C2 = 2 * CIN;
    constexpr int CPAD = (CIN + 3) & ~3;
    extern __shared__ float sm[];
    float* w1s = sm;
    float* w2s = w1s + C2 * 64;
    float* es  = w2s + 4096;
    float* h1  = es + CIN * 36;
    float* red = h1 + 32 * 68;
    float* ctr = red + 256;
    int*   iks = (int*)(ctr + CPAD);

    const int tid = threadIdx.x;
    const int o = tid & 63, kg = tid >> 6;
    for (int t = tid; t < 64 * C2; t += 256) {
        int oo = t / C2, c = t - oo * C2;
        w1s[c * 64 + oo] = w1[t];
    }
    for (int t = tid; t < 4096; t += 256) {
        int oo = t >> 6, c = t & 63;
        w2s[c * 64 + oo] = w2[t];
    }
    const float s1 = bn1[o] * rsqrtf(bn1[192 + o] + 1e-5f);
    const float t1 = bn1[64 + o] - bn1[128 + o] * s1;
    const float s2 = bn2[o] * rsqrtf(bn2[192 + o] + 1e-5f);
    const float t2 = bn2[64 + o] - bn2[128 + o] * s2;
    __syncthreads();

    for (int p = blockIdx.x; p < BB * NPTS; p += gridDim.x) {
        const int b = p >> 11;
        if (tid < CIN) ctr[tid] = xin[(ll)p * rsin + offin + tid];
        if (tid < KNN) iks[tid] = idx[p * KNN + tid];
        __syncthreads();
        if (CIN % 4 == 0) {
            for (int t = tid; t < 32 * (CIN / 4); t += 256) {
                int kq = t & 31, cg = t >> 5;
                int m = iks[kq];
                float4 v = *(const float4*)&xin[(ll)(b * NPTS + m) * rsin + offin + cg * 4];
                float4 c4 = *(const float4*)&ctr[cg * 4];
                es[(cg * 4 + 0) * 36 + kq] = v.x - c4.x;
                es[(cg * 4 + 1) * 36 + kq] = v.y - c4.y;
                es[(cg * 4 + 2) * 36 + kq] = v.z - c4.z;
                es[(cg * 4 + 3) * 36 + kq] = v.w - c4.w;
            }
        } else {
            for (int t = tid; t < 32 * CIN; t += 256) {
                int kq = t & 31, c = t >> 5;
                int m = iks[kq];
                es[c * 36 + kq] = xin[(ll)(b * NPTS + m) * rsin + offin + c] - ctr[c];
            }
        }
        __syncthreads();
        float bias = 0.f;
        for (int c = 0; c < CIN; c++)
            bias += w1s[(CIN + c) * 64 + o] * ctr[c];
        float acc[8];
#pragma unroll
        for (int j = 0; j < 8; j++) acc[j] = bias;
        for (int c = 0; c < CIN; c++) {
            float w = w1s[c * 64 + o];
            float4 e0 = *(const float4*)&es[c * 36 + kg * 8];
            float4 e1 = *(const float4*)&es[c * 36 + kg * 8 + 4];
            acc[0] += w * e0.x; acc[1] += w * e0.y; acc[2] += w * e0.z; acc[3] += w * e0.w;
            acc[4] += w * e1.x; acc[5] += w * e1.y; acc[6] += w * e1.z; acc[7] += w * e1.w;
        }
#pragma unroll
        for (int j = 0; j < 8; j++) {
            float v = acc[j] * s1 + t1;
            v = v >= 0.f ? v : 0.2f * v;
            h1[(kg * 8 + j) * 68 + o] = v;
            acc[j] = 0.f;
        }
        __syncthreads();
#pragma unroll 4
        for (int c4 = 0; c4 < 16; c4++) {
            float w0 = w2s[(c4 * 4 + 0) * 64 + o];
            float w1v = w2s[(c4 * 4 + 1) * 64 + o];
            float w2v = w2s[(c4 * 4 + 2) * 64 + o];
            float w3 = w2s[(c4 * 4 + 3) * 64 + o];
#pragma unroll
            for (int j = 0; j < 8; j++) {
                float4 hv = *(const float4*)&h1[(kg * 8 + j) * 68 + c4 * 4];
                acc[j] += w0 * hv.x + w1v * hv.y + w2v * hv.z + w3 * hv.w;
            }
        }
        float mx = -3.4e38f;
#pragma unroll
        for (int j = 0; j < 8; j++) {
            float v = acc[j] * s2 + t2;
            v = v >= 0.f ? v : 0.2f * v;
            mx = fmaxf(mx, v);
        }
        red[kg * 64 + o] = mx;
        __syncthreads();
        if (kg == 0) {
            float m = fmaxf(fmaxf(red[o], red[64 + o]), fmaxf(red[128 + o], red[192 + o]));
            xout[(ll)p * rsout + offout + o] = m;
        }
        __syncthreads();
    }
}

// ==================== mma.sync GEMM (cp.async 2-stage pipeline) ====================
// DT=0: split-bf16 exact; DT=1: fp16 single-pass
// EPI: 0 pack_hl; 1 lrelu+pack_hl; 2 BN+lrelu fp32; 3 +residual(R,hl)+BN+pack_hl; 4 fp16x2 pack
#define STG_W (128 * 36)
#define STG_B (2 * STG_W * 4)

__device__ __forceinline__ void stage_load(const u32* __restrict__ Ab, const u32* __restrict__ Bb,
                                           int i0, int j0, int k0,
                                           int sAm, int sAk, int sBn, int sBk,
                                           u32 aAddr, u32 bAddr, int tid) {
    if (sAk == 1) {
        for (int t = tid; t < 1024; t += 256) {
            int m = t >> 3, q = (t & 7) << 2;
            cpasync16(aAddr + (u32)(m * 36 + q) * 4, Ab + (ll)(i0 + m) * sAm + k0 + q);
        }
    } else {
        for (int t = tid; t < 4096; t += 256) {
            int m = t & 127, kk = t >> 7;
            cpasync4(aAddr + (u32)(m * 36 + kk) * 4, Ab + (ll)(i0 + m) + (ll)(k0 + kk) * sAk);
        }
    }
    if (sBk == 1) {
        for (int t = tid; t < 1024; t += 256) {
            int n = t >> 3, q = (t & 7) << 2;
            cpasync16(bAddr + (u32)(n * 36 + q) * 4, Bb + (ll)(j0 + n) * sBn + k0 + q);
        }
    } else {
        for (int t = tid; t < 4096; t += 256) {
            int n = t & 127, kk = t >> 7;
            cpasync4(bAddr + (u32)(n * 36 + kk) * 4, Bb + (ll)(j0 + n) + (ll)(k0 + kk) * sBk);
        }
    }
}

template <int EPI, int DT>
__global__ __launch_bounds__(256)
void mmamm_kernel(const u32* __restrict__ A, const u32* __restrict__ B,
                  u32* __restrict__ Co, float* __restrict__ Cf,
                  int K, int sAm, int sAk, int sBn, int sBk, int ldc,
                  ll strideA, ll strideB, ll strideC, const float* __restrict__ bn,
                  const u32* __restrict__ R) {
    extern __shared__ u32 smu[];
    const int tid = threadIdx.x, lane = tid & 31, w = tid >> 5;
    const int mw = (w & 1) * 64, nw = (w >> 1) * 32;
    const int i0 = blockIdx.y * 128, j0 = blockIdx.x * 128, bz = blockIdx.z;
    const u32* Ab = A + (ll)bz * strideA;
    const u32* Bb = B + (ll)bz * strideB;
    const int lq = lane >> 2, lr = lane & 3;
    const u32 sbase = smem_u32p(smu);

    float acc[4][4][4];
#pragma unroll
    for (int a = 0; a < 4; a++)
#pragma unroll
        for (int b = 0; b < 4; b++)
#pragma unroll
            for (int c = 0; c < 4; c++) acc[a][b][c] = 0.f;

    const int nch = K >> 5;
    stage_load(Ab, Bb, i0, j0, 0, sAm, sAk, sBn, sBk, sbase, sbase + STG_W * 4, tid);
    CP_COMMIT();
    for (int ch = 0; ch < nch; ch++) {
        const int st = ch & 1;
        if (ch + 1 < nch) {
            const int st2 = (ch + 1) & 1;
            stage_load(Ab, Bb, i0, j0, (ch + 1) << 5, sAm, sAk, sBn, sBk,
                       sbase + st2 * STG_B, sbase + st2 * STG_B + STG_W * 4, tid);
            CP_COMMIT();
            CP_WAIT1();
        } else {
            CP_WAIT0();
        }
        __syncthreads();
        u32 (*As)[36] = (u32(*)[36])(smu + st * 2 * STG_W);
        u32 (*Bs)[36] = (u32(*)[36])(smu + st * 2 * STG_W + STG_W);
#pragma unroll
        for (int ks = 0; ks < 4; ks++) {
            const int kw = ks * 8;
            if (DT == 0) {
                u32 bh[4][2], bl[4][2];
#pragma unroll
                for (int nt = 0; nt < 4; nt++) {
                    int n = nw + nt * 8 + lq;
                    u32 b0 = Bs[n][kw + lr], b1 = Bs[n][kw + 4 + lr];
                    bh[nt][0] = (b0 & 0xffffu) * 0x10001u;
                    bl[nt][0] = (b0 >> 16) * 0x10001u;
                    bh[nt][1] = (b1 & 0xffffu) * 0x10001u;
                    bl[nt][1] = (b1 >> 16) * 0x10001u;
                }
#pragma unroll
                for (int mt = 0; mt < 4; mt++) {
                    int m = mw + mt * 16 + lq;
                    u32 a0 = As[m][kw + lr], a1 = As[m + 8][kw + lr];
                    u32 a2 = As[m][kw + 4 + lr], a3 = As[m + 8][kw + 4 + lr];
#pragma unroll
                    for (int nt = 0; nt < 4; nt++) {
                        mma16816(acc[mt][nt], a0, a1, a2, a3, bh[nt][0], bh[nt][1]);
                        mma16816(acc[mt][nt], a0, a1, a2, a3, bl[nt][0], bl[nt][1]);
                    }
                }
            } else {
                u32 bq[4][2];
#pragma unroll
                for (int nt = 0; nt < 4; nt++) {
                    int n = nw + nt * 8 + lq;
                    bq[nt][0] = Bs[n][kw + lr];
                    bq[nt][1] = Bs[n][kw + 4 + lr];
                }
#pragma unroll
                for (int mt = 0; mt < 4; mt++) {
                    int m = mw + mt * 16 + lq;
                    u32 a0 = As[m][kw + lr], a1 = As[m + 8][kw + lr];
                    u32 a2 = As[m][kw + 4 + lr], a3 = As[m + 8][kw + 4 + lr];
#pragma unroll
                    for (int nt = 0; nt < 4; nt++)
                        mma16816h(acc[mt][nt], a0, a1, a2, a3, bq[nt][0], bq[nt][1]);
                }
            }
        }
        __syncthreads();
    }

#pragma unroll
    for (int mt = 0; mt < 4; mt++) {
#pragma unroll
        for (int nt = 0; nt < 4; nt++) {
            int gm0 = i0 + mw + mt * 16 + lq;
            int gn  = j0 + nw + nt * 8 + lr * 2;
#pragma unroll
            for (int half = 0; half < 2; half++) {
                int gm = gm0 + half * 8;
                float v0 = acc[mt][nt][half * 2], v1 = acc[mt][nt][half * 2 + 1];
                if (EPI == 0) {
                    uint2 pv = make_uint2(pack_hl(v0), pack_hl(v1));
                    *(uint2*)&Co[(ll)bz * strideC + (ll)gm * ldc + gn] = pv;
                } else if (EPI == 1) {
                    v0 = v0 >= 0.f ? v0 : 0.2f * v0;
                    v1 = v1 >= 0.f ? v1 : 0.2f * v1;
                    uint2 pv = make_uint2(pack_hl(v0), pack_hl(v1));
                    *(uint2*)&Co[(ll)bz * strideC + (ll)gm * ldc + gn] = pv;
                } else if (EPI == 2) {
                    float g = bn[gm], be = bn[1024 + gm], mm = bn[2048 + gm], va = bn[3072 + gm];
                    float s = g * rsqrtf(va + 1e-5f);
                    float t = be - mm * s;
                    v0 = v0 * s + t; v0 = v0 >= 0.f ? v0 : 0.2f * v0;
                    v1 = v1 * s + t; v1 = v1 >= 0.f ? v1 : 0.2f * v1;
                    *(float2*)&Cf[(ll)bz * strideC + (ll)gm * ldc + gn] = make_float2(v0, v1);
                } else if (EPI == 3) {
                    ll idx = (ll)bz * strideC + (ll)gm * ldc + gn;
                    uint2 rv = *(const uint2*)&R[idx];
                    float g = bn[gm], be = bn[1024 + gm], mm = bn[2048 + gm], va = bn[3072 + gm];
                    float s = g * rsqrtf(va + 1e-5f);
                    float t = be - mm * s;
                    v0 = (v0 + unpack_hl(rv.x)) * s + t;
                    v1 = (v1 + unpack_hl(rv.y)) * s + t;
                    uint2 pv = make_uint2(pack_hl(v0), pack_hl(v1));
                    *(uint2*)&Co[idx] = pv;
                } else {
                    Co[(ll)bz * strideC + (ll)gm * ldc + (gn >> 1)] = pack_f16x2(v0, v1);
                }
            }
        }
    }
}

// ==================== softmax over packed-hl logits -> fp16x2 att ====================
__global__ __launch_bounds__(256)
void softmax_f16_kernel(u32* __restrict__ att) {
    __shared__ float sd[NPTS];
    __shared__ float red[256];
    const int tid = threadIdx.x;
    u32* p = att + (ll)blockIdx.x * NPTS;
    float mx = -3.4e38f;
    for (int t = tid; t < NPTS; t += 256) {
        float v = unpack_hl(p[t]) * 0.03125f;
        sd[t] = v;
        mx = fmaxf(mx, v);
    }
    red[tid] = mx;
    __syncthreads();
    for (int h = 128; h > 0; h >>= 1) {
        if (tid < h) red[tid] = fmaxf(red[tid], red[tid + h]);
        __syncthreads();
    }
    mx = red[0];
    __syncthreads();
    float sum = 0.f;
    for (int t = tid; t < NPTS; t += 256) {
        float e = __expf(sd[t] - mx);
        sd[t] = e;
        sum += e;
    }
    red[tid] = sum;
    __syncthreads();
    for (int h = 128; h > 0; h >>= 1) {
        if (tid < h) red[tid] += red[tid + h];
        __syncthreads();
    }
    float inv = 1.f / red[0];
    __syncthreads();
    for (int t = tid; t < NPTS / 2; t += 256)
        p[t] = pack_f16x2(sd[2 * t] * inv, sd[2 * t + 1] * inv);
}

// ==================== launcher ====================
extern "C" void kernel_launch(void* const* d_in, const int* in_sizes, int n_in,
                              void* d_out, int out_size) {
    const float* x       = (const float*)d_in[0];
    const float* ec1_w1  = (const float*)d_in[1];
    const float* ec1_bn1 = (const float*)d_in[2];
    const float* ec1_w2  = (const float*)d_in[3];
    const float* ec1_bn2 = (const float*)d_in[4];
    const float* ec2_w1  = (const float*)d_in[5];
    const float* ec2_bn1 = (const float*)d_in[6];
    const float* ec2_w2  = (const float*)d_in[7];
    const float* ec2_bn2 = (const float*)d_in[8];
    const float* ec3_w1  = (const float*)d_in[9];
    const float* ec3_bn1 = (const float*)d_in[10];
    const float* ec3_w2  = (const float*)d_in[11];
    const float* ec3_bn2 = (const float*)d_in[12];
    const float* emb_w   = (const float*)d_in[13];
    const float* q_w     = (const float*)d_in[14];
    const float* k_w     = (const float*)d_in[15];
    const float* v_w     = (const float*)d_in[16];
    const float* att_bn1 = (const float*)d_in[17];
    const float* ff_w1   = (const float*)d_in[18];
    const float* ff_w2   = (const float*)d_in[19];
    const float* att_bn2 = (const float*)d_in[20];
    const float* cb_w    = (const float*)d_in[21];
    const float* cb_bn   = (const float*)d_in[22];
    float* out = (float*)d_out;

    float *xT3, *sqn, *dist, *xcT;
    u32 *xchl, *h, *q, *kk, *v, *ffo, *embw, *qw, *kw, *vw, *f1w, *f2w, *cw;
    int* idxp;
    cudaGetSymbolAddress((void**)&xT3, g_xT3);
    cudaGetSymbolAddress((void**)&sqn, g_sqn);
    cudaGetSymbolAddress((void**)&dist, g_dist);
    cudaGetSymbolAddress((void**)&idxp, g_idx);
    cudaGetSymbolAddress((void**)&xcT, g_xcT);
    cudaGetSymbolAddress((void**)&xchl, g_xchl);
    cudaGetSymbolAddress((void**)&h, g_h);
    cudaGetSymbolAddress((void**)&q, g_q);
    cudaGetSymbolAddress((void**)&kk, g_k);
    cudaGetSymbolAddress((void**)&v, g_v);
    cudaGetSymbolAddress((void**)&ffo, g_ffo);
    cudaGetSymbolAddress((void**)&embw, g_embw);
    cudaGetSymbolAddress((void**)&qw, g_qw);
    cudaGetSymbolAddress((void**)&kw, g_kw);
    cudaGetSymbolAddress((void**)&vw, g_vw);
    cudaGetSymbolAddress((void**)&f1w, g_f1w);
    cudaGetSymbolAddress((void**)&f2w, g_f2w);
    cudaGetSymbolAddress((void**)&cw, g_cw);

    const size_t sm3  = (size_t)(6 * 64 + 4096 + 3 * 36 + 32 * 68 + 256 + 4 + 32) * 4;
    const size_t sm64 = (size_t)(128 * 64 + 4096 + 64 * 36 + 32 * 68 + 256 + 64 + 32) * 4;
    cudaFuncSetAttribute((const void*)edgeconv_kernel<64>,
                         cudaFuncAttributeMaxDynamicSharedMemorySize, (int)sm64);
    const int SMTC = 2 * STG_B;  // 73728 B
    cudaFuncSetAttribute((const void*)mmamm_kernel<0, 0>, cudaFuncAttributeMaxDynamicSharedMemorySize, SMTC);
    cudaFuncSetAttribute((const void*)mmamm_kernel<1, 0>, cudaFuncAttributeMaxDynamicSharedMemorySize, SMTC);
    cudaFuncSetAttribute((const void*)mmamm_kernel<2, 0>, cudaFuncAttributeMaxDynamicSharedMemorySize, SMTC);
    cudaFuncSetAttribute((const void*)mmamm_kernel<3, 0>, cudaFuncAttributeMaxDynamicSharedMemorySize, SMTC);
    cudaFuncSetAttribute((const void*)mmamm_kernel<4, 0>, cudaFuncAttributeMaxDynamicSharedMemorySize, SMTC);
    cudaFuncSetAttribute((const void*)mmamm_kernel<0, 1>, cudaFuncAttributeMaxDynamicSharedMemorySize, SMTC);
    cudaFuncSetAttribute((const void*)mmamm_kernel<3, 1>, cudaFuncAttributeMaxDynamicSharedMemorySize, SMTC);

    const int npts = BB * NPTS;
    const ll CH = (ll)1024 * NPTS;
    const ll AT = (ll)NPTS * NPTS;
    const ll QT = (ll)NPTS * 512;    // q_t/k_t batch stride (words)
    const ll VT = (ll)1024 * 1024;   // v_f16 batch stride (words)

    transpose_x_kernel<<<(npts + 255) / 256, 256>>>(x, xT3);

    dim3 gd(NPTS / 128, NPTS / 128, BB);
    // EdgeConv 1 (C=3)
    sqnorm_kernel<<<(npts + 255) / 256, 256>>>(xT3, 3, 0, 3, sqn);
    distgemm_kernel<<<gd, 256>>>(xT3, dist, 3, 3, (ll)NPTS * 3, sqn);
    topk_kernel<<<npts, 256>>>(dist, idxp);
    edgeconv_kernel<3><<<1024, 256, sm3>>>(xT3, 3, 0, idxp, ec1_w1, ec1_bn1, ec1_w2, ec1_bn2, xcT, 192, 0);
    // EdgeConv 2
    sqnorm_kernel<<<(npts + 255) / 256, 256>>>(xcT, 192, 0, 64, sqn);
    distgemm_kernel<<<gd, 256>>>(xcT, dist, 64, 192, (ll)NPTS * 192, sqn);
    topk_kernel<<<npts, 256>>>(dist, idxp);
    edgeconv_kernel<64><<<1024, 256, sm64>>>(xcT, 192, 0, idxp, ec2_w1, ec2_bn1, ec2_w2, ec2_bn2, xcT, 192, 64);
    // EdgeConv 3
    sqnorm_kernel<<<(npts + 255) / 256, 256>>>(xcT, 192, 64, 64, sqn);
    distgemm_kernel<<<gd, 256>>>(xcT + 64, dist, 64, 192, (ll)NPTS * 192, sqn);
    topk_kernel<<<npts, 256>>>(dist, idxp);
    edgeconv_kernel<64><<<1024, 256, sm64>>>(xcT, 192, 64, idxp, ec3_w1, ec3_bn1, ec3_w2, ec3_bn2, xcT, 192, 128);

    // pack activations + weights to hi/lo
    split_kernel<<<(int)(((ll)npts * 192 + 255) / 256), 256>>>(xcT, xchl, (ll)npts * 192);
    split_kernel<<<(1024 * 192 + 255) / 256, 256>>>(emb_w, embw, 1024 * 192);
    split_kernel<<<(1024 * 1024 + 255) / 256, 256>>>(q_w, qw, 1024 * 1024);
    split_kernel<<<(1024 * 1024 + 255) / 256, 256>>>(k_w, kw, 1024 * 1024);
    split_kernel<<<(1024 * 1024 + 255) / 256, 256>>>(v_w, vw, 1024 * 1024);
    split_kernel<<<(512 * 1024 + 255) / 256, 256>>>(ff_w1, f1w, 512 * 1024);
    split_kernel<<<(512 * 1024 + 255) / 256, 256>>>(ff_w2, f2w, 512 * 1024);
    split_kernel<<<(1024 * 1024 + 255) / 256, 256>>>(cb_w, cw, 1024 * 1024);

    u32* distu = (u32*)dist;
    dim3 ge(NPTS / 128, 1024 / 128, BB);   // M=1024, N=2048
    dim3 gq(1024 / 128, NPTS / 128, BB);   // M=2048(n), N=1024(o)
    dim3 ga(NPTS / 128, NPTS / 128, BB);
    dim3 gf(NPTS / 128, 512 / 128, BB);
    // h = emb_w @ xc   [c][n] hl
    mmamm_kernel<0, 0><<<ge, 256, SMTC>>>(embw, xchl, h, nullptr, 192, 192, 1, 192, 1, NPTS,
                                          0, (ll)NPTS * 192, CH, nullptr, nullptr);
    // q_t[n][c] fp16:  A = h^T (transposed load), B = q_w (verbatim)
    mmamm_kernel<4, 0><<<gq, 256, SMTC>>>(h, qw, q, nullptr, 1024, 0, NPTS, 1024, 1, 512,
                                          CH, 0, QT, nullptr, nullptr);
    mmamm_kernel<4, 0><<<gq, 256, SMTC>>>(h, kw, kk, nullptr, 1024, 0, NPTS, 1024, 1, 512,
                                          CH, 0, QT, nullptr, nullptr);
    // v[c][m] fp16:    A = v_w (verbatim), B = h (transposed)
    mmamm_kernel<4, 0><<<ge, 256, SMTC>>>(vw, h, v, nullptr, 1024, 1024, 1, 0, NPTS, 1024,
                                          0, CH, VT, nullptr, nullptr);
    // logits[n][m] = q_t @ k_t^T  (fp16 single-pass, both verbatim)
    mmamm_kernel<0, 1><<<ga, 256, SMTC>>>(q, kk, distu, nullptr, 512, 512, 1, 512, 1, NPTS,
                                          QT, QT, AT, nullptr, nullptr);
    softmax_f16_kernel<<<npts, 256>>>(distu);
    // h2[c][n] = BN(h + v @ att^T)  (fp16 single-pass + fused residual/BN epilogue)
    mmamm_kernel<3, 1><<<ge, 256, SMTC>>>(v, distu, q /*h2*/, nullptr, 1024, 1024, 1, 2048, 1, NPTS,
                                          VT, AT, CH, att_bn1, h);
    // ff
    mmamm_kernel<1, 0><<<gf, 256, SMTC>>>(f1w, q, ffo, nullptr, 1024, 1024, 1, 1, NPTS, NPTS,
                                          0, CH, (ll)512 * NPTS, nullptr, nullptr);
    // h3[c][n] = BN(h2 + ff_w2 @ ffo)  (fused residual/BN)
    mmamm_kernel<3, 0><<<ge, 256, SMTC>>>(f2w, ffo, v /*h3*/, nullptr, 512, 512, 1, 1, NPTS, NPTS,
                                          0, (ll)512 * NPTS, CH, att_bn2, q);
    // classifier: BN + lrelu, fp32 out
    mmamm_kernel<2, 0><<<ge, 256, SMTC>>>(cw, v, nullptr, out, 1024, 1024, 1, 1, NPTS, NPTS,
                                          0, CH, CH, cb_bn, nullptr);
}

// round 13
// speedup vs baseline: 6.2654x; 1.4667x over previous
#include <cuda_runtime.h>
#include <cuda_bf16.h>
#include <cuda_fp16.h>
#include <cstdint>

#define BB 8
#define NPTS 2048
#define KNN 32
typedef long long ll;
typedef uint32_t u32;
typedef unsigned short u16;

// ==================== scratch (device globals) ====================
static __device__ float g_xT3[BB * NPTS * 3];
static __device__ float g_sqn[BB * NPTS];
static __device__ float g_dist[(ll)BB * NPTS * NPTS];   // fp32 dist; reused (as u32) for logits/att
static __device__ int   g_idx[BB * NPTS * KNN];
static __device__ float g_xcT[BB * NPTS * 192];
static __device__ u32   g_xchl[BB * NPTS * 192];
static __device__ u32   g_h [(ll)BB * NPTS * 1024];     // h_t hl [n][c]
static __device__ u32   g_hf[(ll)BB * NPTS * 512];      // h_t f16 [n][c/2]; later h3 f16
static __device__ u32   g_q [(ll)BB * NPTS * 1024];     // q_t f16 [n][c/2] (uses half); later h2 hl
static __device__ u32   g_k [(ll)BB * NPTS * 1024];     // k_t f16; later h2 f16
static __device__ u32   g_v [(ll)BB * NPTS * 1024];     // v f16 [c][m/2] (uses half); later h3 hl
static __device__ u32   g_ffo[(ll)BB * NPTS * 512];     // ffo f16 [n][o/2]
static __device__ u32   g_embw[1024 * 192];
static __device__ u32   g_qw[1024 * 512];
static __device__ u32   g_kw[1024 * 512];
static __device__ u32   g_vw[1024 * 512];
static __device__ u32   g_f1w[512 * 512];
static __device__ u32   g_f2w[1024 * 256];
static __device__ u32   g_cw[1024 * 512];

// ==================== helpers ====================
__device__ __forceinline__ u32 pack_hl(float v) {
    __nv_bfloat16 h = __float2bfloat16(v);
    float r = v - __bfloat162float(h);
    __nv_bfloat16 l = __float2bfloat16(r);
    return (u32)__bfloat16_as_ushort(h) | ((u32)__bfloat16_as_ushort(l) << 16);
}
__device__ __forceinline__ float unpack_hl(u32 u) {
    return __bfloat162float(__ushort_as_bfloat16((u16)(u & 0xffffu)))
         + __bfloat162float(__ushort_as_bfloat16((u16)(u >> 16)));
}
__device__ __forceinline__ u32 pack_f16x2(float lo, float hi) {
    __half2 hv = __floats2half2_rn(lo, hi);
    return *reinterpret_cast<u32*>(&hv);
}
__device__ __forceinline__ void mma16816(float* c, u32 a0, u32 a1, u32 a2, u32 a3, u32 b0, u32 b1) {
    asm volatile("mma.sync.aligned.m16n8k16.row.col.f32.bf16.bf16.f32 "
                 "{%0,%1,%2,%3}, {%4,%5,%6,%7}, {%8,%9}, {%0,%1,%2,%3};"
                 : "+f"(c[0]), "+f"(c[1]), "+f"(c[2]), "+f"(c[3])
                 : "r"(a0), "r"(a1), "r"(a2), "r"(a3), "r"(b0), "r"(b1));
}
__device__ __forceinline__ void mma16816h(float* c, u32 a0, u32 a1, u32 a2, u32 a3, u32 b0, u32 b1) {
    asm volatile("mma.sync.aligned.m16n8k16.row.col.f32.f16.f16.f32 "
                 "{%0,%1,%2,%3}, {%4,%5,%6,%7}, {%8,%9}, {%0,%1,%2,%3};"
                 : "+f"(c[0]), "+f"(c[1]), "+f"(c[2]), "+f"(c[3])
                 : "r"(a0), "r"(a1), "r"(a2), "r"(a3), "r"(b0), "r"(b1));
}
__device__ __forceinline__ u32 smem_u32p(const void* p) {
    u32 a;
    asm("{ .reg .u64 t; cvta.to.shared.u64 t, %1; cvt.u32.u64 %0, t; }" : "=r"(a) : "l"(p));
    return a;
}
__device__ __forceinline__ void cpasync16(u32 smaddr, const void* gptr) {
    asm volatile("cp.async.cg.shared.global [%0], [%1], 16;" :: "r"(smaddr), "l"(gptr));
}
__device__ __forceinline__ void cpasync4(u32 smaddr, const void* gptr) {
    asm volatile("cp.async.ca.shared.global [%0], [%1], 4;" :: "r"(smaddr), "l"(gptr));
}
#define CP_COMMIT() asm volatile("cp.async.commit_group;" ::: "memory")
#define CP_WAIT1()  asm volatile("cp.async.wait_group 1;" ::: "memory")
#define CP_WAIT0()  asm volatile("cp.async.wait_group 0;" ::: "memory")

// ==================== small kernels ====================
__global__ void transpose_x_kernel(const float* __restrict__ x, float* __restrict__ xt) {
    int i = blockIdx.x * blockDim.x + threadIdx.x;
    if (i >= BB * NPTS) return;
    int b = i / NPTS, n = i % NPTS;
#pragma unroll
    for (int c = 0; c < 3; c++)
        xt[i * 3 + c] = x[(b * 3 + c) * NPTS + n];
}

__global__ void sqnorm_kernel(const float* __restrict__ xt, int rs, int off, int C,
                              float* __restrict__ sq) {
    int i = blockIdx.x * blockDim.x + threadIdx.x;
    if (i >= BB * NPTS) return;
    const float* p = xt + (ll)i * rs + off;
    float s = 0.f;
    for (int c = 0; c < C; c++) { float v = p[c]; s += v * v; }
    sq[i] = s;
}

__global__ void split_kernel(const float* __restrict__ in, u32* __restrict__ out, ll n) {
    ll i = (ll)blockIdx.x * blockDim.x + threadIdx.x;
    if (i < n) out[i] = pack_hl(in[i]);
}

__global__ void split16_kernel(const float* __restrict__ in, u32* __restrict__ out, ll n2) {
    ll i = (ll)blockIdx.x * blockDim.x + threadIdx.x;
    if (i < n2) out[i] = pack_f16x2(in[2 * i], in[2 * i + 1]);
}

// ==================== SIMT SGEMM for kNN distances ====================
__global__ __launch_bounds__(256, 2)
void distgemm_kernel(const float* __restrict__ A, float* __restrict__ C, int K, int lda,
                     ll sA, const float* __restrict__ sq) {
    __shared__ float As[16][132];
    __shared__ float Bs[16][132];
    const int tid = threadIdx.x;
    const int tx = tid & 15, ty = tid >> 4;
    const int i0 = blockIdx.y * 128, j0 = blockIdx.x * 128;
    const int bz = blockIdx.z;
    const float* Ab = A + (ll)bz * sA;
    float acc[8][8];
#pragma unroll
    for (int i = 0; i < 8; i++)
#pragma unroll
        for (int j = 0; j < 8; j++) acc[i][j] = 0.f;
    for (int k0 = 0; k0 < K; k0 += 16) {
        for (int t = tid; t < 2048; t += 256) {
            int kq = t & 15, i = t >> 4;
            int gk = k0 + kq;
            As[kq][i] = (gk < K) ? Ab[(ll)(i0 + i) * lda + gk] : 0.f;
        }
        for (int t = tid; t < 2048; t += 256) {
            int kq = t & 15, j = t >> 4;
            int gk = k0 + kq;
            Bs[kq][j] = (gk < K) ? Ab[(ll)(j0 + j) * lda + gk] : 0.f;
        }
        __syncthreads();
#pragma unroll
        for (int kq = 0; kq < 16; kq++) {
            float4 a0 = *(const float4*)&As[kq][ty * 8];
            float4 a1 = *(const float4*)&As[kq][ty * 8 + 4];
            float4 b0 = *(const float4*)&Bs[kq][tx * 8];
            float4 b1 = *(const float4*)&Bs[kq][tx * 8 + 4];
            float a[8] = {a0.x, a0.y, a0.z, a0.w, a1.x, a1.y, a1.z, a1.w};
            float b[8] = {b0.x, b0.y, b0.z, b0.w, b1.x, b1.y, b1.z, b1.w};
#pragma unroll
            for (int i = 0; i < 8; i++)
#pragma unroll
                for (int j = 0; j < 8; j++) acc[i][j] += a[i] * b[j];
        }
        __syncthreads();
    }
    float* Cb = C + (ll)bz * NPTS * NPTS;
    const float* sqb = sq + (ll)bz * NPTS;
#pragma unroll
    for (int ii = 0; ii < 8; ii++) {
        int gi = i0 + ty * 8 + ii;
        float sqi = sqb[gi];
#pragma unroll
        for (int jj = 0; jj < 8; jj++) {
            int gj = j0 + tx * 8 + jj;
            Cb[(ll)gi * NPTS + gj] = sqi + sqb[gj] - 2.f * acc[ii][jj];
        }
    }
}

// ==================== top-k via 2-level radix select ====================
__global__ __launch_bounds__(256)
void topk_kernel(const float* __restrict__ dist, int* __restrict__ out) {
    __shared__ u32 hist[256];
    __shared__ u32 cum[256];
    __shared__ u32 candk[2048];
    __shared__ u32 candi[2048];
    __shared__ u32 candk2[2048];
    __shared__ u32 candi2[2048];
    __shared__ u32 ctr[2];
    __shared__ u32 selbin, selbefore;
    const int tid = threadIdx.x;
    const float* rp = dist + (ll)blockIdx.x * NPTS;
    hist[tid] = 0;
    if (tid < 2) ctr[tid] = 0;
    __syncthreads();
    u32 key[8];
#pragma unroll
    for (int j = 0; j < 8; j++) {
        u32 u = __float_as_uint(rp[tid + j * 256]);
        key[j] = (u & 0x80000000u) ? ~u : (u | 0x80000000u);
        atomicAdd(&hist[key[j] >> 24], 1u);
    }
    __syncthreads();
    cum[tid] = hist[tid];
    __syncthreads();
#pragma unroll
    for (int off = 1; off < 256; off <<= 1) {
        u32 v = (tid >= off) ? cum[tid - off] : 0u;
        __syncthreads();
        cum[tid] += v;
        __syncthreads();
    }
    {
        u32 inc = cum[tid], exc = inc - hist[tid];
        if (exc < KNN && inc >= KNN) { selbin = (u32)tid; selbefore = exc; }
    }
    __syncthreads();
    const u32 sb = selbin, before = selbefore;
    int* op = out + (ll)blockIdx.x * KNN;
#pragma unroll
    for (int j = 0; j < 8; j++) {
        u32 b = key[j] >> 24;
        int idx = tid + j * 256;
        if (b < sb) {
            u32 p = atomicAdd(&ctr[0], 1u);
            op[p] = idx;
        } else if (b == sb) {
            u32 p = atomicAdd(&ctr[1], 1u);
            candk[p] = key[j];
            candi[p] = (u32)idx;
        }
    }
    __syncthreads();
    const int cnt = (int)ctr[1];
    const u32 need1 = KNN - before;
    hist[tid] = 0;
    __syncthreads();
    for (int t = tid; t < cnt; t += 256)
        atomicAdd(&hist[(candk[t] >> 16) & 0xffu], 1u);
    __syncthreads();
    cum[tid] = hist[tid];
    __syncthreads();
#pragma unroll
    for (int off = 1; off < 256; off <<= 1) {
        u32 v = (tid >= off) ? cum[tid - off] : 0u;
        __syncthreads();
        cum[tid] += v;
        __syncthreads();
    }
    {
        u32 inc = cum[tid], exc = inc - hist[tid];
        if (exc < need1 && inc >= need1) { selbin = (u32)tid; selbefore = exc; }
    }
    if (tid == 0) { ctr[0] = 0; ctr[1] = 0; }
    __syncthreads();
    const u32 sb2 = selbin, before2 = selbefore;
    for (int t = tid; t < cnt; t += 256) {
        u32 k2 = candk[t];
        u32 b2 = (k2 >> 16) & 0xffu;
        if (b2 < sb2) {
            u32 p = atomicAdd(&ctr[0], 1u);
            op[before + p] = (int)candi[t];
        } else if (b2 == sb2) {
            u32 p = atomicAdd(&ctr[1], 1u);
            candk2[p] = k2;
            candi2[p] = candi[t];
        }
    }
    __syncthreads();
    const int need2 = (int)(KNN - before - before2);
    const int cnt2 = (int)ctr[1];
    if (tid < 32) {
        for (int s = 0; s < need2; s++) {
            u32 bk = 0xffffffffu, bi = 0xffffffffu;
            for (int t = tid; t < cnt2; t += 32) {
                u32 k2 = candk2[t], i2 = candi2[t];
                if (k2 < bk || (k2 == bk && i2 < bi)) { bk = k2; bi = i2; }
            }
#pragma unroll
            for (int off = 16; off > 0; off >>= 1) {
                u32 ok = __shfl_xor_sync(0xffffffffu, bk, off);
                u32 oi = __shfl_xor_sync(0xffffffffu, bi, off);
                if (ok < bk || (ok == bk && oi < bi)) { bk = ok; bi = oi; }
            }
            for (int t = tid; t < cnt2; t += 32) {
                if (candk2[t] == bk && candi2[t] == bi) { candk2[t] = 0xffffffffu; candi2[t] = 0xffffffffu; }
            }
            if (tid == 0) op[before + before2 + s] = (int)bi;
            __syncwarp();
        }
    }
}

// ==================== fused EdgeConv ====================
template <int CIN>
__global__ __launch_bounds__(256)
void edgeconv_kernel(const float* __restrict__ xin, int rsin, int offin,
                     const int* __restrict__ idx,
                     const float* __restrict__ w1, const float* __restrict__ bn1,
                     const float* __restrict__ w2, const float* __restrict__ bn2,
                     float* __restrict__ xout, int rsout, int offout) {
    constexpr int C2 = 2 * CIN;
    constexpr int CPAD = (CIN + 3) & ~3;
    extern __shared__ float sm[];
    float* w1s = sm;
    float* w2s = w1s + C2 * 64;
    float* es  = w2s + 4096;
    float* h1  = es + CIN * 36;
    float* red = h1 + 32 * 68;
    float* ctr = red + 256;
    int*   iks = (int*)(ctr + CPAD);

    const int tid = threadIdx.x;
    const int o = tid & 63, kg = tid >> 6;
    for (int t = tid; t < 64 * C2; t += 256) {
        int oo = t / C2, c = t - oo * C2;
        w1s[c * 64 + oo] = w1[t];
    }
    for (int t = tid; t < 4096; t += 256) {
        int oo = t >> 6, c = t & 63;
        w2s[c * 64 + oo] = w2[t];
    }
    const float s1 = bn1[o] * rsqrtf(bn1[192 + o] + 1e-5f);
    const float t1 = bn1[64 + o] - bn1[128 + o] * s1;
    const float s2 = bn2[o] * rsqrtf(bn2[192 + o] + 1e-5f);
    const float t2 = bn2[64 + o] - bn2[128 + o] * s2;
    __syncthreads();

    for (int p = blockIdx.x; p < BB * NPTS; p += gridDim.x) {
        const int b = p >> 11;
        if (tid < CIN) ctr[tid] = xin[(ll)p * rsin + offin + tid];
        if (tid < KNN) iks[tid] = idx[p * KNN + tid];
        __syncthreads();
        if (CIN % 4 == 0) {
            for (int t = tid; t < 32 * (CIN / 4); t += 256) {
                int kq = t & 31, cg = t >> 5;
                int m = iks[kq];
                float4 v = *(const float4*)&xin[(ll)(b * NPTS + m) * rsin + offin + cg * 4];
                float4 c4 = *(const float4*)&ctr[cg * 4];
                es[(cg * 4 + 0) * 36 + kq] = v.x - c4.x;
                es[(cg * 4 + 1) * 36 + kq] = v.y - c4.y;
                es[(cg * 4 + 2) * 36 + kq] = v.z - c4.z;
                es[(cg * 4 + 3) * 36 + kq] = v.w - c4.w;
            }
        } else {
            for (int t = tid; t < 32 * CIN; t += 256) {
                int kq = t & 31, c = t >> 5;
                int m = iks[kq];
                es[c * 36 + kq] = xin[(ll)(b * NPTS + m) * rsin + offin + c] - ctr[c];
            }
        }
        __syncthreads();
        float bias = 0.f;
        for (int c = 0; c < CIN; c++)
            bias += w1s[(CIN + c) * 64 + o] * ctr[c];
        float acc[8];
#pragma unroll
        for (int j = 0; j < 8; j++) acc[j] = bias;
        for (int c = 0; c < CIN; c++) {
            float w = w1s[c * 64 + o];
            float4 e0 = *(const float4*)&es[c * 36 + kg * 8];
            float4 e1 = *(const float4*)&es[c * 36 + kg * 8 + 4];
            acc[0] += w * e0.x; acc[1] += w * e0.y; acc[2] += w * e0.z; acc[3] += w * e0.w;
            acc[4] += w * e1.x; acc[5] += w * e1.y; acc[6] += w * e1.z; acc[7] += w * e1.w;
        }
#pragma unroll
        for (int j = 0; j < 8; j++) {
            float v = acc[j] * s1 + t1;
            v = v >= 0.f ? v : 0.2f * v;
            h1[(kg * 8 + j) * 68 + o] = v;
            acc[j] = 0.f;
        }
        __syncthreads();
#pragma unroll 4
        for (int c4 = 0; c4 < 16; c4++) {
            float w0 = w2s[(c4 * 4 + 0) * 64 + o];
            float w1v = w2s[(c4 * 4 + 1) * 64 + o];
            float w2v = w2s[(c4 * 4 + 2) * 64 + o];
            float w3 = w2s[(c4 * 4 + 3) * 64 + o];
#pragma unroll
            for (int j = 0; j < 8; j++) {
                float4 hv = *(const float4*)&h1[(kg * 8 + j) * 68 + c4 * 4];
                acc[j] += w0 * hv.x + w1v * hv.y + w2v * hv.z + w3 * hv.w;
            }
        }
        float mx = -3.4e38f;
#pragma unroll
        for (int j = 0; j < 8; j++) {
            float v = acc[j] * s2 + t2;
            v = v >= 0.f ? v : 0.2f * v;
            mx = fmaxf(mx, v);
        }
        red[kg * 64 + o] = mx;
        __syncthreads();
        if (kg == 0) {
            float m = fmaxf(fmaxf(red[o], red[64 + o]), fmaxf(red[128 + o], red[192 + o]));
            xout[(ll)p * rsout + offout + o] = m;
        }
        __syncthreads();
    }
}

// ==================== mma.sync GEMM (cp.async 2-stage pipeline) ====================
// DT=0: split-bf16 exact; DT=1: fp16 single-pass
// EPI: 0 pack_hl; 2 BN(gm)+lrelu fp32; 4 f16 pack; 5 dual hl+f16;
//      6 +residual(R,hl)+BN(gn) dual hl+f16; 7 lrelu+f16 pack
#define STG_W (128 * 36)
#define STG_B (2 * STG_W * 4)

__device__ __forceinline__ void stage_load(const u32* __restrict__ Ab, const u32* __restrict__ Bb,
                                           int i0, int j0, int k0,
                                           int sAm, int sAk, int sBn, int sBk,
                                           u32 aAddr, u32 bAddr, int tid) {
    if (sAk == 1) {
        for (int t = tid; t < 1024; t += 256) {
            int m = t >> 3, q = (t & 7) << 2;
            cpasync16(aAddr + (u32)(m * 36 + q) * 4, Ab + (ll)(i0 + m) * sAm + k0 + q);
        }
    } else {
        for (int t = tid; t < 4096; t += 256) {
            int m = t & 127, kk = t >> 7;
            cpasync4(aAddr + (u32)(m * 36 + kk) * 4, Ab + (ll)(i0 + m) + (ll)(k0 + kk) * sAk);
        }
    }
    if (sBk == 1) {
        for (int t = tid; t < 1024; t += 256) {
            int n = t >> 3, q = (t & 7) << 2;
            cpasync16(bAddr + (u32)(n * 36 + q) * 4, Bb + (ll)(j0 + n) * sBn + k0 + q);
        }
    } else {
        for (int t = tid; t < 4096; t += 256) {
            int n = t & 127, kk = t >> 7;
            cpasync4(bAddr + (u32)(n * 36 + kk) * 4, Bb + (ll)(j0 + n) + (ll)(k0 + kk) * sBk);
        }
    }
}

template <int EPI, int DT>
__global__ __launch_bounds__(256)
void mmamm_kernel(const u32* __restrict__ A, const u32* __restrict__ B,
                  u32* __restrict__ Co, u32* __restrict__ C2, float* __restrict__ Cf,
                  int K, int sAm, int sAk, int sBn, int sBk, int ldc,
                  ll strideA, ll strideB, ll strideC, const float* __restrict__ bn,
                  const u32* __restrict__ R) {
    extern __shared__ u32 smu[];
    const int tid = threadIdx.x, lane = tid & 31, w = tid >> 5;
    const int mw = (w & 1) * 64, nw = (w >> 1) * 32;
    const int i0 = blockIdx.y * 128, j0 = blockIdx.x * 128, bz = blockIdx.z;
    const u32* Ab = A + (ll)bz * strideA;
    const u32* Bb = B + (ll)bz * strideB;
    const int lq = lane >> 2, lr = lane & 3;
    const u32 sbase = smem_u32p(smu);

    float acc[4][4][4];
#pragma unroll
    for (int a = 0; a < 4; a++)
#pragma unroll
        for (int b = 0; b < 4; b++)
#pragma unroll
            for (int c = 0; c < 4; c++) acc[a][b][c] = 0.f;

    const int nch = K >> 5;
    stage_load(Ab, Bb, i0, j0, 0, sAm, sAk, sBn, sBk, sbase, sbase + STG_W * 4, tid);
    CP_COMMIT();
    for (int ch = 0; ch < nch; ch++) {
        const int st = ch & 1;
        if (ch + 1 < nch) {
            const int st2 = (ch + 1) & 1;
            stage_load(Ab, Bb, i0, j0, (ch + 1) << 5, sAm, sAk, sBn, sBk,
                       sbase + st2 * STG_B, sbase + st2 * STG_B + STG_W * 4, tid);
            CP_COMMIT();
            CP_WAIT1();
        } else {
            CP_WAIT0();
        }
        __syncthreads();
        u32 (*As)[36] = (u32(*)[36])(smu + st * 2 * STG_W);
        u32 (*Bs)[36] = (u32(*)[36])(smu + st * 2 * STG_W + STG_W);
#pragma unroll
        for (int ks = 0; ks < 4; ks++) {
            const int kw = ks * 8;
            if (DT == 0) {
                u32 bh[4][2], bl[4][2];
#pragma unroll
                for (int nt = 0; nt < 4; nt++) {
                    int n = nw + nt * 8 + lq;
                    u32 b0 = Bs[n][kw + lr], b1 = Bs[n][kw + 4 + lr];
                    bh[nt][0] = (b0 & 0xffffu) * 0x10001u;
                    bl[nt][0] = (b0 >> 16) * 0x10001u;
                    bh[nt][1] = (b1 & 0xffffu) * 0x10001u;
                    bl[nt][1] = (b1 >> 16) * 0x10001u;
                }
#pragma unroll
                for (int mt = 0; mt < 4; mt++) {
                    int m = mw + mt * 16 + lq;
                    u32 a0 = As[m][kw + lr], a1 = As[m + 8][kw + lr];
                    u32 a2 = As[m][kw + 4 + lr], a3 = As[m + 8][kw + 4 + lr];
#pragma unroll
                    for (int nt = 0; nt < 4; nt++) {
                        mma16816(acc[mt][nt], a0, a1, a2, a3, bh[nt][0], bh[nt][1]);
                        mma16816(acc[mt][nt], a0, a1, a2, a3, bl[nt][0], bl[nt][1]);
                    }
                }
            } else {
                u32 bq[4][2];
#pragma unroll
                for (int nt = 0; nt < 4; nt++) {
                    int n = nw + nt * 8 + lq;
                    bq[nt][0] = Bs[n][kw + lr];
                    bq[nt][1] = Bs[n][kw + 4 + lr];
                }
#pragma unroll
                for (int mt = 0; mt < 4; mt++) {
                    int m = mw + mt * 16 + lq;
                    u32 a0 = As[m][kw + lr], a1 = As[m + 8][kw + lr];
                    u32 a2 = As[m][kw + 4 + lr], a3 = As[m + 8][kw + 4 + lr];
#pragma unroll
                    for (int nt = 0; nt < 4; nt++)
                        mma16816h(acc[mt][nt], a0, a1, a2, a3, bq[nt][0], bq[nt][1]);
                }
            }
        }
        __syncthreads();
    }

#pragma unroll
    for (int mt = 0; mt < 4; mt++) {
#pragma unroll
        for (int nt = 0; nt < 4; nt++) {
            int gm0 = i0 + mw + mt * 16 + lq;
            int gn  = j0 + nw + nt * 8 + lr * 2;
#pragma unroll
            for (int half = 0; half < 2; half++) {
                int gm = gm0 + half * 8;
                float v0 = acc[mt][nt][half * 2], v1 = acc[mt][nt][half * 2 + 1];
                if (EPI == 0) {
                    uint2 pv = make_uint2(pack_hl(v0), pack_hl(v1));
                    *(uint2*)&Co[(ll)bz * strideC + (ll)gm * ldc + gn] = pv;
                } else if (EPI == 2) {
                    float g = bn[gm], be = bn[1024 + gm], mm = bn[2048 + gm], va = bn[3072 + gm];
                    float s = g * rsqrtf(va + 1e-5f);
                    float t = be - mm * s;
                    v0 = v0 * s + t; v0 = v0 >= 0.f ? v0 : 0.2f * v0;
                    v1 = v1 * s + t; v1 = v1 >= 0.f ? v1 : 0.2f * v1;
                    *(float2*)&Cf[(ll)bz * strideC + (ll)gm * ldc + gn] = make_float2(v0, v1);
                } else if (EPI == 4) {
                    Co[(ll)bz * strideC + (ll)gm * ldc + (gn >> 1)] = pack_f16x2(v0, v1);
                } else if (EPI == 5) {
                    ll idx = (ll)bz * strideC + (ll)gm * ldc + gn;
                    *(uint2*)&Co[idx] = make_uint2(pack_hl(v0), pack_hl(v1));
                    C2[(ll)bz * (strideC >> 1) + (ll)gm * (ldc >> 1) + (gn >> 1)] = pack_f16x2(v0, v1);
                } else if (EPI == 6) {
                    ll idx = (ll)bz * strideC + (ll)gm * ldc + gn;
                    uint2 rv = *(const uint2*)&R[idx];
                    float g0 = bn[gn], s0 = g0 * rsqrtf(bn[3072 + gn] + 1e-5f);
                    float t0 = bn[1024 + gn] - bn[2048 + gn] * s0;
                    float g1 = bn[gn + 1], s1 = g1 * rsqrtf(bn[3072 + gn + 1] + 1e-5f);
                    float t1 = bn[1024 + gn + 1] - bn[2048 + gn + 1] * s1;
                    v0 = (v0 + unpack_hl(rv.x)) * s0 + t0;
                    v1 = (v1 + unpack_hl(rv.y)) * s1 + t1;
                    *(uint2*)&Co[idx] = make_uint2(pack_hl(v0), pack_hl(v1));
                    C2[(ll)bz * (strideC >> 1) + (ll)gm * (ldc >> 1) + (gn >> 1)] = pack_f16x2(v0, v1);
                } else {  // EPI == 7: lrelu + f16
                    v0 = v0 >= 0.f ? v0 : 0.2f * v0;
                    v1 = v1 >= 0.f ? v1 : 0.2f * v1;
                    Co[(ll)bz * strideC + (ll)gm * ldc + (gn >> 1)] = pack_f16x2(v0, v1);
                }
            }
        }
    }
}

// ==================== softmax over packed-hl logits -> fp16x2 att ====================
__global__ __launch_bounds__(256)
void softmax_f16_kernel(u32* __restrict__ att) {
    __shared__ float sd[NPTS];
    __shared__ float red[256];
    const int tid = threadIdx.x;
    u32* p = att + (ll)blockIdx.x * NPTS;
    float mx = -3.4e38f;
    for (int t = tid; t < NPTS; t += 256) {
        float v = unpack_hl(p[t]) * 0.03125f;
        sd[t] = v;
        mx = fmaxf(mx, v);
    }
    red[tid] = mx;
    __syncthreads();
    for (int h = 128; h > 0; h >>= 1) {
        if (tid < h) red[tid] = fmaxf(red[tid], red[tid + h]);
        __syncthreads();
    }
    mx = red[0];
    __syncthreads();
    float sum = 0.f;
    for (int t = tid; t < NPTS; t += 256) {
        float e = __expf(sd[t] - mx);
        sd[t] = e;
        sum += e;
    }
    red[tid] = sum;
    __syncthreads();
    for (int h = 128; h > 0; h >>= 1) {
        if (tid < h) red[tid] += red[tid + h];
        __syncthreads();
    }
    float inv = 1.f / red[0];
    __syncthreads();
    for (int t = tid; t < NPTS / 2; t += 256)
        p[t] = pack_f16x2(sd[2 * t] * inv, sd[2 * t + 1] * inv);
}

// ==================== launcher ====================
extern "C" void kernel_launch(void* const* d_in, const int* in_sizes, int n_in,
                              void* d_out, int out_size) {
    const float* x       = (const float*)d_in[0];
    const float* ec1_w1  = (const float*)d_in[1];
    const float* ec1_bn1 = (const float*)d_in[2];
    const float* ec1_w2  = (const float*)d_in[3];
    const float* ec1_bn2 = (const float*)d_in[4];
    const float* ec2_w1  = (const float*)d_in[5];
    const float* ec2_bn1 = (const float*)d_in[6];
    const float* ec2_w2  = (const float*)d_in[7];
    const float* ec2_bn2 = (const float*)d_in[8];
    const float* ec3_w1  = (const float*)d_in[9];
    const float* ec3_bn1 = (const float*)d_in[10];
    const float* ec3_w2  = (const float*)d_in[11];
    const float* ec3_bn2 = (const float*)d_in[12];
    const float* emb_w   = (const float*)d_in[13];
    const float* q_w     = (const float*)d_in[14];
    const float* k_w     = (const float*)d_in[15];
    const float* v_w     = (const float*)d_in[16];
    const float* att_bn1 = (const float*)d_in[17];
    const float* ff_w1   = (const float*)d_in[18];
    const float* ff_w2   = (const float*)d_in[19];
    const float* att_bn2 = (const float*)d_in[20];
    const float* cb_w    = (const float*)d_in[21];
    const float* cb_bn   = (const float*)d_in[22];
    float* out = (float*)d_out;

    float *xT3, *sqn, *dist, *xcT;
    u32 *xchl, *h, *hf, *q, *kk, *v, *ffo, *embw, *qw, *kw, *vw, *f1w, *f2w, *cw;
    int* idxp;
    cudaGetSymbolAddress((void**)&xT3, g_xT3);
    cudaGetSymbolAddress((void**)&sqn, g_sqn);
    cudaGetSymbolAddress((void**)&dist, g_dist);
    cudaGetSymbolAddress((void**)&idxp, g_idx);
    cudaGetSymbolAddress((void**)&xcT, g_xcT);
    cudaGetSymbolAddress((void**)&xchl, g_xchl);
    cudaGetSymbolAddress((void**)&h, g_h);
    cudaGetSymbolAddress((void**)&hf, g_hf);
    cudaGetSymbolAddress((void**)&q, g_q);
    cudaGetSymbolAddress((void**)&kk, g_k);
    cudaGetSymbolAddress((void**)&v, g_v);
    cudaGetSymbolAddress((void**)&ffo, g_ffo);
    cudaGetSymbolAddress((void**)&embw, g_embw);
    cudaGetSymbolAddress((void**)&qw, g_qw);
    cudaGetSymbolAddress((void**)&kw, g_kw);
    cudaGetSymbolAddress((void**)&vw, g_vw);
    cudaGetSymbolAddress((void**)&f1w, g_f1w);
    cudaGetSymbolAddress((void**)&f2w, g_f2w);
    cudaGetSymbolAddress((void**)&cw, g_cw);

    const size_t sm3  = (size_t)(6 * 64 + 4096 + 3 * 36 + 32 * 68 + 256 + 4 + 32) * 4;
    const size_t sm64 = (size_t)(128 * 64 + 4096 + 64 * 36 + 32 * 68 + 256 + 64 + 32) * 4;
    cudaFuncSetAttribute((const void*)edgeconv_kernel<64>,
                         cudaFuncAttributeMaxDynamicSharedMemorySize, (int)sm64);
    const int SMTC = 2 * STG_B;  // 73728 B
    cudaFuncSetAttribute((const void*)mmamm_kernel<5, 0>, cudaFuncAttributeMaxDynamicSharedMemorySize, SMTC);
    cudaFuncSetAttribute((const void*)mmamm_kernel<4, 1>, cudaFuncAttributeMaxDynamicSharedMemorySize, SMTC);
    cudaFuncSetAttribute((const void*)mmamm_kernel<0, 1>, cudaFuncAttributeMaxDynamicSharedMemorySize, SMTC);
    cudaFuncSetAttribute((const void*)mmamm_kernel<6, 1>, cudaFuncAttributeMaxDynamicSharedMemorySize, SMTC);
    cudaFuncSetAttribute((const void*)mmamm_kernel<7, 1>, cudaFuncAttributeMaxDynamicSharedMemorySize, SMTC);
    cudaFuncSetAttribute((const void*)mmamm_kernel<2, 1>, cudaFuncAttributeMaxDynamicSharedMemorySize, SMTC);

    const int npts = BB * NPTS;
    const ll CH = (ll)NPTS * 1024;   // hl [n][1024] per-batch words (also [c][n])
    const ll HF = (ll)NPTS * 512;    // f16 [n][512] per-batch words
    const ll AT = (ll)NPTS * NPTS;
    const ll VF = (ll)1024 * 1024;   // v f16 [c][1024] per-batch words
    const ll FF = (ll)NPTS * 256;    // ffo f16 [n][256] per-batch words

    transpose_x_kernel<<<(npts + 255) / 256, 256>>>(x, xT3);

    dim3 gd(NPTS / 128, NPTS / 128, BB);
    // EdgeConv 1 (C=3)
    sqnorm_kernel<<<(npts + 255) / 256, 256>>>(xT3, 3, 0, 3, sqn);
    distgemm_kernel<<<gd, 256>>>(xT3, dist, 3, 3, (ll)NPTS * 3, sqn);
    topk_kernel<<<npts, 256>>>(dist, idxp);
    edgeconv_kernel<3><<<1024, 256, sm3>>>(xT3, 3, 0, idxp, ec1_w1, ec1_bn1, ec1_w2, ec1_bn2, xcT, 192, 0);
    // EdgeConv 2
    sqnorm_kernel<<<(npts + 255) / 256, 256>>>(xcT, 192, 0, 64, sqn);
    distgemm_kernel<<<gd, 256>>>(xcT, dist, 64, 192, (ll)NPTS * 192, sqn);
    topk_kernel<<<npts, 256>>>(dist, idxp);
    edgeconv_kernel<64><<<1024, 256, sm64>>>(xcT, 192, 0, idxp, ec2_w1, ec2_bn1, ec2_w2, ec2_bn2, xcT, 192, 64);
    // EdgeConv 3
    sqnorm_kernel<<<(npts + 255) / 256, 256>>>(xcT, 192, 64, 64, sqn);
    distgemm_kernel<<<gd, 256>>>(xcT + 64, dist, 64, 192, (ll)NPTS * 192, sqn);
    topk_kernel<<<npts, 256>>>(dist, idxp);
    edgeconv_kernel<64><<<1024, 256, sm64>>>(xcT, 192, 64, idxp, ec3_w1, ec3_bn1, ec3_w2, ec3_bn2, xcT, 192, 128);

    // pack activations (hl) + weights (emb hl; rest fp16)
    split_kernel<<<(int)(((ll)npts * 192 + 255) / 256), 256>>>(xcT, xchl, (ll)npts * 192);
    split_kernel<<<(1024 * 192 + 255) / 256, 256>>>(emb_w, embw, 1024 * 192);
    split16_kernel<<<(1024 * 512 + 255) / 256, 256>>>(q_w, qw, 1024 * 512);
    split16_kernel<<<(1024 * 512 + 255) / 256, 256>>>(k_w, kw, 1024 * 512);
    split16_kernel<<<(1024 * 512 + 255) / 256, 256>>>(v_w, vw, 1024 * 512);
    split16_kernel<<<(512 * 512 + 255) / 256, 256>>>(ff_w1, f1w, 512 * 512);
    split16_kernel<<<(1024 * 256 + 255) / 256, 256>>>(ff_w2, f2w, 1024 * 256);
    split16_kernel<<<(1024 * 512 + 255) / 256, 256>>>(cb_w, cw, 1024 * 512);

    u32* distu = (u32*)dist;
    dim3 gnm(1024 / 128, NPTS / 128, BB);  // M=2048(n), N=1024
    dim3 gmn(NPTS / 128, 1024 / 128, BB);  // M=1024,    N=2048
    dim3 ga(NPTS / 128, NPTS / 128, BB);
    dim3 gff(512 / 128, NPTS / 128, BB);   // M=2048(n), N=512
    // h_t[n][c] = xc[n] @ emb_w^T   (split-bf16; dual store hl + f16)
    mmamm_kernel<5, 0><<<gnm, 256, SMTC>>>(xchl, embw, h, hf, nullptr, 192, 192, 1, 192, 1, 1024,
                                           (ll)NPTS * 192, 0, CH, nullptr, nullptr);
    // q_t[n][o] f16, k_t[n][o] f16
    mmamm_kernel<4, 1><<<gnm, 256, SMTC>>>(hf, qw, q, nullptr, nullptr, 512, 512, 1, 512, 1, 512,
                                           HF, 0, HF, nullptr, nullptr);
    mmamm_kernel<4, 1><<<gnm, 256, SMTC>>>(hf, kw, kk, nullptr, nullptr, 512, 512, 1, 512, 1, 512,
                                           HF, 0, HF, nullptr, nullptr);
    // v[c][m] f16
    mmamm_kernel<4, 1><<<gmn, 256, SMTC>>>(vw, hf, v, nullptr, nullptr, 512, 512, 1, 512, 1, 1024,
                                           0, HF, VF, nullptr, nullptr);
    // logits[n][m] hl
    mmamm_kernel<0, 1><<<ga, 256, SMTC>>>(q, kk, distu, nullptr, nullptr, 512, 512, 1, 512, 1, NPTS,
                                          HF, HF, AT, nullptr, nullptr);
    softmax_f16_kernel<<<npts, 256>>>(distu);
    // h2_t[n][c] = BN(h_t + att @ v^T); dual hl(g_q) + f16(g_k)
    mmamm_kernel<6, 1><<<gnm, 256, SMTC>>>(distu, v, q, kk, nullptr, 1024, 2048, 1, 1024, 1, 1024,
                                           AT, VF, CH, att_bn1, h);
    // ffo_t[n][o] = lrelu(h2 @ ff_w1^T) f16
    mmamm_kernel<7, 1><<<gff, 256, SMTC>>>(kk, f1w, ffo, nullptr, nullptr, 512, 512, 1, 512, 1, 256,
                                           HF, 0, FF, nullptr, nullptr);
    // h3_t[n][c] = BN(h2_t + ffo @ ff_w2^T); dual hl(g_v) + f16(g_hf)
    mmamm_kernel<6, 1><<<gnm, 256, SMTC>>>(ffo, f2w, v, hf, nullptr, 256, 256, 1, 256, 1, 1024,
                                           FF, 0, CH, att_bn2, q);
    // out[c][n] = lrelu(BN(cb_w @ h3)) fp32
    mmamm_kernel<2, 1><<<gmn, 256, SMTC>>>(cw, hf, nullptr, nullptr, out, 512, 512, 1, 512, 1, NPTS,
                                           0, HF, CH, cb_bn, nullptr);
}

// round 14
// speedup vs baseline: 6.3860x; 1.0192x over previous
#include <cuda_runtime.h>
#include <cuda_bf16.h>
#include <cuda_fp16.h>
#include <cstdint>

#define BB 8
#define NPTS 2048
#define KNN 32
typedef long long ll;
typedef uint32_t u32;
typedef unsigned short u16;

// ==================== scratch (device globals) ====================
static __device__ float g_xT3[BB * NPTS * 3];
static __device__ float g_sqn[BB * NPTS];
static __device__ float g_dist[(ll)BB * NPTS * NPTS];   // fp32 dist; reused (as u32) for logits/att
static __device__ int   g_idx[BB * NPTS * KNN];
static __device__ float g_xcT[BB * NPTS * 192];
static __device__ u32   g_xcf[BB * NPTS * 96];          // xc f16 [n][96]
static __device__ u32   g_h [(ll)BB * NPTS * 1024];     // h_t hl [n][c]
static __device__ u32   g_hf[(ll)BB * NPTS * 512];      // h_t f16 [n][c/2]; later h3 f16
static __device__ u32   g_q [(ll)BB * NPTS * 1024];     // q_t f16 (half used); later h2 hl
static __device__ u32   g_k [(ll)BB * NPTS * 1024];     // k_t f16; later h2 f16
static __device__ u32   g_v [(ll)BB * NPTS * 1024];     // v f16 (half used); later h3 hl
static __device__ u32   g_ffo[(ll)BB * NPTS * 512];     // ffo f16 [n][o/2]
static __device__ u32   g_embw[1024 * 96];
static __device__ u32   g_qw[1024 * 512];
static __device__ u32   g_kw[1024 * 512];
static __device__ u32   g_vw[1024 * 512];
static __device__ u32   g_f1w[512 * 512];
static __device__ u32   g_f2w[1024 * 256];
static __device__ u32   g_cw[1024 * 512];

// ==================== helpers ====================
__device__ __forceinline__ u32 pack_hl(float v) {
    __nv_bfloat16 h = __float2bfloat16(v);
    float r = v - __bfloat162float(h);
    __nv_bfloat16 l = __float2bfloat16(r);
    return (u32)__bfloat16_as_ushort(h) | ((u32)__bfloat16_as_ushort(l) << 16);
}
__device__ __forceinline__ float unpack_hl(u32 u) {
    return __bfloat162float(__ushort_as_bfloat16((u16)(u & 0xffffu)))
         + __bfloat162float(__ushort_as_bfloat16((u16)(u >> 16)));
}
__device__ __forceinline__ u32 pack_f16x2(float lo, float hi) {
    __half2 hv = __floats2half2_rn(lo, hi);
    return *reinterpret_cast<u32*>(&hv);
}
__device__ __forceinline__ void mma16816h(float* c, u32 a0, u32 a1, u32 a2, u32 a3, u32 b0, u32 b1) {
    asm volatile("mma.sync.aligned.m16n8k16.row.col.f32.f16.f16.f32 "
                 "{%0,%1,%2,%3}, {%4,%5,%6,%7}, {%8,%9}, {%0,%1,%2,%3};"
                 : "+f"(c[0]), "+f"(c[1]), "+f"(c[2]), "+f"(c[3])
                 : "r"(a0), "r"(a1), "r"(a2), "r"(a3), "r"(b0), "r"(b1));
}
__device__ __forceinline__ u32 smem_u32p(const void* p) {
    u32 a;
    asm("{ .reg .u64 t; cvta.to.shared.u64 t, %1; cvt.u32.u64 %0, t; }" : "=r"(a) : "l"(p));
    return a;
}
__device__ __forceinline__ void cpasync16(u32 smaddr, const void* gptr) {
    asm volatile("cp.async.cg.shared.global [%0], [%1], 16;" :: "r"(smaddr), "l"(gptr));
}
__device__ __forceinline__ void cpasync4(u32 smaddr, const void* gptr) {
    asm volatile("cp.async.ca.shared.global [%0], [%1], 4;" :: "r"(smaddr), "l"(gptr));
}
#define CP_COMMIT() asm volatile("cp.async.commit_group;" ::: "memory")
#define CP_WAIT1()  asm volatile("cp.async.wait_group 1;" ::: "memory")
#define CP_WAIT0()  asm volatile("cp.async.wait_group 0;" ::: "memory")

// ==================== small kernels ====================
__global__ void transpose_x_kernel(const float* __restrict__ x, float* __restrict__ xt) {
    int i = blockIdx.x * blockDim.x + threadIdx.x;
    if (i >= BB * NPTS) return;
    int b = i / NPTS, n = i % NPTS;
#pragma unroll
    for (int c = 0; c < 3; c++)
        xt[i * 3 + c] = x[(b * 3 + c) * NPTS + n];
}

__global__ void sqnorm_kernel(const float* __restrict__ xt, int rs, int off, int C,
                              float* __restrict__ sq) {
    int i = blockIdx.x * blockDim.x + threadIdx.x;
    if (i >= BB * NPTS) return;
    const float* p = xt + (ll)i * rs + off;
    float s = 0.f;
    for (int c = 0; c < C; c++) { float v = p[c]; s += v * v; }
    sq[i] = s;
}

__global__ void split16_kernel(const float* __restrict__ in, u32* __restrict__ out, ll n2) {
    ll i = (ll)blockIdx.x * blockDim.x + threadIdx.x;
    if (i < n2) out[i] = pack_f16x2(in[2 * i], in[2 * i + 1]);
}

// ==================== SIMT SGEMM for kNN distances ====================
__global__ __launch_bounds__(256, 2)
void distgemm_kernel(const float* __restrict__ A, float* __restrict__ C, int K, int lda,
                     ll sA, const float* __restrict__ sq) {
    __shared__ float As[16][132];
    __shared__ float Bs[16][132];
    const int tid = threadIdx.x;
    const int tx = tid & 15, ty = tid >> 4;
    const int i0 = blockIdx.y * 128, j0 = blockIdx.x * 128;
    const int bz = blockIdx.z;
    const float* Ab = A + (ll)bz * sA;
    float acc[8][8];
#pragma unroll
    for (int i = 0; i < 8; i++)
#pragma unroll
        for (int j = 0; j < 8; j++) acc[i][j] = 0.f;
    for (int k0 = 0; k0 < K; k0 += 16) {
        for (int t = tid; t < 2048; t += 256) {
            int kq = t & 15, i = t >> 4;
            int gk = k0 + kq;
            As[kq][i] = (gk < K) ? Ab[(ll)(i0 + i) * lda + gk] : 0.f;
        }
        for (int t = tid; t < 2048; t += 256) {
            int kq = t & 15, j = t >> 4;
            int gk = k0 + kq;
            Bs[kq][j] = (gk < K) ? Ab[(ll)(j0 + j) * lda + gk] : 0.f;
        }
        __syncthreads();
#pragma unroll
        for (int kq = 0; kq < 16; kq++) {
            float4 a0 = *(const float4*)&As[kq][ty * 8];
            float4 a1 = *(const float4*)&As[kq][ty * 8 + 4];
            float4 b0 = *(const float4*)&Bs[kq][tx * 8];
            float4 b1 = *(const float4*)&Bs[kq][tx * 8 + 4];
            float a[8] = {a0.x, a0.y, a0.z, a0.w, a1.x, a1.y, a1.z, a1.w};
            float b[8] = {b0.x, b0.y, b0.z, b0.w, b1.x, b1.y, b1.z, b1.w};
#pragma unroll
            for (int i = 0; i < 8; i++)
#pragma unroll
                for (int j = 0; j < 8; j++) acc[i][j] += a[i] * b[j];
        }
        __syncthreads();
    }
    float* Cb = C + (ll)bz * NPTS * NPTS;
    const float* sqb = sq + (ll)bz * NPTS;
#pragma unroll
    for (int ii = 0; ii < 8; ii++) {
        int gi = i0 + ty * 8 + ii;
        float sqi = sqb[gi];
#pragma unroll
        for (int jj = 0; jj < 8; jj++) {
            int gj = j0 + tx * 8 + jj;
            Cb[(ll)gi * NPTS + gj] = sqi + sqb[gj] - 2.f * acc[ii][jj];
        }
    }
}

// ==================== top-k via 2-level radix select (float4 loads) ====================
__global__ __launch_bounds__(256)
void topk_kernel(const float* __restrict__ dist, int* __restrict__ out) {
    __shared__ u32 hist[256];
    __shared__ u32 cum[256];
    __shared__ u32 candk[2048];
    __shared__ u32 candi[2048];
    __shared__ u32 candk2[2048];
    __shared__ u32 candi2[2048];
    __shared__ u32 ctr[2];
    __shared__ u32 selbin, selbefore;
    const int tid = threadIdx.x;
    const float* rp = dist + (ll)blockIdx.x * NPTS;
    hist[tid] = 0;
    if (tid < 2) ctr[tid] = 0;
    __syncthreads();
    float4 f0 = *(const float4*)&rp[tid * 8];
    float4 f1 = *(const float4*)&rp[tid * 8 + 4];
    float vv[8] = {f0.x, f0.y, f0.z, f0.w, f1.x, f1.y, f1.z, f1.w};
    u32 key[8];
#pragma unroll
    for (int j = 0; j < 8; j++) {
        u32 u = __float_as_uint(vv[j]);
        key[j] = (u & 0x80000000u) ? ~u : (u | 0x80000000u);
        atomicAdd(&hist[key[j] >> 24], 1u);
    }
    __syncthreads();
    cum[tid] = hist[tid];
    __syncthreads();
#pragma unroll
    for (int off = 1; off < 256; off <<= 1) {
        u32 v = (tid >= off) ? cum[tid - off] : 0u;
        __syncthreads();
        cum[tid] += v;
        __syncthreads();
    }
    {
        u32 inc = cum[tid], exc = inc - hist[tid];
        if (exc < KNN && inc >= KNN) { selbin = (u32)tid; selbefore = exc; }
    }
    __syncthreads();
    const u32 sb = selbin, before = selbefore;
    int* op = out + (ll)blockIdx.x * KNN;
#pragma unroll
    for (int j = 0; j < 8; j++) {
        u32 b = key[j] >> 24;
        int idx = tid * 8 + j;
        if (b < sb) {
            u32 p = atomicAdd(&ctr[0], 1u);
            op[p] = idx;
        } else if (b == sb) {
            u32 p = atomicAdd(&ctr[1], 1u);
            candk[p] = key[j];
            candi[p] = (u32)idx;
        }
    }
    __syncthreads();
    const int cnt = (int)ctr[1];
    const u32 need1 = KNN - before;
    hist[tid] = 0;
    __syncthreads();
    for (int t = tid; t < cnt; t += 256)
        atomicAdd(&hist[(candk[t] >> 16) & 0xffu], 1u);
    __syncthreads();
    cum[tid] = hist[tid];
    __syncthreads();
#pragma unroll
    for (int off = 1; off < 256; off <<= 1) {
        u32 v = (tid >= off) ? cum[tid - off] : 0u;
        __syncthreads();
        cum[tid] += v;
        __syncthreads();
    }
    {
        u32 inc = cum[tid], exc = inc - hist[tid];
        if (exc < need1 && inc >= need1) { selbin = (u32)tid; selbefore = exc; }
    }
    if (tid == 0) { ctr[0] = 0; ctr[1] = 0; }
    __syncthreads();
    const u32 sb2 = selbin, before2 = selbefore;
    for (int t = tid; t < cnt; t += 256) {
        u32 k2 = candk[t];
        u32 b2 = (k2 >> 16) & 0xffu;
        if (b2 < sb2) {
            u32 p = atomicAdd(&ctr[0], 1u);
            op[before + p] = (int)candi[t];
        } else if (b2 == sb2) {
            u32 p = atomicAdd(&ctr[1], 1u);
            candk2[p] = k2;
            candi2[p] = candi[t];
        }
    }
    __syncthreads();
    const int need2 = (int)(KNN - before - before2);
    const int cnt2 = (int)ctr[1];
    if (tid < 32) {
        for (int s = 0; s < need2; s++) {
            u32 bk = 0xffffffffu, bi = 0xffffffffu;
            for (int t = tid; t < cnt2; t += 32) {
                u32 k2 = candk2[t], i2 = candi2[t];
                if (k2 < bk || (k2 == bk && i2 < bi)) { bk = k2; bi = i2; }
            }
#pragma unroll
            for (int off = 16; off > 0; off >>= 1) {
                u32 ok = __shfl_xor_sync(0xffffffffu, bk, off);
                u32 oi = __shfl_xor_sync(0xffffffffu, bi, off);
                if (ok < bk || (ok == bk && oi < bi)) { bk = ok; bi = oi; }
            }
            for (int t = tid; t < cnt2; t += 32) {
                if (candk2[t] == bk && candi2[t] == bi) { candk2[t] = 0xffffffffu; candi2[t] = 0xffffffffu; }
            }
            if (tid == 0) op[before + before2 + s] = (int)bi;
            __syncwarp();
        }
    }
}

// ==================== fused EdgeConv: 2 points per 512-thread CTA ====================
template <int CIN>
__global__ __launch_bounds__(512)
void edgeconv_kernel(const float* __restrict__ xin, int rsin, int offin,
                     const int* __restrict__ idx,
                     const float* __restrict__ w1, const float* __restrict__ bn1,
                     const float* __restrict__ w2, const float* __restrict__ bn2,
                     float* __restrict__ xout, int rsout, int offout) {
    constexpr int C2 = 2 * CIN;
    constexpr int CPAD = (CIN + 3) & ~3;
    constexpr int ESZ = CIN * 36;
    constexpr int HSZ = 32 * 68;
    constexpr int HALFSZ = ESZ + HSZ + 256 + CPAD + 32;
    extern __shared__ float sm[];
    float* w1s = sm;                          // C2*64
    float* w2s = w1s + C2 * 64;               // 4096
    const int tid = threadIdx.x;
    const int half = tid >> 8, stid = tid & 255;
    float* es  = w2s + 4096 + half * HALFSZ;
    float* h1  = es + ESZ;
    float* red = h1 + HSZ;
    float* ctr = red + 256;
    int*   iks = (int*)(ctr + CPAD);

    const int o = stid & 63, kg = stid >> 6;
    for (int t = tid; t < 64 * C2; t += 512) {
        int oo = t / C2, c = t - oo * C2;
        w1s[c * 64 + oo] = w1[t];
    }
    for (int t = tid; t < 4096; t += 512) {
        int oo = t >> 6, c = t & 63;
        w2s[c * 64 + oo] = w2[t];
    }
    const float s1 = bn1[o] * rsqrtf(bn1[192 + o] + 1e-5f);
    const float t1 = bn1[64 + o] - bn1[128 + o] * s1;
    const float s2 = bn2[o] * rsqrtf(bn2[192 + o] + 1e-5f);
    const float t2 = bn2[64 + o] - bn2[128 + o] * s2;
    __syncthreads();

    for (int pp = blockIdx.x; pp < BB * NPTS / 2; pp += gridDim.x) {
        const int p = pp * 2 + half;
        const int b = p >> 11;
        if (stid < CIN) ctr[stid] = xin[(ll)p * rsin + offin + stid];
        if (stid < KNN) iks[stid] = idx[p * KNN + stid];
        __syncthreads();
        if (CIN % 4 == 0) {
            for (int t = stid; t < 32 * (CIN / 4); t += 256) {
                int kq = t & 31, cg = t >> 5;
                int m = iks[kq];
                float4 v = *(const float4*)&xin[(ll)(b * NPTS + m) * rsin + offin + cg * 4];
                float4 c4 = *(const float4*)&ctr[cg * 4];
                es[(cg * 4 + 0) * 36 + kq] = v.x - c4.x;
                es[(cg * 4 + 1) * 36 + kq] = v.y - c4.y;
                es[(cg * 4 + 2) * 36 + kq] = v.z - c4.z;
                es[(cg * 4 + 3) * 36 + kq] = v.w - c4.w;
            }
        } else {
            for (int t = stid; t < 32 * CIN; t += 256) {
                int kq = t & 31, c = t >> 5;
                int m = iks[kq];
                es[c * 36 + kq] = xin[(ll)(b * NPTS + m) * rsin + offin + c] - ctr[c];
            }
        }
        __syncthreads();
        float bias = 0.f;
        for (int c = 0; c < CIN; c++)
            bias += w1s[(CIN + c) * 64 + o] * ctr[c];
        float acc[8];
#pragma unroll
        for (int j = 0; j < 8; j++) acc[j] = bias;
        for (int c = 0; c < CIN; c++) {
            float w = w1s[c * 64 + o];
            float4 e0 = *(const float4*)&es[c * 36 + kg * 8];
            float4 e1 = *(const float4*)&es[c * 36 + kg * 8 + 4];
            acc[0] += w * e0.x; acc[1] += w * e0.y; acc[2] += w * e0.z; acc[3] += w * e0.w;
            acc[4] += w * e1.x; acc[5] += w * e1.y; acc[6] += w * e1.z; acc[7] += w * e1.w;
        }
#pragma unroll
        for (int j = 0; j < 8; j++) {
            float v = acc[j] * s1 + t1;
            v = v >= 0.f ? v : 0.2f * v;
            h1[(kg * 8 + j) * 68 + o] = v;
            acc[j] = 0.f;
        }
        __syncthreads();
#pragma unroll 4
        for (int c4 = 0; c4 < 16; c4++) {
            float w0 = w2s[(c4 * 4 + 0) * 64 + o];
            float w1v = w2s[(c4 * 4 + 1) * 64 + o];
            float w2v = w2s[(c4 * 4 + 2) * 64 + o];
            float w3 = w2s[(c4 * 4 + 3) * 64 + o];
#pragma unroll
            for (int j = 0; j < 8; j++) {
                float4 hv = *(const float4*)&h1[(kg * 8 + j) * 68 + c4 * 4];
                acc[j] += w0 * hv.x + w1v * hv.y + w2v * hv.z + w3 * hv.w;
            }
        }
        float mx = -3.4e38f;
#pragma unroll
        for (int j = 0; j < 8; j++) {
            float v = acc[j] * s2 + t2;
            v = v >= 0.f ? v : 0.2f * v;
            mx = fmaxf(mx, v);
        }
        red[kg * 64 + o] = mx;
        __syncthreads();
        if (kg == 0) {
            float m = fmaxf(fmaxf(red[o], red[64 + o]), fmaxf(red[128 + o], red[192 + o]));
            xout[(ll)p * rsout + offout + o] = m;
        }
        __syncthreads();
    }
}

// ==================== mma.sync fp16 GEMM (cp.async 2-stage pipeline) ====================
// EPI: 2 BN(gm)+lrelu fp32; 4 f16 pack; 5 dual hl+f16; 6 +residual(R,hl)+BN(gn) dual; 7 lrelu+f16
#define STG_W (128 * 36)
#define STG_B (2 * STG_W * 4)

__device__ __forceinline__ void stage_load(const u32* __restrict__ Ab, const u32* __restrict__ Bb,
                                           int i0, int j0, int k0,
                                           int sAm, int sAk, int sBn, int sBk,
                                           u32 aAddr, u32 bAddr, int tid) {
    if (sAk == 1) {
        for (int t = tid; t < 1024; t += 256) {
            int m = t >> 3, q = (t & 7) << 2;
            cpasync16(aAddr + (u32)(m * 36 + q) * 4, Ab + (ll)(i0 + m) * sAm + k0 + q);
        }
    } else {
        for (int t = tid; t < 4096; t += 256) {
            int m = t & 127, kk = t >> 7;
            cpasync4(aAddr + (u32)(m * 36 + kk) * 4, Ab + (ll)(i0 + m) + (ll)(k0 + kk) * sAk);
        }
    }
    if (sBk == 1) {
        for (int t = tid; t < 1024; t += 256) {
            int n = t >> 3, q = (t & 7) << 2;
            cpasync16(bAddr + (u32)(n * 36 + q) * 4, Bb + (ll)(j0 + n) * sBn + k0 + q);
        }
    } else {
        for (int t = tid; t < 4096; t += 256) {
            int n = t & 127, kk = t >> 7;
            cpasync4(bAddr + (u32)(n * 36 + kk) * 4, Bb + (ll)(j0 + n) + (ll)(k0 + kk) * sBk);
        }
    }
}

template <int EPI>
__global__ __launch_bounds__(256)
void mmamm_kernel(const u32* __restrict__ A, const u32* __restrict__ B,
                  u32* __restrict__ Co, u32* __restrict__ C2, float* __restrict__ Cf,
                  int K, int sAm, int sAk, int sBn, int sBk, int ldc,
                  ll strideA, ll strideB, ll strideC, const float* __restrict__ bn,
                  const u32* __restrict__ R) {
    extern __shared__ u32 smu[];
    const int tid = threadIdx.x, lane = tid & 31, w = tid >> 5;
    const int mw = (w & 1) * 64, nw = (w >> 1) * 32;
    const int i0 = blockIdx.y * 128, j0 = blockIdx.x * 128, bz = blockIdx.z;
    const u32* Ab = A + (ll)bz * strideA;
    const u32* Bb = B + (ll)bz * strideB;
    const int lq = lane >> 2, lr = lane & 3;
    const u32 sbase = smem_u32p(smu);

    float acc[4][4][4];
#pragma unroll
    for (int a = 0; a < 4; a++)
#pragma unroll
        for (int b = 0; b < 4; b++)
#pragma unroll
            for (int c = 0; c < 4; c++) acc[a][b][c] = 0.f;

    const int nch = K >> 5;
    stage_load(Ab, Bb, i0, j0, 0, sAm, sAk, sBn, sBk, sbase, sbase + STG_W * 4, tid);
    CP_COMMIT();
    for (int ch = 0; ch < nch; ch++) {
        const int st = ch & 1;
        if (ch + 1 < nch) {
            const int st2 = (ch + 1) & 1;
            stage_load(Ab, Bb, i0, j0, (ch + 1) << 5, sAm, sAk, sBn, sBk,
                       sbase + st2 * STG_B, sbase + st2 * STG_B + STG_W * 4, tid);
            CP_COMMIT();
            CP_WAIT1();
        } else {
            CP_WAIT0();
        }
        __syncthreads();
        u32 (*As)[36] = (u32(*)[36])(smu + st * 2 * STG_W);
        u32 (*Bs)[36] = (u32(*)[36])(smu + st * 2 * STG_W + STG_W);
#pragma unroll
        for (int ks = 0; ks < 4; ks++) {
            const int kw = ks * 8;
            u32 bq[4][2];
#pragma unroll
            for (int nt = 0; nt < 4; nt++) {
                int n = nw + nt * 8 + lq;
                bq[nt][0] = Bs[n][kw + lr];
                bq[nt][1] = Bs[n][kw + 4 + lr];
            }
#pragma unroll
            for (int mt = 0; mt < 4; mt++) {
                int m = mw + mt * 16 + lq;
                u32 a0 = As[m][kw + lr], a1 = As[m + 8][kw + lr];
                u32 a2 = As[m][kw + 4 + lr], a3 = As[m + 8][kw + 4 + lr];
#pragma unroll
                for (int nt = 0; nt < 4; nt++)
                    mma16816h(acc[mt][nt], a0, a1, a2, a3, bq[nt][0], bq[nt][1]);
            }
        }
        __syncthreads();
    }

#pragma unroll
    for (int mt = 0; mt < 4; mt++) {
#pragma unroll
        for (int nt = 0; nt < 4; nt++) {
            int gm0 = i0 + mw + mt * 16 + lq;
            int gn  = j0 + nw + nt * 8 + lr * 2;
#pragma unroll
            for (int half = 0; half < 2; half++) {
                int gm = gm0 + half * 8;
                float v0 = acc[mt][nt][half * 2], v1 = acc[mt][nt][half * 2 + 1];
                if (EPI == 2) {
                    float g = bn[gm], be = bn[1024 + gm], mm = bn[2048 + gm], va = bn[3072 + gm];
                    float s = g * rsqrtf(va + 1e-5f);
                    float t = be - mm * s;
                    v0 = v0 * s + t; v0 = v0 >= 0.f ? v0 : 0.2f * v0;
                    v1 = v1 * s + t; v1 = v1 >= 0.f ? v1 : 0.2f * v1;
                    *(float2*)&Cf[(ll)bz * strideC + (ll)gm * ldc + gn] = make_float2(v0, v1);
                } else if (EPI == 4) {
                    Co[(ll)bz * strideC + (ll)gm * ldc + (gn >> 1)] = pack_f16x2(v0, v1);
                } else if (EPI == 5) {
                    ll idx = (ll)bz * strideC + (ll)gm * ldc + gn;
                    *(uint2*)&Co[idx] = make_uint2(pack_hl(v0), pack_hl(v1));
                    C2[(ll)bz * (strideC >> 1) + (ll)gm * (ldc >> 1) + (gn >> 1)] = pack_f16x2(v0, v1);
                } else if (EPI == 6) {
                    ll idx = (ll)bz * strideC + (ll)gm * ldc + gn;
                    uint2 rv = *(const uint2*)&R[idx];
                    float g0 = bn[gn], s0 = g0 * rsqrtf(bn[3072 + gn] + 1e-5f);
                    float t0 = bn[1024 + gn] - bn[2048 + gn] * s0;
                    float g1 = bn[gn + 1], s1 = g1 * rsqrtf(bn[3072 + gn + 1] + 1e-5f);
                    float t1 = bn[1024 + gn + 1] - bn[2048 + gn + 1] * s1;
                    v0 = (v0 + unpack_hl(rv.x)) * s0 + t0;
                    v1 = (v1 + unpack_hl(rv.y)) * s1 + t1;
                    *(uint2*)&Co[idx] = make_uint2(pack_hl(v0), pack_hl(v1));
                    C2[(ll)bz * (strideC >> 1) + (ll)gm * (ldc >> 1) + (gn >> 1)] = pack_f16x2(v0, v1);
                } else {  // EPI == 7
                    v0 = v0 >= 0.f ? v0 : 0.2f * v0;
                    v1 = v1 >= 0.f ? v1 : 0.2f * v1;
                    Co[(ll)bz * strideC + (ll)gm * ldc + (gn >> 1)] = pack_f16x2(v0, v1);
                }
            }
        }
    }
}

// ==================== softmax over f16 logits -> f16 att ====================
__global__ __launch_bounds__(256)
void softmax_f16_kernel(u32* __restrict__ att) {
    __shared__ float sd[NPTS];
    __shared__ float red[256];
    const int tid = threadIdx.x;
    u32* p = att + (ll)blockIdx.x * NPTS;
    float mx = -3.4e38f;
    for (int t = tid; t < NPTS / 2; t += 256) {
        __half2 hv = *reinterpret_cast<__half2*>(&p[t]);
        float v0 = __low2float(hv) * 0.03125f;
        float v1 = __high2float(hv) * 0.03125f;
        sd[2 * t] = v0;
        sd[2 * t + 1] = v1;
        mx = fmaxf(mx, fmaxf(v0, v1));
    }
    red[tid] = mx;
    __syncthreads();
    for (int h = 128; h > 0; h >>= 1) {
        if (tid < h) red[tid] = fmaxf(red[tid], red[tid + h]);
        __syncthreads();
    }
    mx = red[0];
    __syncthreads();
    float sum = 0.f;
    for (int t = tid; t < NPTS; t += 256) {
        float e = __expf(sd[t] - mx);
        sd[t] = e;
        sum += e;
    }
    red[tid] = sum;
    __syncthreads();
    for (int h = 128; h > 0; h >>= 1) {
        if (tid < h) red[tid] += red[tid + h];
        __syncthreads();
    }
    float inv = 1.f / red[0];
    __syncthreads();
    for (int t = tid; t < NPTS / 2; t += 256)
        p[t] = pack_f16x2(sd[2 * t] * inv, sd[2 * t + 1] * inv);
}

// ==================== launcher ====================
extern "C" void kernel_launch(void* const* d_in, const int* in_sizes, int n_in,
                              void* d_out, int out_size) {
    const float* x       = (const float*)d_in[0];
    const float* ec1_w1  = (const float*)d_in[1];
    const float* ec1_bn1 = (const float*)d_in[2];
    const float* ec1_w2  = (const float*)d_in[3];
    const float* ec1_bn2 = (const float*)d_in[4];
    const float* ec2_w1  = (const float*)d_in[5];
    const float* ec2_bn1 = (const float*)d_in[6];
    const float* ec2_w2  = (const float*)d_in[7];
    const float* ec2_bn2 = (const float*)d_in[8];
    const float* ec3_w1  = (const float*)d_in[9];
    const float* ec3_bn1 = (const float*)d_in[10];
    const float* ec3_w2  = (const float*)d_in[11];
    const float* ec3_bn2 = (const float*)d_in[12];
    const float* emb_w   = (const float*)d_in[13];
    const float* q_w     = (const float*)d_in[14];
    const float* k_w     = (const float*)d_in[15];
    const float* v_w     = (const float*)d_in[16];
    const float* att_bn1 = (const float*)d_in[17];
    const float* ff_w1   = (const float*)d_in[18];
    const float* ff_w2   = (const float*)d_in[19];
    const float* att_bn2 = (const float*)d_in[20];
    const float* cb_w    = (const float*)d_in[21];
    const float* cb_bn   = (const float*)d_in[22];
    float* out = (float*)d_out;

    float *xT3, *sqn, *dist, *xcT;
    u32 *xcf, *h, *hf, *q, *kk, *v, *ffo, *embw, *qw, *kw, *vw, *f1w, *f2w, *cw;
    int* idxp;
    cudaGetSymbolAddress((void**)&xT3, g_xT3);
    cudaGetSymbolAddress((void**)&sqn, g_sqn);
    cudaGetSymbolAddress((void**)&dist, g_dist);
    cudaGetSymbolAddress((void**)&idxp, g_idx);
    cudaGetSymbolAddress((void**)&xcT, g_xcT);
    cudaGetSymbolAddress((void**)&xcf, g_xcf);
    cudaGetSymbolAddress((void**)&h, g_h);
    cudaGetSymbolAddress((void**)&hf, g_hf);
    cudaGetSymbolAddress((void**)&q, g_q);
    cudaGetSymbolAddress((void**)&kk, g_k);
    cudaGetSymbolAddress((void**)&v, g_v);
    cudaGetSymbolAddress((void**)&ffo, g_ffo);
    cudaGetSymbolAddress((void**)&embw, g_embw);
    cudaGetSymbolAddress((void**)&qw, g_qw);
    cudaGetSymbolAddress((void**)&kw, g_kw);
    cudaGetSymbolAddress((void**)&vw, g_vw);
    cudaGetSymbolAddress((void**)&f1w, g_f1w);
    cudaGetSymbolAddress((void**)&f2w, g_f2w);
    cudaGetSymbolAddress((void**)&cw, g_cw);

    const size_t sm3  = (size_t)(6 * 64 + 4096 + 2 * (3 * 36 + 32 * 68 + 256 + 4 + 32)) * 4;
    const size_t sm64 = (size_t)(128 * 64 + 4096 + 2 * (64 * 36 + 32 * 68 + 256 + 64 + 32)) * 4;
    cudaFuncSetAttribute((const void*)edgeconv_kernel<64>,
                         cudaFuncAttributeMaxDynamicSharedMemorySize, (int)sm64);
    const int SMTC = 2 * STG_B;  // 73728 B
    cudaFuncSetAttribute((const void*)mmamm_kernel<2>, cudaFuncAttributeMaxDynamicSharedMemorySize, SMTC);
    cudaFuncSetAttribute((const void*)mmamm_kernel<4>, cudaFuncAttributeMaxDynamicSharedMemorySize, SMTC);
    cudaFuncSetAttribute((const void*)mmamm_kernel<5>, cudaFuncAttributeMaxDynamicSharedMemorySize, SMTC);
    cudaFuncSetAttribute((const void*)mmamm_kernel<6>, cudaFuncAttributeMaxDynamicSharedMemorySize, SMTC);
    cudaFuncSetAttribute((const void*)mmamm_kernel<7>, cudaFuncAttributeMaxDynamicSharedMemorySize, SMTC);

    const int npts = BB * NPTS;
    const ll CH = (ll)NPTS * 1024;
    const ll HF = (ll)NPTS * 512;
    const ll AT = (ll)NPTS * NPTS;
    const ll VF = (ll)1024 * 1024;
    const ll FF = (ll)NPTS * 256;

    transpose_x_kernel<<<(npts + 255) / 256, 256>>>(x, xT3);

    dim3 gd(NPTS / 128, NPTS / 128, BB);
    // EdgeConv 1 (C=3)
    sqnorm_kernel<<<(npts + 255) / 256, 256>>>(xT3, 3, 0, 3, sqn);
    distgemm_kernel<<<gd, 256>>>(xT3, dist, 3, 3, (ll)NPTS * 3, sqn);
    topk_kernel<<<npts, 256>>>(dist, idxp);
    edgeconv_kernel<3><<<512, 512, sm3>>>(xT3, 3, 0, idxp, ec1_w1, ec1_bn1, ec1_w2, ec1_bn2, xcT, 192, 0);
    // EdgeConv 2
    sqnorm_kernel<<<(npts + 255) / 256, 256>>>(xcT, 192, 0, 64, sqn);
    distgemm_kernel<<<gd, 256>>>(xcT, dist, 64, 192, (ll)NPTS * 192, sqn);
    topk_kernel<<<npts, 256>>>(dist, idxp);
    edgeconv_kernel<64><<<512, 512, sm64>>>(xcT, 192, 0, idxp, ec2_w1, ec2_bn1, ec2_w2, ec2_bn2, xcT, 192, 64);
    // EdgeConv 3
    sqnorm_kernel<<<(npts + 255) / 256, 256>>>(xcT, 192, 64, 64, sqn);
    distgemm_kernel<<<gd, 256>>>(xcT + 64, dist, 64, 192, (ll)NPTS * 192, sqn);
    topk_kernel<<<npts, 256>>>(dist, idxp);
    edgeconv_kernel<64><<<512, 512, sm64>>>(xcT, 192, 64, idxp, ec3_w1, ec3_bn1, ec3_w2, ec3_bn2, xcT, 192, 128);

    // pack activations + all weights to fp16
    split16_kernel<<<(int)(((ll)npts * 96 + 255) / 256), 256>>>(xcT, xcf, (ll)npts * 96);
    split16_kernel<<<(1024 * 96 + 255) / 256, 256>>>(emb_w, embw, 1024 * 96);
    split16_kernel<<<(1024 * 512 + 255) / 256, 256>>>(q_w, qw, 1024 * 512);
    split16_kernel<<<(1024 * 512 + 255) / 256, 256>>>(k_w, kw, 1024 * 512);
    split16_kernel<<<(1024 * 512 + 255) / 256, 256>>>(v_w, vw, 1024 * 512);
    split16_kernel<<<(512 * 512 + 255) / 256, 256>>>(ff_w1, f1w, 512 * 512);
    split16_kernel<<<(1024 * 256 + 255) / 256, 256>>>(ff_w2, f2w, 1024 * 256);
    split16_kernel<<<(1024 * 512 + 255) / 256, 256>>>(cb_w, cw, 1024 * 512);

    u32* distu = (u32*)dist;
    dim3 gnm(1024 / 128, NPTS / 128, BB);  // M=2048(n), N=1024
    dim3 gmn(NPTS / 128, 1024 / 128, BB);  // M=1024,    N=2048
    dim3 ga(NPTS / 128, NPTS / 128, BB);
    dim3 gff(512 / 128, NPTS / 128, BB);   // M=2048(n), N=512
    // h_t[n][c] = xc[n] @ emb_w^T  (fp16; dual store hl + f16)
    mmamm_kernel<5><<<gnm, 256, SMTC>>>(xcf, embw, h, hf, nullptr, 96, 96, 1, 96, 1, 1024,
                                        (ll)NPTS * 96, 0, CH, nullptr, nullptr);
    // q_t, k_t f16
    mmamm_kernel<4><<<gnm, 256, SMTC>>>(hf, qw, q, nullptr, nullptr, 512, 512, 1, 512, 1, 512,
                                        HF, 0, HF, nullptr, nullptr);
    mmamm_kernel<4><<<gnm, 256, SMTC>>>(hf, kw, kk, nullptr, nullptr, 512, 512, 1, 512, 1, 512,
                                        HF, 0, HF, nullptr, nullptr);
    // v[c][m] f16
    mmamm_kernel<4><<<gmn, 256, SMTC>>>(vw, hf, v, nullptr, nullptr, 512, 512, 1, 512, 1, 1024,
                                        0, HF, VF, nullptr, nullptr);
    // logits[n][m] f16
    mmamm_kernel<4><<<ga, 256, SMTC>>>(q, kk, distu, nullptr, nullptr, 512, 512, 1, 512, 1, NPTS,
                                       HF, HF, AT, nullptr, nullptr);
    softmax_f16_kernel<<<npts, 256>>>(distu);
    // h2_t[n][c] = BN(h_t + att @ v^T); dual hl(g_q) + f16(g_k)
    mmamm_kernel<6><<<gnm, 256, SMTC>>>(distu, v, q, kk, nullptr, 1024, 2048, 1, 1024, 1, 1024,
                                        AT, VF, CH, att_bn1, h);
    // ffo_t[n][o] = lrelu(h2 @ ff_w1^T) f16
    mmamm_kernel<7><<<gff, 256, SMTC>>>(kk, f1w, ffo, nullptr, nullptr, 512, 512, 1, 512, 1, 256,
                                        HF, 0, FF, nullptr, nullptr);
    // h3_t[n][c] = BN(h2_t + ffo @ ff_w2^T); dual hl(g_v) + f16(g_hf)
    mmamm_kernel<6><<<gnm, 256, SMTC>>>(ffo, f2w, v, hf, nullptr, 256, 256, 1, 256, 1, 1024,
                                        FF, 0, CH, att_bn2, q);
    // out[c][n] = lrelu(BN(cb_w @ h3)) fp32
    mmamm_kernel<2><<<gmn, 256, SMTC>>>(cw, hf, nullptr, nullptr, out, 512, 512, 1, 512, 1, NPTS,
                                        0, HF, CH, cb_bn, nullptr);
}

// round 15
// speedup vs baseline: 6.5776x; 1.0300x over previous
#include <cuda_runtime.h>
#include <cuda_bf16.h>
#include <cuda_fp16.h>
#include <cstdint>

#define BB 8
#define NPTS 2048
#define KNN 32
typedef long long ll;
typedef uint32_t u32;
typedef unsigned short u16;

// ==================== scratch (device globals) ====================
static __device__ float g_xT3[BB * NPTS * 3];
static __device__ float g_sqn[BB * NPTS];
static __device__ float g_dist[(ll)BB * NPTS * NPTS];   // fp32 dist; reused (as u32) for logits/att
static __device__ int   g_idx[BB * NPTS * KNN];
static __device__ float g_xcT[BB * NPTS * 192];
static __device__ u32   g_xcf[BB * NPTS * 96];          // xc f16 [n][96]
static __device__ u32   g_h [(ll)BB * NPTS * 1024];     // h_t hl [n][c]
static __device__ u32   g_hf[(ll)BB * NPTS * 512];      // h_t f16 [n][c/2]; later h3 f16
static __device__ u32   g_q [(ll)BB * NPTS * 1024];     // q_t f16 (half used); later h2 hl
static __device__ u32   g_k [(ll)BB * NPTS * 1024];     // k_t f16; later h2 f16
static __device__ u32   g_v [(ll)BB * NPTS * 1024];     // v f16 (half used); later h3 hl
static __device__ u32   g_ffo[(ll)BB * NPTS * 512];     // ffo f16 [n][o/2]
static __device__ u32   g_embw[1024 * 96];
static __device__ u32   g_qw[1024 * 512];
static __device__ u32   g_kw[1024 * 512];
static __device__ u32   g_vw[1024 * 512];
static __device__ u32   g_f1w[512 * 512];
static __device__ u32   g_f2w[1024 * 256];
static __device__ u32   g_cw[1024 * 512];

// ==================== helpers ====================
__device__ __forceinline__ u32 pack_hl(float v) {
    __nv_bfloat16 h = __float2bfloat16(v);
    float r = v - __bfloat162float(h);
    __nv_bfloat16 l = __float2bfloat16(r);
    return (u32)__bfloat16_as_ushort(h) | ((u32)__bfloat16_as_ushort(l) << 16);
}
__device__ __forceinline__ float unpack_hl(u32 u) {
    return __bfloat162float(__ushort_as_bfloat16((u16)(u & 0xffffu)))
         + __bfloat162float(__ushort_as_bfloat16((u16)(u >> 16)));
}
__device__ __forceinline__ u32 pack_f16x2(float lo, float hi) {
    __half2 hv = __floats2half2_rn(lo, hi);
    return *reinterpret_cast<u32*>(&hv);
}
__device__ __forceinline__ void mma16816h(float* c, u32 a0, u32 a1, u32 a2, u32 a3, u32 b0, u32 b1) {
    asm volatile("mma.sync.aligned.m16n8k16.row.col.f32.f16.f16.f32 "
                 "{%0,%1,%2,%3}, {%4,%5,%6,%7}, {%8,%9}, {%0,%1,%2,%3};"
                 : "+f"(c[0]), "+f"(c[1]), "+f"(c[2]), "+f"(c[3])
                 : "r"(a0), "r"(a1), "r"(a2), "r"(a3), "r"(b0), "r"(b1));
}
__device__ __forceinline__ void ldsm_x4(u32& r0, u32& r1, u32& r2, u32& r3, u32 addr) {
    asm volatile("ldmatrix.sync.aligned.m8n8.x4.shared.b16 {%0,%1,%2,%3}, [%4];"
                 : "=r"(r0), "=r"(r1), "=r"(r2), "=r"(r3) : "r"(addr));
}
__device__ __forceinline__ u32 smem_u32p(const void* p) {
    u32 a;
    asm("{ .reg .u64 t; cvta.to.shared.u64 t, %1; cvt.u32.u64 %0, t; }" : "=r"(a) : "l"(p));
    return a;
}
__device__ __forceinline__ void cpasync16(u32 smaddr, const void* gptr) {
    asm volatile("cp.async.cg.shared.global [%0], [%1], 16;" :: "r"(smaddr), "l"(gptr));
}
__device__ __forceinline__ void cpasync4(u32 smaddr, const void* gptr) {
    asm volatile("cp.async.ca.shared.global [%0], [%1], 4;" :: "r"(smaddr), "l"(gptr));
}
#define CP_COMMIT() asm volatile("cp.async.commit_group;" ::: "memory")
#define CP_WAIT1()  asm volatile("cp.async.wait_group 1;" ::: "memory")
#define CP_WAIT0()  asm volatile("cp.async.wait_group 0;" ::: "memory")

// ==================== small kernels ====================
__global__ void transpose_x_kernel(const float* __restrict__ x, float* __restrict__ xt) {
    int i = blockIdx.x * blockDim.x + threadIdx.x;
    if (i >= BB * NPTS) return;
    int b = i / NPTS, n = i % NPTS;
#pragma unroll
    for (int c = 0; c < 3; c++)
        xt[i * 3 + c] = x[(b * 3 + c) * NPTS + n];
}

__global__ void sqnorm_kernel(const float* __restrict__ xt, int rs, int off, int C,
                              float* __restrict__ sq) {
    int i = blockIdx.x * blockDim.x + threadIdx.x;
    if (i >= BB * NPTS) return;
    const float* p = xt + (ll)i * rs + off;
    float s = 0.f;
    for (int c = 0; c < C; c++) { float v = p[c]; s += v * v; }
    sq[i] = s;
}

__global__ void split16_kernel(const float* __restrict__ in, u32* __restrict__ out, ll n2) {
    ll i = (ll)blockIdx.x * blockDim.x + threadIdx.x;
    if (i < n2) out[i] = pack_f16x2(in[2 * i], in[2 * i + 1]);
}

// ==================== SIMT SGEMM for kNN distances ====================
__global__ __launch_bounds__(256, 2)
void distgemm_kernel(const float* __restrict__ A, float* __restrict__ C, int K, int lda,
                     ll sA, const float* __restrict__ sq) {
    __shared__ float As[16][132];
    __shared__ float Bs[16][132];
    const int tid = threadIdx.x;
    const int tx = tid & 15, ty = tid >> 4;
    const int i0 = blockIdx.y * 128, j0 = blockIdx.x * 128;
    const int bz = blockIdx.z;
    const float* Ab = A + (ll)bz * sA;
    float acc[8][8];
#pragma unroll
    for (int i = 0; i < 8; i++)
#pragma unroll
        for (int j = 0; j < 8; j++) acc[i][j] = 0.f;
    for (int k0 = 0; k0 < K; k0 += 16) {
        for (int t = tid; t < 2048; t += 256) {
            int kq = t & 15, i = t >> 4;
            int gk = k0 + kq;
            As[kq][i] = (gk < K) ? Ab[(ll)(i0 + i) * lda + gk] : 0.f;
        }
        for (int t = tid; t < 2048; t += 256) {
            int kq = t & 15, j = t >> 4;
            int gk = k0 + kq;
            Bs[kq][j] = (gk < K) ? Ab[(ll)(j0 + j) * lda + gk] : 0.f;
        }
        __syncthreads();
#pragma unroll
        for (int kq = 0; kq < 16; kq++) {
            float4 a0 = *(const float4*)&As[kq][ty * 8];
            float4 a1 = *(const float4*)&As[kq][ty * 8 + 4];
            float4 b0 = *(const float4*)&Bs[kq][tx * 8];
            float4 b1 = *(const float4*)&Bs[kq][tx * 8 + 4];
            float a[8] = {a0.x, a0.y, a0.z, a0.w, a1.x, a1.y, a1.z, a1.w};
            float b[8] = {b0.x, b0.y, b0.z, b0.w, b1.x, b1.y, b1.z, b1.w};
#pragma unroll
            for (int i = 0; i < 8; i++)
#pragma unroll
                for (int j = 0; j < 8; j++) acc[i][j] += a[i] * b[j];
        }
        __syncthreads();
    }
    float* Cb = C + (ll)bz * NPTS * NPTS;
    const float* sqb = sq + (ll)bz * NPTS;
#pragma unroll
    for (int ii = 0; ii < 8; ii++) {
        int gi = i0 + ty * 8 + ii;
        float sqi = sqb[gi];
#pragma unroll
        for (int jj = 0; jj < 8; jj++) {
            int gj = j0 + tx * 8 + jj;
            Cb[(ll)gi * NPTS + gj] = sqi + sqb[gj] - 2.f * acc[ii][jj];
        }
    }
}

// ==================== top-k via 2-level radix select ====================
__global__ __launch_bounds__(256)
void topk_kernel(const float* __restrict__ dist, int* __restrict__ out) {
    __shared__ u32 hist[256];
    __shared__ u32 cum[256];
    __shared__ u32 candk[2048];
    __shared__ u32 candi[2048];
    __shared__ u32 candk2[2048];
    __shared__ u32 candi2[2048];
    __shared__ u32 ctr[2];
    __shared__ u32 selbin, selbefore;
    const int tid = threadIdx.x;
    const float* rp = dist + (ll)blockIdx.x * NPTS;
    hist[tid] = 0;
    if (tid < 2) ctr[tid] = 0;
    __syncthreads();
    float4 f0 = *(const float4*)&rp[tid * 8];
    float4 f1 = *(const float4*)&rp[tid * 8 + 4];
    float vv[8] = {f0.x, f0.y, f0.z, f0.w, f1.x, f1.y, f1.z, f1.w};
    u32 key[8];
#pragma unroll
    for (int j = 0; j < 8; j++) {
        u32 u = __float_as_uint(vv[j]);
        key[j] = (u & 0x80000000u) ? ~u : (u | 0x80000000u);
        atomicAdd(&hist[key[j] >> 24], 1u);
    }
    __syncthreads();
    cum[tid] = hist[tid];
    __syncthreads();
#pragma unroll
    for (int off = 1; off < 256; off <<= 1) {
        u32 v = (tid >= off) ? cum[tid - off] : 0u;
        __syncthreads();
        cum[tid] += v;
        __syncthreads();
    }
    {
        u32 inc = cum[tid], exc = inc - hist[tid];
        if (exc < KNN && inc >= KNN) { selbin = (u32)tid; selbefore = exc; }
    }
    __syncthreads();
    const u32 sb = selbin, before = selbefore;
    int* op = out + (ll)blockIdx.x * KNN;
#pragma unroll
    for (int j = 0; j < 8; j++) {
        u32 b = key[j] >> 24;
        int idx = tid * 8 + j;
        if (b < sb) {
            u32 p = atomicAdd(&ctr[0], 1u);
            op[p] = idx;
        } else if (b == sb) {
            u32 p = atomicAdd(&ctr[1], 1u);
            candk[p] = key[j];
            candi[p] = (u32)idx;
        }
    }
    __syncthreads();
    const int cnt = (int)ctr[1];
    const u32 need1 = KNN - before;
    hist[tid] = 0;
    __syncthreads();
    for (int t = tid; t < cnt; t += 256)
        atomicAdd(&hist[(candk[t] >> 16) & 0xffu], 1u);
    __syncthreads();
    cum[tid] = hist[tid];
    __syncthreads();
#pragma unroll
    for (int off = 1; off < 256; off <<= 1) {
        u32 v = (tid >= off) ? cum[tid - off] : 0u;
        __syncthreads();
        cum[tid] += v;
        __syncthreads();
    }
    {
        u32 inc = cum[tid], exc = inc - hist[tid];
        if (exc < need1 && inc >= need1) { selbin = (u32)tid; selbefore = exc; }
    }
    if (tid == 0) { ctr[0] = 0; ctr[1] = 0; }
    __syncthreads();
    const u32 sb2 = selbin, before2 = selbefore;
    for (int t = tid; t < cnt; t += 256) {
        u32 k2 = candk[t];
        u32 b2 = (k2 >> 16) & 0xffu;
        if (b2 < sb2) {
            u32 p = atomicAdd(&ctr[0], 1u);
            op[before + p] = (int)candi[t];
        } else if (b2 == sb2) {
            u32 p = atomicAdd(&ctr[1], 1u);
            candk2[p] = k2;
            candi2[p] = candi[t];
        }
    }
    __syncthreads();
    const int need2 = (int)(KNN - before - before2);
    const int cnt2 = (int)ctr[1];
    if (tid < 32) {
        for (int s = 0; s < need2; s++) {
            u32 bk = 0xffffffffu, bi = 0xffffffffu;
            for (int t = tid; t < cnt2; t += 32) {
                u32 k2 = candk2[t], i2 = candi2[t];
                if (k2 < bk || (k2 == bk && i2 < bi)) { bk = k2; bi = i2; }
            }
#pragma unroll
            for (int off = 16; off > 0; off >>= 1) {
                u32 ok = __shfl_xor_sync(0xffffffffu, bk, off);
                u32 oi = __shfl_xor_sync(0xffffffffu, bi, off);
                if (ok < bk || (ok == bk && oi < bi)) { bk = ok; bi = oi; }
            }
            for (int t = tid; t < cnt2; t += 32) {
                if (candk2[t] == bk && candi2[t] == bi) { candk2[t] = 0xffffffffu; candi2[t] = 0xffffffffu; }
            }
            if (tid == 0) op[before + before2 + s] = (int)bi;
            __syncwarp();
        }
    }
}

// ==================== fused EdgeConv: 2 points per 512-thread CTA ====================
template <int CIN>
__global__ __launch_bounds__(512)
void edgeconv_kernel(const float* __restrict__ xin, int rsin, int offin,
                     const int* __restrict__ idx,
                     const float* __restrict__ w1, const float* __restrict__ bn1,
                     const float* __restrict__ w2, const float* __restrict__ bn2,
                     float* __restrict__ xout, int rsout, int offout) {
    constexpr int C2 = 2 * CIN;
    constexpr int CPAD = (CIN + 3) & ~3;
    constexpr int ESZ = CIN * 36;
    constexpr int HSZ = 32 * 68;
    constexpr int HALFSZ = ESZ + HSZ + 256 + CPAD + 32;
    extern __shared__ float sm[];
    float* w1s = sm;
    float* w2s = w1s + C2 * 64;
    const int tid = threadIdx.x;
    const int half = tid >> 8, stid = tid & 255;
    float* es  = w2s + 4096 + half * HALFSZ;
    float* h1  = es + ESZ;
    float* red = h1 + HSZ;
    float* ctr = red + 256;
    int*   iks = (int*)(ctr + CPAD);

    const int o = stid & 63, kg = stid >> 6;
    for (int t = tid; t < 64 * C2; t += 512) {
        int oo = t / C2, c = t - oo * C2;
        w1s[c * 64 + oo] = w1[t];
    }
    for (int t = tid; t < 4096; t += 512) {
        int oo = t >> 6, c = t & 63;
        w2s[c * 64 + oo] = w2[t];
    }
    const float s1 = bn1[o] * rsqrtf(bn1[192 + o] + 1e-5f);
    const float t1 = bn1[64 + o] - bn1[128 + o] * s1;
    const float s2 = bn2[o] * rsqrtf(bn2[192 + o] + 1e-5f);
    const float t2 = bn2[64 + o] - bn2[128 + o] * s2;
    __syncthreads();

    for (int pp = blockIdx.x; pp < BB * NPTS / 2; pp += gridDim.x) {
        const int p = pp * 2 + half;
        const int b = p >> 11;
        if (stid < CIN) ctr[stid] = xin[(ll)p * rsin + offin + stid];
        if (stid < KNN) iks[stid] = idx[p * KNN + stid];
        __syncthreads();
        if (CIN % 4 == 0) {
            for (int t = stid; t < 32 * (CIN / 4); t += 256) {
                int kq = t & 31, cg = t >> 5;
                int m = iks[kq];
                float4 v = *(const float4*)&xin[(ll)(b * NPTS + m) * rsin + offin + cg * 4];
                float4 c4 = *(const float4*)&ctr[cg * 4];
                es[(cg * 4 + 0) * 36 + kq] = v.x - c4.x;
                es[(cg * 4 + 1) * 36 + kq] = v.y - c4.y;
                es[(cg * 4 + 2) * 36 + kq] = v.z - c4.z;
                es[(cg * 4 + 3) * 36 + kq] = v.w - c4.w;
            }
        } else {
            for (int t = stid; t < 32 * CIN; t += 256) {
                int kq = t & 31, c = t >> 5;
                int m = iks[kq];
                es[c * 36 + kq] = xin[(ll)(b * NPTS + m) * rsin + offin + c] - ctr[c];
            }
        }
        __syncthreads();
        float bias = 0.f;
        for (int c = 0; c < CIN; c++)
            bias += w1s[(CIN + c) * 64 + o] * ctr[c];
        float acc[8];
#pragma unroll
        for (int j = 0; j < 8; j++) acc[j] = bias;
        for (int c = 0; c < CIN; c++) {
            float w = w1s[c * 64 + o];
            float4 e0 = *(const float4*)&es[c * 36 + kg * 8];
            float4 e1 = *(const float4*)&es[c * 36 + kg * 8 + 4];
            acc[0] += w * e0.x; acc[1] += w * e0.y; acc[2] += w * e0.z; acc[3] += w * e0.w;
            acc[4] += w * e1.x; acc[5] += w * e1.y; acc[6] += w * e1.z; acc[7] += w * e1.w;
        }
#pragma unroll
        for (int j = 0; j < 8; j++) {
            float v = acc[j] * s1 + t1;
            v = v >= 0.f ? v : 0.2f * v;
            h1[(kg * 8 + j) * 68 + o] = v;
            acc[j] = 0.f;
        }
        __syncthreads();
#pragma unroll 4
        for (int c4 = 0; c4 < 16; c4++) {
            float w0 = w2s[(c4 * 4 + 0) * 64 + o];
            float w1v = w2s[(c4 * 4 + 1) * 64 + o];
            float w2v = w2s[(c4 * 4 + 2) * 64 + o];
            float w3 = w2s[(c4 * 4 + 3) * 64 + o];
#pragma unroll
            for (int j = 0; j < 8; j++) {
                float4 hv = *(const float4*)&h1[(kg * 8 + j) * 68 + c4 * 4];
                acc[j] += w0 * hv.x + w1v * hv.y + w2v * hv.z + w3 * hv.w;
            }
        }
        float mx = -3.4e38f;
#pragma unroll
        for (int j = 0; j < 8; j++) {
            float v = acc[j] * s2 + t2;
            v = v >= 0.f ? v : 0.2f * v;
            mx = fmaxf(mx, v);
        }
        red[kg * 64 + o] = mx;
        __syncthreads();
        if (kg == 0) {
            float m = fmaxf(fmaxf(red[o], red[64 + o]), fmaxf(red[128 + o], red[192 + o]));
            xout[(ll)p * rsout + offout + o] = m;
        }
        __syncthreads();
    }
}

// ==================== mma.sync fp16 GEMM (cp.async pipeline + ldmatrix) ====================
// EPI: 2 BN(gm)+lrelu fp32; 4 f16 pack; 5 dual hl+f16; 6 +residual(R,hl)+BN(gn) dual; 7 lrelu+f16
#define STG_W (128 * 36)
#define STG_B (2 * STG_W * 4)

__device__ __forceinline__ void stage_load(const u32* __restrict__ Ab, const u32* __restrict__ Bb,
                                           int i0, int j0, int k0,
                                           int sAm, int sAk, int sBn, int sBk,
                                           u32 aAddr, u32 bAddr, int tid) {
    if (sAk == 1) {
        for (int t = tid; t < 1024; t += 256) {
            int m = t >> 3, q = (t & 7) << 2;
            cpasync16(aAddr + (u32)(m * 36 + q) * 4, Ab + (ll)(i0 + m) * sAm + k0 + q);
        }
    } else {
        for (int t = tid; t < 4096; t += 256) {
            int m = t & 127, kk = t >> 7;
            cpasync4(aAddr + (u32)(m * 36 + kk) * 4, Ab + (ll)(i0 + m) + (ll)(k0 + kk) * sAk);
        }
    }
    if (sBk == 1) {
        for (int t = tid; t < 1024; t += 256) {
            int n = t >> 3, q = (t & 7) << 2;
            cpasync16(bAddr + (u32)(n * 36 + q) * 4, Bb + (ll)(j0 + n) * sBn + k0 + q);
        }
    } else {
        for (int t = tid; t < 4096; t += 256) {
            int n = t & 127, kk = t >> 7;
            cpasync4(bAddr + (u32)(n * 36 + kk) * 4, Bb + (ll)(j0 + n) + (ll)(k0 + kk) * sBk);
        }
    }
}

template <int EPI>
__global__ __launch_bounds__(256)
void mmamm_kernel(const u32* __restrict__ A, const u32* __restrict__ B,
                  u32* __restrict__ Co, u32* __restrict__ C2, float* __restrict__ Cf,
                  int K, int sAm, int sAk, int sBn, int sBk, int ldc,
                  ll strideA, ll strideB, ll strideC, const float* __restrict__ bn,
                  const u32* __restrict__ R) {
    extern __shared__ u32 smu[];
    const int tid = threadIdx.x, lane = tid & 31, w = tid >> 5;
    const int mw = (w & 1) * 64, nw = (w >> 1) * 32;
    const int i0 = blockIdx.y * 128, j0 = blockIdx.x * 128, bz = blockIdx.z;
    const u32* Ab = A + (ll)bz * strideA;
    const u32* Bb = B + (ll)bz * strideB;
    const int lq = lane >> 2, lr = lane & 3;
    const u32 sbase = smem_u32p(smu);
    // ldmatrix per-lane offsets (words)
    const int ra = ((lane >> 3) & 1) * 8 + (lane & 7);   // A row-in-16
    const int ca = ((lane >> 4) & 1) * 4;                // A k-word offset
    const int rb = ((lane >> 4) & 1) * 8 + (lane & 7);   // B row-in-16 (nt pair)
    const int cb = ((lane >> 3) & 1) * 4;                // B k-word offset

    float acc[4][4][4];
#pragma unroll
    for (int a = 0; a < 4; a++)
#pragma unroll
        for (int b = 0; b < 4; b++)
#pragma unroll
            for (int c = 0; c < 4; c++) acc[a][b][c] = 0.f;

    const int nch = K >> 5;
    stage_load(Ab, Bb, i0, j0, 0, sAm, sAk, sBn, sBk, sbase, sbase + STG_W * 4, tid);
    CP_COMMIT();
    for (int ch = 0; ch < nch; ch++) {
        const int st = ch & 1;
        if (ch + 1 < nch) {
            const int st2 = (ch + 1) & 1;
            stage_load(Ab, Bb, i0, j0, (ch + 1) << 5, sAm, sAk, sBn, sBk,
                       sbase + st2 * STG_B, sbase + st2 * STG_B + STG_W * 4, tid);
            CP_COMMIT();
            CP_WAIT1();
        } else {
            CP_WAIT0();
        }
        __syncthreads();
        const u32 abase = sbase + (u32)st * STG_B;
        const u32 bbase = abase + STG_W * 4;
        const u32 aLane = abase + (u32)((mw + ra) * 36 + ca) * 4;
        const u32 bLane = bbase + (u32)((nw + rb) * 36 + cb) * 4;
#pragma unroll
        for (int ks = 0; ks < 4; ks++) {
            const int kw = ks * 8;
            u32 bq[4][2];
#pragma unroll
            for (int p = 0; p < 2; p++)
                ldsm_x4(bq[2 * p][0], bq[2 * p][1], bq[2 * p + 1][0], bq[2 * p + 1][1],
                        bLane + (u32)(p * 16 * 36 + kw) * 4);
#pragma unroll
            for (int mt = 0; mt < 4; mt++) {
                u32 a0, a1, a2, a3;
                ldsm_x4(a0, a1, a2, a3, aLane + (u32)(mt * 16 * 36 + kw) * 4);
#pragma unroll
                for (int nt = 0; nt < 4; nt++)
                    mma16816h(acc[mt][nt], a0, a1, a2, a3, bq[nt][0], bq[nt][1]);
            }
        }
        __syncthreads();
    }

#pragma unroll
    for (int mt = 0; mt < 4; mt++) {
#pragma unroll
        for (int nt = 0; nt < 4; nt++) {
            int gm0 = i0 + mw + mt * 16 + lq;
            int gn  = j0 + nw + nt * 8 + lr * 2;
#pragma unroll
            for (int half = 0; half < 2; half++) {
                int gm = gm0 + half * 8;
                float v0 = acc[mt][nt][half * 2], v1 = acc[mt][nt][half * 2 + 1];
                if (EPI == 2) {
                    float g = bn[gm], be = bn[1024 + gm], mm = bn[2048 + gm], va = bn[3072 + gm];
                    float s = g * rsqrtf(va + 1e-5f);
                    float t = be - mm * s;
                    v0 = v0 * s + t; v0 = v0 >= 0.f ? v0 : 0.2f * v0;
                    v1 = v1 * s + t; v1 = v1 >= 0.f ? v1 : 0.2f * v1;
                    *(float2*)&Cf[(ll)bz * strideC + (ll)gm * ldc + gn] = make_float2(v0, v1);
                } else if (EPI == 4) {
                    Co[(ll)bz * strideC + (ll)gm * ldc + (gn >> 1)] = pack_f16x2(v0, v1);
                } else if (EPI == 5) {
                    ll idx = (ll)bz * strideC + (ll)gm * ldc + gn;
                    *(uint2*)&Co[idx] = make_uint2(pack_hl(v0), pack_hl(v1));
                    C2[(ll)bz * (strideC >> 1) + (ll)gm * (ldc >> 1) + (gn >> 1)] = pack_f16x2(v0, v1);
                } else if (EPI == 6) {
                    ll idx = (ll)bz * strideC + (ll)gm * ldc + gn;
                    uint2 rv = *(const uint2*)&R[idx];
                    float g0 = bn[gn], s0 = g0 * rsqrtf(bn[3072 + gn] + 1e-5f);
                    float t0 = bn[1024 + gn] - bn[2048 + gn] * s0;
                    float g1 = bn[gn + 1], s1 = g1 * rsqrtf(bn[3072 + gn + 1] + 1e-5f);
                    float t1 = bn[1024 + gn + 1] - bn[2048 + gn + 1] * s1;
                    v0 = (v0 + unpack_hl(rv.x)) * s0 + t0;
                    v1 = (v1 + unpack_hl(rv.y)) * s1 + t1;
                    *(uint2*)&Co[idx] = make_uint2(pack_hl(v0), pack_hl(v1));
                    C2[(ll)bz * (strideC >> 1) + (ll)gm * (ldc >> 1) + (gn >> 1)] = pack_f16x2(v0, v1);
                } else {  // EPI == 7
                    v0 = v0 >= 0.f ? v0 : 0.2f * v0;
                    v1 = v1 >= 0.f ? v1 : 0.2f * v1;
                    Co[(ll)bz * strideC + (ll)gm * ldc + (gn >> 1)] = pack_f16x2(v0, v1);
                }
            }
        }
    }
}

// ==================== softmax over f16 logits -> f16 att ====================
__global__ __launch_bounds__(256)
void softmax_f16_kernel(u32* __restrict__ att) {
    __shared__ float sd[NPTS];
    __shared__ float red[256];
    const int tid = threadIdx.x;
    u32* p = att + (ll)blockIdx.x * NPTS;
    float mx = -3.4e38f;
    for (int t = tid; t < NPTS / 2; t += 256) {
        __half2 hv = *reinterpret_cast<__half2*>(&p[t]);
        float v0 = __low2float(hv) * 0.03125f;
        float v1 = __high2float(hv) * 0.03125f;
        sd[2 * t] = v0;
        sd[2 * t + 1] = v1;
        mx = fmaxf(mx, fmaxf(v0, v1));
    }
    red[tid] = mx;
    __syncthreads();
    for (int h = 128; h > 0; h >>= 1) {
        if (tid < h) red[tid] = fmaxf(red[tid], red[tid + h]);
        __syncthreads();
    }
    mx = red[0];
    __syncthreads();
    float sum = 0.f;
    for (int t = tid; t < NPTS; t += 256) {
        float e = __expf(sd[t] - mx);
        sd[t] = e;
        sum += e;
    }
    red[tid] = sum;
    __syncthreads();
    for (int h = 128; h > 0; h >>= 1) {
        if (tid < h) red[tid] += red[tid + h];
        __syncthreads();
    }
    float inv = 1.f / red[0];
    __syncthreads();
    for (int t = tid; t < NPTS / 2; t += 256)
        p[t] = pack_f16x2(sd[2 * t] * inv, sd[2 * t + 1] * inv);
}

// ==================== launcher ====================
extern "C" void kernel_launch(void* const* d_in, const int* in_sizes, int n_in,
                              void* d_out, int out_size) {
    const float* x       = (const float*)d_in[0];
    const float* ec1_w1  = (const float*)d_in[1];
    const float* ec1_bn1 = (const float*)d_in[2];
    const float* ec1_w2  = (const float*)d_in[3];
    const float* ec1_bn2 = (const float*)d_in[4];
    const float* ec2_w1  = (const float*)d_in[5];
    const float* ec2_bn1 = (const float*)d_in[6];
    const float* ec2_w2  = (const float*)d_in[7];
    const float* ec2_bn2 = (const float*)d_in[8];
    const float* ec3_w1  = (const float*)d_in[9];
    const float* ec3_bn1 = (const float*)d_in[10];
    const float* ec3_w2  = (const float*)d_in[11];
    const float* ec3_bn2 = (const float*)d_in[12];
    const float* emb_w   = (const float*)d_in[13];
    const float* q_w     = (const float*)d_in[14];
    const float* k_w     = (const float*)d_in[15];
    const float* v_w     = (const float*)d_in[16];
    const float* att_bn1 = (const float*)d_in[17];
    const float* ff_w1   = (const float*)d_in[18];
    const float* ff_w2   = (const float*)d_in[19];
    const float* att_bn2 = (const float*)d_in[20];
    const float* cb_w    = (const float*)d_in[21];
    const float* cb_bn   = (const float*)d_in[22];
    float* out = (float*)d_out;

    float *xT3, *sqn, *dist, *xcT;
    u32 *xcf, *h, *hf, *q, *kk, *v, *ffo, *embw, *qw, *kw, *vw, *f1w, *f2w, *cw;
    int* idxp;
    cudaGetSymbolAddress((void**)&xT3, g_xT3);
    cudaGetSymbolAddress((void**)&sqn, g_sqn);
    cudaGetSymbolAddress((void**)&dist, g_dist);
    cudaGetSymbolAddress((void**)&idxp, g_idx);
    cudaGetSymbolAddress((void**)&xcT, g_xcT);
    cudaGetSymbolAddress((void**)&xcf, g_xcf);
    cudaGetSymbolAddress((void**)&h, g_h);
    cudaGetSymbolAddress((void**)&hf, g_hf);
    cudaGetSymbolAddress((void**)&q, g_q);
    cudaGetSymbolAddress((void**)&kk, g_k);
    cudaGetSymbolAddress((void**)&v, g_v);
    cudaGetSymbolAddress((void**)&ffo, g_ffo);
    cudaGetSymbolAddress((void**)&embw, g_embw);
    cudaGetSymbolAddress((void**)&qw, g_qw);
    cudaGetSymbolAddress((void**)&kw, g_kw);
    cudaGetSymbolAddress((void**)&vw, g_vw);
    cudaGetSymbolAddress((void**)&f1w, g_f1w);
    cudaGetSymbolAddress((void**)&f2w, g_f2w);
    cudaGetSymbolAddress((void**)&cw, g_cw);

    const size_t sm3  = (size_t)(6 * 64 + 4096 + 2 * (3 * 36 + 32 * 68 + 256 + 4 + 32)) * 4;
    const size_t sm64 = (size_t)(128 * 64 + 4096 + 2 * (64 * 36 + 32 * 68 + 256 + 64 + 32)) * 4;
    cudaFuncSetAttribute((const void*)edgeconv_kernel<64>,
                         cudaFuncAttributeMaxDynamicSharedMemorySize, (int)sm64);
    const int SMTC = 2 * STG_B;  // 73728 B
    cudaFuncSetAttribute((const void*)mmamm_kernel<2>, cudaFuncAttributeMaxDynamicSharedMemorySize, SMTC);
    cudaFuncSetAttribute((const void*)mmamm_kernel<4>, cudaFuncAttributeMaxDynamicSharedMemorySize, SMTC);
    cudaFuncSetAttribute((const void*)mmamm_kernel<5>, cudaFuncAttributeMaxDynamicSharedMemorySize, SMTC);
    cudaFuncSetAttribute((const void*)mmamm_kernel<6>, cudaFuncAttributeMaxDynamicSharedMemorySize, SMTC);
    cudaFuncSetAttribute((const void*)mmamm_kernel<7>, cudaFuncAttributeMaxDynamicSharedMemorySize, SMTC);

    const int npts = BB * NPTS;
    const ll CH = (ll)NPTS * 1024;
    const ll HF = (ll)NPTS * 512;
    const ll AT = (ll)NPTS * NPTS;
    const ll VF = (ll)1024 * 1024;
    const ll FF = (ll)NPTS * 256;

    transpose_x_kernel<<<(npts + 255) / 256, 256>>>(x, xT3);

    dim3 gd(NPTS / 128, NPTS / 128, BB);
    // EdgeConv 1 (C=3)
    sqnorm_kernel<<<(npts + 255) / 256, 256>>>(xT3, 3, 0, 3, sqn);
    distgemm_kernel<<<gd, 256>>>(xT3, dist, 3, 3, (ll)NPTS * 3, sqn);
    topk_kernel<<<npts, 256>>>(dist, idxp);
    edgeconv_kernel<3><<<512, 512, sm3>>>(xT3, 3, 0, idxp, ec1_w1, ec1_bn1, ec1_w2, ec1_bn2, xcT, 192, 0);
    // EdgeConv 2
    sqnorm_kernel<<<(npts + 255) / 256, 256>>>(xcT, 192, 0, 64, sqn);
    distgemm_kernel<<<gd, 256>>>(xcT, dist, 64, 192, (ll)NPTS * 192, sqn);
    topk_kernel<<<npts, 256>>>(dist, idxp);
    edgeconv_kernel<64><<<512, 512, sm64>>>(xcT, 192, 0, idxp, ec2_w1, ec2_bn1, ec2_w2, ec2_bn2, xcT, 192, 64);
    // EdgeConv 3
    sqnorm_kernel<<<(npts + 255) / 256, 256>>>(xcT, 192, 64, 64, sqn);
    distgemm_kernel<<<gd, 256>>>(xcT + 64, dist, 64, 192, (ll)NPTS * 192, sqn);
    topk_kernel<<<npts, 256>>>(dist, idxp);
    edgeconv_kernel<64><<<512, 512, sm64>>>(xcT, 192, 64, idxp, ec3_w1, ec3_bn1, ec3_w2, ec3_bn2, xcT, 192, 128);

    // pack activations + all weights to fp16
    split16_kernel<<<(int)(((ll)npts * 96 + 255) / 256), 256>>>(xcT, xcf, (ll)npts * 96);
    split16_kernel<<<(1024 * 96 + 255) / 256, 256>>>(emb_w, embw, 1024 * 96);
    split16_kernel<<<(1024 * 512 + 255) / 256, 256>>>(q_w, qw, 1024 * 512);
    split16_kernel<<<(1024 * 512 + 255) / 256, 256>>>(k_w, kw, 1024 * 512);
    split16_kernel<<<(1024 * 512 + 255) / 256, 256>>>(v_w, vw, 1024 * 512);
    split16_kernel<<<(512 * 512 + 255) / 256, 256>>>(ff_w1, f1w, 512 * 512);
    split16_kernel<<<(1024 * 256 + 255) / 256, 256>>>(ff_w2, f2w, 1024 * 256);
    split16_kernel<<<(1024 * 512 + 255) / 256, 256>>>(cb_w, cw, 1024 * 512);

    u32* distu = (u32*)dist;
    dim3 gnm(1024 / 128, NPTS / 128, BB);  // M=2048(n), N=1024
    dim3 gmn(NPTS / 128, 1024 / 128, BB);  // M=1024,    N=2048
    dim3 ga(NPTS / 128, NPTS / 128, BB);
    dim3 gff(512 / 128, NPTS / 128, BB);   // M=2048(n), N=512
    // h_t[n][c] = xc[n] @ emb_w^T  (fp16; dual store hl + f16)
    mmamm_kernel<5><<<gnm, 256, SMTC>>>(xcf, embw, h, hf, nullptr, 96, 96, 1, 96, 1, 1024,
                                        (ll)NPTS * 96, 0, CH, nullptr, nullptr);
    // q_t, k_t f16
    mmamm_kernel<4><<<gnm, 256, SMTC>>>(hf, qw, q, nullptr, nullptr, 512, 512, 1, 512, 1, 512,
                                        HF, 0, HF, nullptr, nullptr);
    mmamm_kernel<4><<<gnm, 256, SMTC>>>(hf, kw, kk, nullptr, nullptr, 512, 512, 1, 512, 1, 512,
                                        HF, 0, HF, nullptr, nullptr);
    // v[c][m] f16
    mmamm_kernel<4><<<gmn, 256, SMTC>>>(vw, hf, v, nullptr, nullptr, 512, 512, 1, 512, 1, 1024,
                                        0, HF, VF, nullptr, nullptr);
    // logits[n][m] f16
    mmamm_kernel<4><<<ga, 256, SMTC>>>(q, kk, distu, nullptr, nullptr, 512, 512, 1, 512, 1, NPTS,
                                       HF, HF, AT, nullptr, nullptr);
    softmax_f16_kernel<<<npts, 256>>>(distu);
    // h2_t[n][c] = BN(h_t + att @ v^T); dual hl(g_q) + f16(g_k)
    mmamm_kernel<6><<<gnm, 256, SMTC>>>(distu, v, q, kk, nullptr, 1024, 2048, 1, 1024, 1, 1024,
                                        AT, VF, CH, att_bn1, h);
    // ffo_t[n][o] = lrelu(h2 @ ff_w1^T) f16
    mmamm_kernel<7><<<gff, 256, SMTC>>>(kk, f1w, ffo, nullptr, nullptr, 512, 512, 1, 512, 1, 256,
                                        HF, 0, FF, nullptr, nullptr);
    // h3_t[n][c] = BN(h2_t + ffo @ ff_w2^T); dual hl(g_v) + f16(g_hf)
    mmamm_kernel<6><<<gnm, 256, SMTC>>>(ffo, f2w, v, hf, nullptr, 256, 256, 1, 256, 1, 1024,
                                        FF, 0, CH, att_bn2, q);
    // out[c][n] = lrelu(BN(cb_w @ h3)) fp32
    mmamm_kernel<2><<<gmn, 256, SMTC>>>(cw, hf, nullptr, nullptr, out, 512, 512, 1, 512, 1, NPTS,
                                        0, HF, CH, cb_bn, nullptr);
}